// round 4
// baseline (speedup 1.0000x reference)
#include <cuda_runtime.h>
#include <cuda_bf16.h>
#include <cstdint>
#include <math.h>

// Problem constants
#define BB 4
#define LL 512
#define DD 768
#define HH 12
#define MM 48
#define EE 32
#define PP 512
#define RR 97
#define NBK 12      // D / 64 group blocks
#define NCH 24      // NBK * 2 (i-split)
#define KCLAS 49152 // D * 64
#define WTSTRIDE 7168  // floats per (n,i) W fragment slice

// ---------------- scratch (device globals; allocation-free) ----------------
__device__ float g_att_sum[BB*LL*LL];
__device__ float g_mention[BB*MM*DD];
__device__ float g_tmp1[BB*MM*LL];
__device__ float g_matt[BB*MM*MM];
__device__ float g_eatt[BB*EE*MM];
__device__ float g_emtok[BB*EE*LL];
__device__ float g_entatt[BB*HH*EE*LL];
__device__ float g_hatt[BB*PP*MM];
__device__ float g_tatt[BB*PP*MM];
__device__ float g_ctxH[BB*PP*LL];
__device__ float g_ctxL[BB*PP*LL];
__device__ float g_hH[BB*PP*DD];
__device__ float g_hL[BB*PP*DD];
__device__ float g_tH[BB*PP*DD];
__device__ float g_tL[BB*PP*DD];
__device__ float g_cinfoH[BB*PP*DD];
__device__ float g_cinfoL[BB*PP*DD];
__device__ float g_hf[BB*PP*DD];
__device__ float g_tf[BB*PP*DD];
__device__ float g_part[NCH*BB*PP*RR];
// pre-split static operands
__device__ float g_hWH[DD*DD];
__device__ float g_hWL[DD*DD];
__device__ float g_tWH[DD*DD];
__device__ float g_tWL[DD*DD];
__device__ float g_hcWH[DD*DD];
__device__ float g_hcWL[DD*DD];
__device__ float g_tcWH[DD*DD];
__device__ float g_tcWL[DD*DD];
__device__ float g_ctxtH[BB*LL*DD];
__device__ float g_ctxtL[BB*LL*DD];
__device__ float g_WtH[NBK*64*WTSTRIDE];
__device__ float g_WtL[NBK*64*WTSTRIDE];

// ---------------- tf32 helpers ----------------
static __device__ __forceinline__ uint32_t fu(float f) { return __float_as_uint(f); }

static __device__ __forceinline__ void split3(float x, uint32_t& h, uint32_t& l) {
    asm("cvt.rna.tf32.f32 %0, %1;" : "=r"(h) : "f"(x));
    float hf = __uint_as_float(h);
    float r = x - hf;
    asm("cvt.rna.tf32.f32 %0, %1;" : "=r"(l) : "f"(r));
}
static __device__ __forceinline__ void split3f(float x, float& hf, float& lf) {
    uint32_t h, l; split3(x, h, l);
    hf = __uint_as_float(h); lf = __uint_as_float(l);
}
static __device__ __forceinline__ void mma_tf32(float* c,
    uint32_t a0, uint32_t a1, uint32_t a2, uint32_t a3, uint32_t b0, uint32_t b1) {
    asm volatile(
        "mma.sync.aligned.m16n8k8.row.col.f32.tf32.tf32.f32 "
        "{%0,%1,%2,%3}, {%4,%5,%6,%7}, {%8,%9}, {%0,%1,%2,%3};"
        : "+f"(c[0]), "+f"(c[1]), "+f"(c[2]), "+f"(c[3])
        : "r"(a0), "r"(a1), "r"(a2), "r"(a3), "r"(b0), "r"(b1));
}

// ---------------- split kernels ----------------
__global__ void split_k(const float* __restrict__ x, float* __restrict__ xh,
                        float* __restrict__ xl, int n)
{
    int i = blockIdx.x * 256 + threadIdx.x;
    if (i >= n) return;
    float h, l; split3f(x[i], h, l);
    xh[i] = h; xl[i] = l;
}

// clasW -> fragment-packed per-(n,i) layout, split, padded r 97..111 with zeros
__global__ void wtransform_k(const float* __restrict__ W,
                             float* __restrict__ WtH, float* __restrict__ WtL)
{
    int idx = blockIdx.x * 256 + threadIdx.x;        // over NBK*64*WTSTRIDE
    if (idx >= NBK*64*WTSTRIDE) return;
    int fi = idx % WTSTRIDE;
    int ni = idx / WTSTRIDE;
    int i = ni & 63, n = ni >> 6;
    int half = fi & 1;
    int kq2 = (fi >> 1) & 3;
    int r = (fi >> 3) % 112;
    int s = (fi >> 3) / 112;
    int j = s*8 + half*4 + kq2;
    float w = 0.f;
    if (r < RR) w = W[(size_t)r*KCLAS + (size_t)n*4096 + i*64 + j];
    float h, l; split3f(w, h, l);
    WtH[idx] = h; WtL[idx] = l;
}

// ---------------- small kernels ----------------
__global__ void att_sum_k(const float* __restrict__ att, float* __restrict__ out)
{
    int idx = blockIdx.x * 256 + threadIdx.x;
    if (idx >= BB*LL*LL) return;
    int b  = idx >> 18;
    int lm = idx & (LL*LL - 1);
    const float* p = att + (size_t)b*HH*LL*LL + lm;
    float s = 0.f;
#pragma unroll
    for (int h = 0; h < HH; ++h) s += p[(size_t)h*LL*LL];
    out[idx] = s;
}

__global__ void rownorm_k(float* __restrict__ x)
{
    int row = blockIdx.x;
    float* p = x + (size_t)row * LL;
    int t = threadIdx.x;
    float v0 = p[t], v1 = p[t + 256];
    __shared__ float sm[256];
    sm[t] = v0 + v1; __syncthreads();
    for (int o = 128; o > 0; o >>= 1) { if (t < o) sm[t] += sm[t + o]; __syncthreads(); }
    float inv = 1.f / (sm[0] + 1e-30f);
    p[t] = v0 * inv; p[t + 256] = v1 * inv;
}

__global__ void pair_att_k(const int* __restrict__ hts,
                           const float* __restrict__ emap,
                           const float* __restrict__ eatt,
                           float* __restrict__ hattO, float* __restrict__ tattO)
{
    int bp = blockIdx.x;
    int b  = bp >> 9;
    int hi = hts[(size_t)bp*2], ti = hts[(size_t)bp*2 + 1];
    float mask = (hi + ti != 0) ? 1.f : 0.f;
    int t = threadIdx.x;
    float ha = 0.f, ta = 0.f;
    if (t < MM) {
        float hm = emap[((size_t)b*EE + hi)*MM + t] * mask;
        float tm = emap[((size_t)b*EE + ti)*MM + t] * mask;
        ha = eatt[((size_t)b*EE + hi)*MM + t] * tm;
        ta = eatt[((size_t)b*EE + ti)*MM + t] * hm;
    }
    __shared__ float smh[64], smt[64];
    smh[t] = ha; smt[t] = ta; __syncthreads();
    for (int o = 32; o > 0; o >>= 1) {
        if (t < o) { smh[t] += smh[t + o]; smt[t] += smt[t + o]; }
        __syncthreads();
    }
    float invh = 1.f / (smh[0] + 1e-30f);
    float invt = 1.f / (smt[0] + 1e-30f);
    if (t < MM) {
        hattO[(size_t)bp*MM + t] = ha * invh;
        tattO[(size_t)bp*MM + t] = ta * invt;
    }
}

// writes split ctx (H/L)
__global__ void ctx_k(const int* __restrict__ hts,
                      const float* __restrict__ entatt,
                      float* __restrict__ ctxH, float* __restrict__ ctxL)
{
    int bp = blockIdx.x; int b = bp >> 9;
    int hi = hts[(size_t)bp*2], ti = hts[(size_t)bp*2 + 1];
    float mask = (hi + ti != 0) ? 1.f : 0.f;
    int t = threadIdx.x;
    const float* base = entatt + (size_t)b*HH*EE*LL;
    float v0 = 0.f, v1 = 0.f;
#pragma unroll
    for (int h = 0; h < HH; ++h) {
        const float* ph = base + ((size_t)h*EE + hi)*LL;
        const float* pt = base + ((size_t)h*EE + ti)*LL;
        v0 += ph[t]       * pt[t];
        v1 += ph[t + 256] * pt[t + 256];
    }
    __shared__ float sm[256];
    sm[t] = v0 + v1; __syncthreads();
    for (int o = 128; o > 0; o >>= 1) { if (t < o) sm[t] += sm[t + o]; __syncthreads(); }
    float inv = mask / (sm[0] + 1e-30f);
    float h0, l0, h1, l1;
    split3f(v0 * inv, h0, l0);
    split3f(v1 * inv, h1, l1);
    ctxH[(size_t)bp*LL + t]       = h0; ctxL[(size_t)bp*LL + t]       = l0;
    ctxH[(size_t)bp*LL + t + 256] = h1; ctxL[(size_t)bp*LL + t + 256] = l1;
}

// matt: warp per output element (b,m,j), dot over K=512
__global__ void matt_k(const float* __restrict__ tmp1, const float* __restrict__ mmap,
                       float* __restrict__ matt)
{
    int gw = (blockIdx.x * 256 + threadIdx.x) >> 5;
    if (gw >= BB*MM*MM) return;
    int lane = threadIdx.x & 31;
    int b = gw / (MM*MM);
    int rem = gw % (MM*MM);
    int m = rem / MM, j = rem % MM;
    const float4* a = (const float4*)(tmp1 + ((size_t)b*MM + m)*LL);
    const float4* c = (const float4*)(mmap + ((size_t)b*MM + j)*LL);
    float s = 0.f;
#pragma unroll
    for (int k = lane; k < 128; k += 32) {
        float4 x = a[k], y = c[k];
        s += x.x*y.x + x.y*y.y + x.z*y.z + x.w*y.w;
    }
#pragma unroll
    for (int o = 16; o; o >>= 1) s += __shfl_xor_sync(0xffffffffu, s, o);
    if (lane == 0) matt[gw] = s;
}

__global__ void eatt_k(const float* __restrict__ emap, const float* __restrict__ matt,
                       float* __restrict__ eatt)
{
    int b = blockIdx.x;
    int idx = threadIdx.x;
    for (int v = idx; v < EE*MM; v += 256) {
        int e = v / MM, j = v % MM;
        float s = 0.f;
#pragma unroll
        for (int m = 0; m < MM; ++m)
            s += emap[((size_t)b*EE + e)*MM + m] * matt[(size_t)b*MM*MM + m*MM + j];
        eatt[(size_t)b*EE*MM + v] = s;
    }
}

// ---------------- generic FFMA GEMM (small steps) ----------------
// SPLIT: write split3(C) into Cg / CLg instead of raw C.
template<bool TB, bool SPLIT>
__global__ __launch_bounds__(256)
void gemm_k(const float* __restrict__ Ag, const float* __restrict__ Bg,
            float* __restrict__ Cg, float* __restrict__ CLg,
            int M, int N, int K,
            long long sA, long long sB, long long sC,
            int dA, int dB, int dC)
{
    const int BM = 64, BN = 64, BK = 16;
    int z = blockIdx.z;
    const float* A  = Ag + (long long)(z / dA) * sA;
    const float* Bp = Bg + (long long)(z / dB) * sB;
    float*       C  = Cg + (long long)(z / dC) * sC;
    float*       CL = SPLIT ? (CLg + (long long)(z / dC) * sC) : nullptr;
    int row0 = blockIdx.y * BM;
    int col0 = blockIdx.x * BN;

    __shared__ float As[BK][BM + 1];
    __shared__ float Bs[BK][BN + 1];

    int tid = threadIdx.x;
    int tx = tid & 15, ty = tid >> 4;
    float acc[4][4] = {};

    for (int k0 = 0; k0 < K; k0 += BK) {
#pragma unroll
        for (int r = 0; r < 4; ++r) {
            int idx = tid + r * 256;
            int m = idx >> 4, k = idx & 15;
            float v = 0.f;
            if (row0 + m < M) v = A[(size_t)(row0 + m) * K + k0 + k];
            As[k][m] = v;
        }
        if (!TB) {
#pragma unroll
            for (int r = 0; r < 4; ++r) {
                int idx = tid + r * 256;
                int k = idx >> 6, n = idx & 63;
                float v = 0.f;
                if (col0 + n < N) v = Bp[(size_t)(k0 + k) * N + col0 + n];
                Bs[k][n] = v;
            }
        } else {
#pragma unroll
            for (int r = 0; r < 4; ++r) {
                int idx = tid + r * 256;
                int n = idx >> 4, k = idx & 15;
                float v = 0.f;
                if (col0 + n < N) v = Bp[(size_t)(col0 + n) * K + k0 + k];
                Bs[k][n] = v;
            }
        }
        __syncthreads();
#pragma unroll
        for (int k = 0; k < BK; ++k) {
            float a[4], bb[4];
#pragma unroll
            for (int i = 0; i < 4; ++i) a[i]  = As[k][ty * 4 + i];
#pragma unroll
            for (int j = 0; j < 4; ++j) bb[j] = Bs[k][tx * 4 + j];
#pragma unroll
            for (int i = 0; i < 4; ++i)
#pragma unroll
                for (int j = 0; j < 4; ++j) acc[i][j] += a[i] * bb[j];
        }
        __syncthreads();
    }

#pragma unroll
    for (int i = 0; i < 4; ++i) {
        int m = row0 + ty * 4 + i;
        if (m >= M) continue;
#pragma unroll
        for (int j = 0; j < 4; ++j) {
            int n = col0 + tx * 4 + j;
            if (n >= N) continue;
            if (SPLIT) {
                float h, l; split3f(acc[i][j], h, l);
                C[(size_t)m * N + n] = h;
                CL[(size_t)m * N + n] = l;
            } else {
                C[(size_t)m * N + n] = acc[i][j];
            }
        }
    }
}

// ---------------- tf32 (3x compensated) GEMM, pre-split operands ----------------
// C = [tanh+bias]( A1 @ B1^T + [A2 @ B2^T] )     A: [M,K] split (H/L), B split
// TB=true : B row-major [N,K]; TB=false : B row-major [K,N]
// SPLITOUT: write split C (H/L) instead of raw.
#define TF32_SMEM ((128*36*2 + 64*36*2) * 4)
template<bool TB, bool FUSE2, bool EPI, bool SPLITOUT>
__global__ __launch_bounds__(256)
void tf32gemm_k(const float* __restrict__ A1H, const float* __restrict__ A1L,
                const float* __restrict__ B1H, const float* __restrict__ B1L,
                const float* __restrict__ A2H, const float* __restrict__ A2L,
                const float* __restrict__ B2H, const float* __restrict__ B2L,
                const float* __restrict__ bias1, const float* __restrict__ bias2,
                float* __restrict__ Cg, float* __restrict__ CLg,
                int M, int N, int K,
                long long sA, long long sB, long long sC)
{
    extern __shared__ char smraw[];
    float* AsH = (float*)smraw;            // [128][36]
    float* AsL = AsH + 128*36;
    float* BsH = AsL + 128*36;             // [64][36]
    float* BsL = BsH + 64*36;

    int z = blockIdx.z;
    int row0 = blockIdx.y * 128, col0 = blockIdx.x * 64;
    int tid = threadIdx.x, lane = tid & 31, wid = tid >> 5;
    int m_off = (wid & 3) * 32, n_off = (wid >> 2) * 32;
    int l4 = lane >> 2, kq = lane & 3;

    float acc[2][4][4];
#pragma unroll
    for (int a = 0; a < 2; ++a)
#pragma unroll
        for (int b = 0; b < 4; ++b)
#pragma unroll
            for (int c = 0; c < 4; ++c) acc[a][b][c] = 0.f;

    const int NPASS = FUSE2 ? 2 : 1;
    for (int pass = 0; pass < NPASS; ++pass) {
        const float* AH = (pass ? A2H : A1H) + (long long)z * sA;
        const float* AL = (pass ? A2L : A1L) + (long long)z * sA;
        const float* BH = (pass ? B2H : B1H) + (long long)z * sB;
        const float* BL = (pass ? B2L : B1L) + (long long)z * sB;
        for (int k0 = 0; k0 < K; k0 += 32) {
            __syncthreads();
            // stage A tile 128x32 (pure copy)
#pragma unroll
            for (int r2 = 0; r2 < 4; ++r2) {
                int slot = tid + r2 * 256;
                int m = slot >> 3, kk = (slot & 7) * 4;
                float4 vh = *(const float4*)(AH + (size_t)(row0 + m) * K + k0 + kk);
                float4 vl = *(const float4*)(AL + (size_t)(row0 + m) * K + k0 + kk);
                *(float4*)(AsH + m*36 + kk) = vh;
                *(float4*)(AsL + m*36 + kk) = vl;
            }
            // stage B tile 64x32 -> Bs[n][k]
            if (TB) {
#pragma unroll
                for (int r2 = 0; r2 < 2; ++r2) {
                    int slot = tid + r2 * 256;
                    int n = slot >> 3, kk = (slot & 7) * 4;
                    float4 vh = *(const float4*)(BH + (size_t)(col0 + n) * K + k0 + kk);
                    float4 vl = *(const float4*)(BL + (size_t)(col0 + n) * K + k0 + kk);
                    *(float4*)(BsH + n*36 + kk) = vh;
                    *(float4*)(BsL + n*36 + kk) = vl;
                }
            } else {
#pragma unroll
                for (int r2 = 0; r2 < 2; ++r2) {
                    int slot = tid + r2 * 256;
                    int k = slot >> 4, nq = (slot & 15) * 4;
                    float4 vh = *(const float4*)(BH + (size_t)(k0 + k) * N + col0 + nq);
                    float4 vl = *(const float4*)(BL + (size_t)(k0 + k) * N + col0 + nq);
                    BsH[(nq+0)*36+k] = vh.x; BsH[(nq+1)*36+k] = vh.y;
                    BsH[(nq+2)*36+k] = vh.z; BsH[(nq+3)*36+k] = vh.w;
                    BsL[(nq+0)*36+k] = vl.x; BsL[(nq+1)*36+k] = vl.y;
                    BsL[(nq+2)*36+k] = vl.z; BsL[(nq+3)*36+k] = vl.w;
                }
            }
            __syncthreads();
#pragma unroll
            for (int s = 0; s < 4; ++s) {
                int kb = s * 8 + kq;
                uint32_t aH[2][4], aL[2][4];
#pragma unroll
                for (int mt = 0; mt < 2; ++mt) {
                    int mr = m_off + mt*16 + l4;
                    aH[mt][0] = fu(AsH[mr*36+kb]);       aL[mt][0] = fu(AsL[mr*36+kb]);
                    aH[mt][1] = fu(AsH[(mr+8)*36+kb]);   aL[mt][1] = fu(AsL[(mr+8)*36+kb]);
                    aH[mt][2] = fu(AsH[mr*36+kb+4]);     aL[mt][2] = fu(AsL[mr*36+kb+4]);
                    aH[mt][3] = fu(AsH[(mr+8)*36+kb+4]); aL[mt][3] = fu(AsL[(mr+8)*36+kb+4]);
                }
#pragma unroll
                for (int nt = 0; nt < 4; ++nt) {
                    int nr = n_off + nt*8 + l4;
                    uint32_t bH0 = fu(BsH[nr*36+kb]), bH1 = fu(BsH[nr*36+kb+4]);
                    uint32_t bL0 = fu(BsL[nr*36+kb]), bL1 = fu(BsL[nr*36+kb+4]);
#pragma unroll
                    for (int mt = 0; mt < 2; ++mt) {
                        mma_tf32(acc[mt][nt], aH[mt][0],aH[mt][1],aH[mt][2],aH[mt][3], bH0, bH1);
                        mma_tf32(acc[mt][nt], aH[mt][0],aH[mt][1],aH[mt][2],aH[mt][3], bL0, bL1);
                        mma_tf32(acc[mt][nt], aL[mt][0],aL[mt][1],aL[mt][2],aL[mt][3], bH0, bH1);
                    }
                }
            }
        }
    }

    float* C  = Cg + (long long)z * sC;
    float* CL = SPLITOUT ? (CLg + (long long)z * sC) : nullptr;
#pragma unroll
    for (int mt = 0; mt < 2; ++mt) {
#pragma unroll
        for (int nt = 0; nt < 4; ++nt) {
            int mr = row0 + m_off + mt*16 + l4;
            int nc = col0 + n_off + nt*8 + 2*kq;
            float b0 = 0.f, b1 = 0.f;
            if (EPI) {
                b0 = bias1[nc]   + (FUSE2 ? bias2[nc]   : 0.f);
                b1 = bias1[nc+1] + (FUSE2 ? bias2[nc+1] : 0.f);
            }
            float v0 = acc[mt][nt][0] + b0;
            float v1 = acc[mt][nt][1] + b1;
            float v2 = acc[mt][nt][2] + b0;
            float v3 = acc[mt][nt][3] + b1;
            if (EPI) { v0 = tanhf(v0); v1 = tanhf(v1); v2 = tanhf(v2); v3 = tanhf(v3); }
            if (SPLITOUT) {
                float h, l;
                split3f(v0, h, l); C[(size_t)mr*N+nc]       = h; CL[(size_t)mr*N+nc]       = l;
                split3f(v1, h, l); C[(size_t)mr*N+nc+1]     = h; CL[(size_t)mr*N+nc+1]     = l;
                split3f(v2, h, l); C[(size_t)(mr+8)*N+nc]   = h; CL[(size_t)(mr+8)*N+nc]   = l;
                split3f(v3, h, l); C[(size_t)(mr+8)*N+nc+1] = h; CL[(size_t)(mr+8)*N+nc+1] = l;
            } else {
                C[(size_t)mr * N + nc]       = v0;
                C[(size_t)mr * N + nc + 1]   = v1;
                C[(size_t)(mr+8) * N + nc]   = v2;
                C[(size_t)(mr+8) * N + nc+1] = v3;
            }
        }
    }
}

// ---------------- classifier (group bilinear, tf32 3x MMA, pre-split W) ----------------
#define CLAS_SMEM ((128*33 + 8*128*4*2 + 2*WTSTRIDE) * 4)
__global__ __launch_bounds__(256)
void clasmma_k(const float* __restrict__ Hf, const float* __restrict__ Tf,
               const float* __restrict__ WtH, const float* __restrict__ WtL,
               float* __restrict__ part)
{
    extern __shared__ char smraw[];
    float* hs  = (float*)smraw;          // [128][33]
    float* tsS = hs + 128*33;            // float2[(s*128+p)*4+kq] = 8192 floats
    float* wsH = tsS + 8192;             // WTSTRIDE/2 float2 each
    float* wsL = wsH + WTSTRIDE;

    const int n = blockIdx.y, z = blockIdx.z;
    const int p0 = blockIdx.x * 128;
    int tid = threadIdx.x, lane = tid & 31, wid = tid >> 5;
    int pbase = (wid & 3) * 32, nbase = (wid >> 2) * 56;
    int l4 = lane >> 2, kq = lane & 3;

    for (int v = tid; v < 128*32; v += 256) {
        int p = v >> 5, ii = v & 31;
        hs[p*33 + ii] = Hf[(size_t)(p0 + p)*DD + n*64 + z*32 + ii];
    }
    for (int v = tid; v < 128*64; v += 256) {
        int p = v >> 6, j = v & 63;
        float t = Tf[(size_t)(p0 + p)*DD + n*64 + j];
        int s = j >> 3, kq2 = j & 3, half = (j >> 2) & 1;
        tsS[(((s << 7) + p)*4 + kq2)*2 + half] = t;
    }

    float acc[2][7][4];
#pragma unroll
    for (int a = 0; a < 2; ++a)
#pragma unroll
        for (int b = 0; b < 7; ++b)
#pragma unroll
            for (int c = 0; c < 4; ++c) acc[a][b][c] = 0.f;

    for (int ii = 0; ii < 32; ++ii) {
        int i = z*32 + ii;
        size_t wbase = (size_t)(n*64 + i) * WTSTRIDE;
        __syncthreads();
        {
            const float4* srcH = (const float4*)(WtH + wbase);
            const float4* srcL = (const float4*)(WtL + wbase);
            float4* dH = (float4*)wsH;
            float4* dL = (float4*)wsL;
            for (int v = tid; v < WTSTRIDE/4; v += 256) {
                dH[v] = srcH[v];
                dL[v] = srcL[v];
            }
        }
        __syncthreads();

        float hv0[2], hv1[2];
#pragma unroll
        for (int mt = 0; mt < 2; ++mt) {
            int pr = pbase + mt*16 + l4;
            hv0[mt] = hs[pr*33 + ii];
            hv1[mt] = hs[(pr+8)*33 + ii];
        }
        const float2* ts2 = (const float2*)tsS;
        const float2* wh2 = (const float2*)wsH;
        const float2* wl2 = (const float2*)wsL;
#pragma unroll
        for (int s = 0; s < 8; ++s) {
            uint32_t aH[2][4], aL[2][4];
#pragma unroll
            for (int mt = 0; mt < 2; ++mt) {
                int pr = pbase + mt*16 + l4;
                float2 ta = ts2[((s << 7) + pr)*4 + kq];
                float2 tb = ts2[((s << 7) + pr + 8)*4 + kq];
                split3(hv0[mt]*ta.x, aH[mt][0], aL[mt][0]);
                split3(hv1[mt]*tb.x, aH[mt][1], aL[mt][1]);
                split3(hv0[mt]*ta.y, aH[mt][2], aL[mt][2]);
                split3(hv1[mt]*tb.y, aH[mt][3], aL[mt][3]);
            }
#pragma unroll
            for (int nt = 0; nt < 7; ++nt) {
                int r = nbase + nt*8 + l4;
                float2 bh = wh2[(s*112 + r)*4 + kq];
                float2 bl = wl2[(s*112 + r)*4 + kq];
                uint32_t bH0 = fu(bh.x), bH1 = fu(bh.y);
                uint32_t bL0 = fu(bl.x), bL1 = fu(bl.y);
#pragma unroll
                for (int mt = 0; mt < 2; ++mt) {
                    mma_tf32(acc[mt][nt], aH[mt][0],aH[mt][1],aH[mt][2],aH[mt][3], bH0, bH1);
                    mma_tf32(acc[mt][nt], aH[mt][0],aH[mt][1],aH[mt][2],aH[mt][3], bL0, bL1);
                    mma_tf32(acc[mt][nt], aL[mt][0],aL[mt][1],aL[mt][2],aL[mt][3], bH0, bH1);
                }
            }
        }
    }

    int chunk = n*2 + z;
    float* po = part + (size_t)chunk * (BB*PP*RR);
#pragma unroll
    for (int mt = 0; mt < 2; ++mt) {
#pragma unroll
        for (int nt = 0; nt < 7; ++nt) {
            int p = p0 + pbase + mt*16 + l4;
            int r = nbase + nt*8 + 2*kq;
            if (r < RR)   po[(size_t)p*RR + r]       = acc[mt][nt][0];
            if (r+1 < RR) po[(size_t)p*RR + r + 1]   = acc[mt][nt][1];
            if (r < RR)   po[(size_t)(p+8)*RR + r]   = acc[mt][nt][2];
            if (r+1 < RR) po[(size_t)(p+8)*RR + r+1] = acc[mt][nt][3];
        }
    }
}

__global__ void clas_red_k(const float* __restrict__ part,
                           const float* __restrict__ clasb,
                           float* __restrict__ out)
{
    int idx = blockIdx.x * 256 + threadIdx.x;
    if (idx >= BB * PP * RR) return;
    int r = idx % RR;
    float s = clasb[r];
#pragma unroll
    for (int c = 0; c < NCH; ++c) s += part[(size_t)c * (BB * PP * RR) + idx];
    out[idx] = s;
}

// ---------------- host ----------------
extern "C" void kernel_launch(void* const* d_in, const int* in_sizes, int n_in,
                              void* d_out, int out_size)
{
    const float* context   = (const float*)d_in[0];
    const float* attention = (const float*)d_in[1];
    const float* mmap      = (const float*)d_in[2];
    const float* emap      = (const float*)d_in[3];
    const int*   hts       = (const int*)d_in[4];
    const float* hW   = (const float*)d_in[5];
    const float* hb   = (const float*)d_in[6];
    const float* tW   = (const float*)d_in[7];
    const float* tb   = (const float*)d_in[8];
    const float* hcW  = (const float*)d_in[9];
    const float* hcb  = (const float*)d_in[10];
    const float* tcW  = (const float*)d_in[11];
    const float* tcb  = (const float*)d_in[12];
    const float* clasW = (const float*)d_in[13];
    const float* clasb = (const float*)d_in[14];
    float* out = (float*)d_out;

#define GETSYM(p, s) float* p; cudaGetSymbolAddress((void**)&p, s)
    GETSYM(att_sum, g_att_sum); GETSYM(mention, g_mention); GETSYM(tmp1, g_tmp1);
    GETSYM(matt, g_matt); GETSYM(eatt, g_eatt); GETSYM(emtok, g_emtok);
    GETSYM(entatt, g_entatt); GETSYM(hatt, g_hatt); GETSYM(tatt, g_tatt);
    GETSYM(ctxH, g_ctxH); GETSYM(ctxL, g_ctxL);
    GETSYM(hH, g_hH); GETSYM(hL, g_hL); GETSYM(tH, g_tH); GETSYM(tL, g_tL);
    GETSYM(cinfoH, g_cinfoH); GETSYM(cinfoL, g_cinfoL);
    GETSYM(hf, g_hf); GETSYM(tf, g_tf); GETSYM(part, g_part);
    GETSYM(hWH, g_hWH); GETSYM(hWL, g_hWL); GETSYM(tWH, g_tWH); GETSYM(tWL, g_tWL);
    GETSYM(hcWH, g_hcWH); GETSYM(hcWL, g_hcWL); GETSYM(tcWH, g_tcWH); GETSYM(tcWL, g_tcWL);
    GETSYM(ctxtH, g_ctxtH); GETSYM(ctxtL, g_ctxtL);
    GETSYM(WtH, g_WtH); GETSYM(WtL, g_WtL);
#undef GETSYM

    cudaFuncSetAttribute(tf32gemm_k<true,true,true,false>,
                         cudaFuncAttributeMaxDynamicSharedMemorySize, TF32_SMEM);
    cudaFuncSetAttribute(tf32gemm_k<false,false,false,true>,
                         cudaFuncAttributeMaxDynamicSharedMemorySize, TF32_SMEM);
    cudaFuncSetAttribute(clasmma_k,
                         cudaFuncAttributeMaxDynamicSharedMemorySize, CLAS_SMEM);

    // 0) static splits
    split_k<<<(DD*DD+255)/256, 256>>>(hW,  hWH,  hWL,  DD*DD);
    split_k<<<(DD*DD+255)/256, 256>>>(tW,  tWH,  tWL,  DD*DD);
    split_k<<<(DD*DD+255)/256, 256>>>(hcW, hcWH, hcWL, DD*DD);
    split_k<<<(DD*DD+255)/256, 256>>>(tcW, tcWH, tcWL, DD*DD);
    split_k<<<(BB*LL*DD+255)/256, 256>>>(context, ctxtH, ctxtL, BB*LL*DD);
    wtransform_k<<<(NBK*64*WTSTRIDE+255)/256, 256>>>(clasW, WtH, WtL);

    // 1) att_sum
    att_sum_k<<<(BB*LL*LL + 255)/256, 256>>>(attention, att_sum);

    // 2) mention = mention_map @ context
    gemm_k<false,false><<<dim3(12,1,BB),256>>>(
        mmap, context, mention, nullptr, MM, DD, LL,
        (long long)MM*LL, (long long)LL*DD, (long long)MM*DD, 1,1,1);

    // 3) tmp1 = mention_map @ att_sum
    gemm_k<false,false><<<dim3(8,1,BB),256>>>(
        mmap, att_sum, tmp1, nullptr, MM, LL, LL,
        (long long)MM*LL, (long long)LL*LL, (long long)MM*LL, 1,1,1);

    // 4) mention_att (warp-per-output)
    matt_k<<<(BB*MM*MM*32 + 255)/256, 256>>>(tmp1, mmap, matt);

    // 5) entity_att
    eatt_k<<<BB, 256>>>(emap, matt, eatt);

    // 6) em_tok + normalize
    gemm_k<false,false><<<dim3(8,1,BB),256>>>(
        emap, mmap, emtok, nullptr, EE, LL, MM,
        (long long)EE*MM, (long long)MM*LL, (long long)EE*LL, 1,1,1);
    rownorm_k<<<BB*EE, 256>>>(emtok);

    // 7) ent_att
    gemm_k<false,false><<<dim3(8,1,BB*HH),256>>>(
        emtok, attention, entatt, nullptr, EE, LL, LL,
        (long long)EE*LL, (long long)LL*LL, (long long)EE*LL, HH,1,1);

    // 8) per-pair vectors
    pair_att_k<<<BB*PP, 64>>>(hts, emap, eatt, hatt, tatt);
    ctx_k<<<BB*PP, 256>>>(hts, entatt, ctxH, ctxL);

    // 9) h, t (FFMA, split-write epilogue)
    gemm_k<false,true><<<dim3(12,8,BB),256>>>(
        tatt, mention, hH, hL, PP, DD, MM,
        (long long)PP*MM, (long long)MM*DD, (long long)PP*DD, 1,1,1);
    gemm_k<false,true><<<dim3(12,8,BB),256>>>(
        hatt, mention, tH, tL, PP, DD, MM,
        (long long)PP*MM, (long long)MM*DD, (long long)PP*DD, 1,1,1);

    // 10) context_info = ctx @ context (tf32x3 NN, split output)
    tf32gemm_k<false,false,false,true><<<dim3(12,4,BB),256,TF32_SMEM>>>(
        ctxH, ctxL, ctxtH, ctxtL, nullptr, nullptr, nullptr, nullptr,
        nullptr, nullptr, cinfoH, cinfoL, PP, DD, LL,
        (long long)PP*LL, (long long)LL*DD, (long long)PP*DD);

    // 11+12) hf = tanh(h@hW^T + cinfo@hcW^T + hb + hcb); tf likewise
    tf32gemm_k<true,true,true,false><<<dim3(12,16,1),256,TF32_SMEM>>>(
        hH, hL, hWH, hWL, cinfoH, cinfoL, hcWH, hcWL,
        hb, hcb, hf, nullptr, BB*PP, DD, DD, 0,0,0);
    tf32gemm_k<true,true,true,false><<<dim3(12,16,1),256,TF32_SMEM>>>(
        tH, tL, tWH, tWL, cinfoH, cinfoL, tcWH, tcWL,
        tb, tcb, tf, nullptr, BB*PP, DD, DD, 0,0,0);

    // 13) classifier
    clasmma_k<<<dim3(BB*PP/128, NBK, 2), 256, CLAS_SMEM>>>(hf, tf, WtH, WtL, part);
    clas_red_k<<<(BB*PP*RR + 255)/256, 256>>>(part, clasb, out);
}

// round 5
// speedup vs baseline: 1.4459x; 1.4459x over previous
#include <cuda_runtime.h>
#include <cuda_bf16.h>
#include <cstdint>
#include <math.h>

// Problem constants
#define BB 4
#define LL 512
#define DD 768
#define HH 12
#define MM 48
#define EE 32
#define PP 512
#define RR 97
#define NBK 12      // D / 64 group blocks
#define NCH 24      // NBK * 2 (i-split)
#define KCLAS 49152 // D * 64
#define WT_U 3584   // uints (bf162 pairs) per (n,i) W fragment slice

// ---------------- scratch (device globals; allocation-free) ----------------
__device__ float g_att_sum[BB*LL*LL];
__device__ float g_mention[BB*MM*DD];
__device__ float g_tmp1[BB*MM*LL];
__device__ float g_matt[BB*MM*MM];
__device__ float g_eatt[BB*EE*MM];
__device__ float g_emtok[BB*EE*LL];
__device__ float g_entatt[BB*HH*EE*LL];
__device__ float g_hatt[BB*PP*MM];
__device__ float g_tatt[BB*PP*MM];
__device__ uint32_t g_ctxH2[BB*PP*LL/2];
__device__ uint32_t g_ctxL2[BB*PP*LL/2];
__device__ uint32_t g_hH2[BB*PP*DD/2];
__device__ uint32_t g_hL2[BB*PP*DD/2];
__device__ uint32_t g_tH2[BB*PP*DD/2];
__device__ uint32_t g_tL2[BB*PP*DD/2];
__device__ uint32_t g_cinfoH2[BB*PP*DD/2];
__device__ uint32_t g_cinfoL2[BB*PP*DD/2];
__device__ float g_hf[BB*PP*DD];
__device__ float g_tf[BB*PP*DD];
__device__ float g_part[NCH*BB*PP*RR];
// pre-split static operands (bf162 pair-packed, [rows][K/2])
__device__ uint32_t g_hWH2[DD*DD/2];
__device__ uint32_t g_hWL2[DD*DD/2];
__device__ uint32_t g_tWH2[DD*DD/2];
__device__ uint32_t g_tWL2[DD*DD/2];
__device__ uint32_t g_hcWH2[DD*DD/2];
__device__ uint32_t g_hcWL2[DD*DD/2];
__device__ uint32_t g_tcWH2[DD*DD/2];
__device__ uint32_t g_tcWL2[DD*DD/2];
__device__ uint32_t g_ctxtH2[BB*DD*LL/2];  // context transposed: [b][d][l/2]
__device__ uint32_t g_ctxtL2[BB*DD*LL/2];
__device__ uint32_t g_WtH[NBK*64*WT_U];
__device__ uint32_t g_WtL[NBK*64*WT_U];

// ---------------- bf16 helpers ----------------
static __device__ __forceinline__ uint32_t pk2(float e0, float e1) {
    uint32_t r;
    asm("cvt.rn.bf16x2.f32 %0, %1, %2;" : "=r"(r) : "f"(e1), "f"(e0));
    return r; // lo = e0, hi = e1
}
static __device__ __forceinline__ void splitbf(float e0, float e1,
                                               uint32_t& H, uint32_t& L) {
    H = pk2(e0, e1);
    float h0 = __uint_as_float(H << 16);
    float h1 = __uint_as_float(H & 0xffff0000u);
    L = pk2(e0 - h0, e1 - h1);
}
static __device__ __forceinline__ void mma_bf(float* c, const uint32_t* a,
                                              uint32_t b0, uint32_t b1) {
    asm volatile(
        "mma.sync.aligned.m16n8k16.row.col.f32.bf16.bf16.f32 "
        "{%0,%1,%2,%3}, {%4,%5,%6,%7}, {%8,%9}, {%0,%1,%2,%3};"
        : "+f"(c[0]), "+f"(c[1]), "+f"(c[2]), "+f"(c[3])
        : "r"(a[0]), "r"(a[1]), "r"(a[2]), "r"(a[3]), "r"(b0), "r"(b1));
}

// ---------------- preprocessing kernels ----------------
__global__ void splitpair_k(const float* __restrict__ x, uint32_t* __restrict__ H,
                            uint32_t* __restrict__ L, int npairs)
{
    int i = blockIdx.x * 256 + threadIdx.x;
    if (i >= npairs) return;
    float2 v = ((const float2*)x)[i];
    uint32_t h, l; splitbf(v.x, v.y, h, l);
    H[i] = h; L[i] = l;
}

// context -> transposed pair-split: out[b][d][lp] = {ctx[b][2lp][d], ctx[b][2lp+1][d]}
__global__ void ctxt_k(const float* __restrict__ ctxt,
                       uint32_t* __restrict__ H, uint32_t* __restrict__ L)
{
    int idx = blockIdx.x * 256 + threadIdx.x;
    if (idx >= BB*DD*(LL/2)) return;
    int lp = idx & 255;
    int bd = idx >> 8;
    int d = bd % DD, b = bd / DD;
    float e0 = ctxt[((size_t)b*LL + 2*lp)     * DD + d];
    float e1 = ctxt[((size_t)b*LL + 2*lp + 1) * DD + d];
    uint32_t h, l; splitbf(e0, e1, h, l);
    H[idx] = h; L[idx] = l;
}

// clasW -> fragment-packed bf162 per (n,i), padded r 97..111 with zeros
// fi = ((s*112 + r)*4 + kq)*2 + half; entry = {W[.., j0], W[.., j0+1]},
// j0 = s*16 + half*8 + 2*kq
__global__ void wtransform_k(const float* __restrict__ W,
                             uint32_t* __restrict__ WtH, uint32_t* __restrict__ WtL)
{
    int idx = blockIdx.x * 256 + threadIdx.x;
    if (idx >= NBK*64*WT_U) return;
    int fi = idx % WT_U;
    int ni = idx / WT_U;
    int i = ni & 63, n = ni >> 6;
    int half = fi & 1;
    int kq = (fi >> 1) & 3;
    int r = (fi >> 3) % 112;
    int s = (fi >> 3) / 112;
    int j0 = s*16 + half*8 + 2*kq;
    float w0 = 0.f, w1 = 0.f;
    if (r < RR) {
        const float* base = W + (size_t)r*KCLAS + (size_t)n*4096 + i*64;
        w0 = base[j0]; w1 = base[j0 + 1];
    }
    uint32_t h, l; splitbf(w0, w1, h, l);
    WtH[idx] = h; WtL[idx] = l;
}

// ---------------- small kernels ----------------
__global__ void att_sum_k(const float* __restrict__ att, float* __restrict__ out)
{
    int idx = blockIdx.x * 256 + threadIdx.x;
    if (idx >= BB*LL*LL) return;
    int b  = idx >> 18;
    int lm = idx & (LL*LL - 1);
    const float* p = att + (size_t)b*HH*LL*LL + lm;
    float s = 0.f;
#pragma unroll
    for (int h = 0; h < HH; ++h) s += p[(size_t)h*LL*LL];
    out[idx] = s;
}

__global__ void rownorm_k(float* __restrict__ x)
{
    int row = blockIdx.x;
    float* p = x + (size_t)row * LL;
    int t = threadIdx.x;
    float v0 = p[t], v1 = p[t + 256];
    __shared__ float sm[256];
    sm[t] = v0 + v1; __syncthreads();
    for (int o = 128; o > 0; o >>= 1) { if (t < o) sm[t] += sm[t + o]; __syncthreads(); }
    float inv = 1.f / (sm[0] + 1e-30f);
    p[t] = v0 * inv; p[t + 256] = v1 * inv;
}

__global__ void pair_att_k(const int* __restrict__ hts,
                           const float* __restrict__ emap,
                           const float* __restrict__ eatt,
                           float* __restrict__ hattO, float* __restrict__ tattO)
{
    int bp = blockIdx.x;
    int b  = bp >> 9;
    int hi = hts[(size_t)bp*2], ti = hts[(size_t)bp*2 + 1];
    float mask = (hi + ti != 0) ? 1.f : 0.f;
    int t = threadIdx.x;
    float ha = 0.f, ta = 0.f;
    if (t < MM) {
        float hm = emap[((size_t)b*EE + hi)*MM + t] * mask;
        float tm = emap[((size_t)b*EE + ti)*MM + t] * mask;
        ha = eatt[((size_t)b*EE + hi)*MM + t] * tm;
        ta = eatt[((size_t)b*EE + ti)*MM + t] * hm;
    }
    __shared__ float smh[64], smt[64];
    smh[t] = ha; smt[t] = ta; __syncthreads();
    for (int o = 32; o > 0; o >>= 1) {
        if (t < o) { smh[t] += smh[t + o]; smt[t] += smt[t + o]; }
        __syncthreads();
    }
    float invh = 1.f / (smh[0] + 1e-30f);
    float invt = 1.f / (smt[0] + 1e-30f);
    if (t < MM) {
        hattO[(size_t)bp*MM + t] = ha * invh;
        tattO[(size_t)bp*MM + t] = ta * invt;
    }
}

// writes pair-split ctx (bf162 H/L): thread t handles elements 2t, 2t+1
__global__ void ctx_k(const int* __restrict__ hts,
                      const float* __restrict__ entatt,
                      uint32_t* __restrict__ ctxH2, uint32_t* __restrict__ ctxL2)
{
    int bp = blockIdx.x; int b = bp >> 9;
    int hi = hts[(size_t)bp*2], ti = hts[(size_t)bp*2 + 1];
    float mask = (hi + ti != 0) ? 1.f : 0.f;
    int t = threadIdx.x;   // 256
    const float* base = entatt + (size_t)b*HH*EE*LL;
    float v0 = 0.f, v1 = 0.f;
#pragma unroll
    for (int h = 0; h < HH; ++h) {
        const float2* ph = (const float2*)(base + ((size_t)h*EE + hi)*LL);
        const float2* pt = (const float2*)(base + ((size_t)h*EE + ti)*LL);
        float2 x = ph[t], y = pt[t];
        v0 += x.x * y.x;
        v1 += x.y * y.y;
    }
    __shared__ float sm[256];
    sm[t] = v0 + v1; __syncthreads();
    for (int o = 128; o > 0; o >>= 1) { if (t < o) sm[t] += sm[t + o]; __syncthreads(); }
    float inv = mask / (sm[0] + 1e-30f);
    uint32_t H, L; splitbf(v0 * inv, v1 * inv, H, L);
    ctxH2[(size_t)bp*(LL/2) + t] = H;
    ctxL2[(size_t)bp*(LL/2) + t] = L;
}

// matt: warp per output element (b,m,j), dot over K=512
__global__ void matt_k(const float* __restrict__ tmp1, const float* __restrict__ mmap,
                       float* __restrict__ matt)
{
    int gw = (blockIdx.x * 256 + threadIdx.x) >> 5;
    if (gw >= BB*MM*MM) return;
    int lane = threadIdx.x & 31;
    int b = gw / (MM*MM);
    int rem = gw % (MM*MM);
    int m = rem / MM, j = rem % MM;
    const float4* a = (const float4*)(tmp1 + ((size_t)b*MM + m)*LL);
    const float4* c = (const float4*)(mmap + ((size_t)b*MM + j)*LL);
    float s = 0.f;
#pragma unroll
    for (int k = lane; k < 128; k += 32) {
        float4 x = a[k], y = c[k];
        s += x.x*y.x + x.y*y.y + x.z*y.z + x.w*y.w;
    }
#pragma unroll
    for (int o = 16; o; o >>= 1) s += __shfl_xor_sync(0xffffffffu, s, o);
    if (lane == 0) matt[gw] = s;
}

__global__ void eatt_k(const float* __restrict__ emap, const float* __restrict__ matt,
                       float* __restrict__ eatt)
{
    int b = blockIdx.x;
    int idx = threadIdx.x;
    for (int v = idx; v < EE*MM; v += 256) {
        int e = v / MM, j = v % MM;
        float s = 0.f;
#pragma unroll
        for (int m = 0; m < MM; ++m)
            s += emap[((size_t)b*EE + e)*MM + m] * matt[(size_t)b*MM*MM + m*MM + j];
        eatt[(size_t)b*EE*MM + v] = s;
    }
}

// ---------------- generic FFMA GEMM (small steps) ----------------
// SPLITPAIR: write bf162 pair-split C into CH2/CL2 (N even, full tiles).
template<bool SPLITPAIR>
__global__ __launch_bounds__(256)
void gemm_k(const float* __restrict__ Ag, const float* __restrict__ Bg,
            float* __restrict__ Cg, uint32_t* __restrict__ CH2, uint32_t* __restrict__ CL2,
            int M, int N, int K,
            long long sA, long long sB, long long sC,
            int dA, int dB, int dC)
{
    const int BM = 64, BN = 64, BK = 16;
    int z = blockIdx.z;
    const float* A  = Ag + (long long)(z / dA) * sA;
    const float* Bp = Bg + (long long)(z / dB) * sB;
    int row0 = blockIdx.y * BM;
    int col0 = blockIdx.x * BN;

    __shared__ float As[BK][BM + 1];
    __shared__ float Bs[BK][BN + 1];

    int tid = threadIdx.x;
    int tx = tid & 15, ty = tid >> 4;
    float acc[4][4] = {};

    for (int k0 = 0; k0 < K; k0 += BK) {
#pragma unroll
        for (int r = 0; r < 4; ++r) {
            int idx = tid + r * 256;
            int m = idx >> 4, k = idx & 15;
            float v = 0.f;
            if (row0 + m < M) v = A[(size_t)(row0 + m) * K + k0 + k];
            As[k][m] = v;
        }
#pragma unroll
        for (int r = 0; r < 4; ++r) {
            int idx = tid + r * 256;
            int k = idx >> 6, n = idx & 63;
            float v = 0.f;
            if (col0 + n < N) v = Bp[(size_t)(k0 + k) * N + col0 + n];
            Bs[k][n] = v;
        }
        __syncthreads();
#pragma unroll
        for (int k = 0; k < BK; ++k) {
            float a[4], bb[4];
#pragma unroll
            for (int i = 0; i < 4; ++i) a[i]  = As[k][ty * 4 + i];
#pragma unroll
            for (int j = 0; j < 4; ++j) bb[j] = Bs[k][tx * 4 + j];
#pragma unroll
            for (int i = 0; i < 4; ++i)
#pragma unroll
                for (int j = 0; j < 4; ++j) acc[i][j] += a[i] * bb[j];
        }
        __syncthreads();
    }

    if (SPLITPAIR) {
        uint32_t* CH = CH2 + (long long)(z / dC) * (sC / 2);
        uint32_t* CL = CL2 + (long long)(z / dC) * (sC / 2);
#pragma unroll
        for (int i = 0; i < 4; ++i) {
            int m = row0 + ty * 4 + i;
            int np = (col0 + tx * 4) >> 1;
            uint32_t H, L;
            splitbf(acc[i][0], acc[i][1], H, L);
            CH[(size_t)m * (N/2) + np]     = H;
            CL[(size_t)m * (N/2) + np]     = L;
            splitbf(acc[i][2], acc[i][3], H, L);
            CH[(size_t)m * (N/2) + np + 1] = H;
            CL[(size_t)m * (N/2) + np + 1] = L;
        }
    } else {
        float* C = Cg + (long long)(z / dC) * sC;
#pragma unroll
        for (int i = 0; i < 4; ++i) {
            int m = row0 + ty * 4 + i;
            if (m >= M) continue;
#pragma unroll
            for (int j = 0; j < 4; ++j) {
                int n = col0 + tx * 4 + j;
                if (n >= N) continue;
                C[(size_t)m * N + n] = acc[i][j];
            }
        }
    }
}

// ---------------- bf16 (3x compensated) NT GEMM, pair-packed operands ----------------
// C = [tanh+bias]( A1 @ B1^T + [A2 @ B2^T] )
// A: [M][KP] bf162-pairs (H/L), B: [N][KP] bf162-pairs (H/L). Full tiles assumed
// (M mult of 128, N mult of 64, KP mult of 16).
#define BF_SMEM ((128*20 + 64*20) * 2 * 4)
template<bool FUSE2, bool EPI, bool PAIROUT>
__global__ __launch_bounds__(256)
void bfgemm_k(const uint32_t* __restrict__ A1H, const uint32_t* __restrict__ A1L,
              const uint32_t* __restrict__ B1H, const uint32_t* __restrict__ B1L,
              const uint32_t* __restrict__ A2H, const uint32_t* __restrict__ A2L,
              const uint32_t* __restrict__ B2H, const uint32_t* __restrict__ B2L,
              const float* __restrict__ bias1, const float* __restrict__ bias2,
              float* __restrict__ Cf, uint32_t* __restrict__ CH2, uint32_t* __restrict__ CL2,
              int M, int N, int KP,
              long long sA, long long sB, long long sC)
{
    extern __shared__ uint32_t usm[];
    uint32_t* AsH = usm;                 // [128][20] (16 pairs used)
    uint32_t* AsL = AsH + 128*20;
    uint32_t* BsH = AsL + 128*20;        // [64][20]
    uint32_t* BsL = BsH + 64*20;

    int z = blockIdx.z;
    int row0 = blockIdx.y * 128, col0 = blockIdx.x * 64;
    int tid = threadIdx.x, lane = tid & 31, wid = tid >> 5;
    int m_off = (wid & 3) * 32, n_off = (wid >> 2) * 32;
    int g = lane >> 2, kq = lane & 3;

    float acc[2][4][4];
#pragma unroll
    for (int a = 0; a < 2; ++a)
#pragma unroll
        for (int b = 0; b < 4; ++b)
#pragma unroll
            for (int c = 0; c < 4; ++c) acc[a][b][c] = 0.f;

    const int NPASS = FUSE2 ? 2 : 1;
    for (int pass = 0; pass < NPASS; ++pass) {
        const uint32_t* AH = (pass ? A2H : A1H) + (long long)z * sA;
        const uint32_t* AL = (pass ? A2L : A1L) + (long long)z * sA;
        const uint32_t* BH = (pass ? B2H : B1H) + (long long)z * sB;
        const uint32_t* BL = (pass ? B2L : B1L) + (long long)z * sB;
        for (int kp0 = 0; kp0 < KP; kp0 += 16) {
            __syncthreads();
            // A tile: 128 rows x 16 uints = 512 uint4 per component
#pragma unroll
            for (int r2 = 0; r2 < 2; ++r2) {
                int slot = tid + r2 * 256;
                int m = slot >> 2, q = slot & 3;
                *(uint4*)(AsH + m*20 + q*4) =
                    *(const uint4*)(AH + (size_t)(row0 + m)*KP + kp0 + q*4);
                *(uint4*)(AsL + m*20 + q*4) =
                    *(const uint4*)(AL + (size_t)(row0 + m)*KP + kp0 + q*4);
            }
            // B tile: 64 x 16 = 256 uint4
            {
                int n = tid >> 2, q = tid & 3;
                *(uint4*)(BsH + n*20 + q*4) =
                    *(const uint4*)(BH + (size_t)(col0 + n)*KP + kp0 + q*4);
                *(uint4*)(BsL + n*20 + q*4) =
                    *(const uint4*)(BL + (size_t)(col0 + n)*KP + kp0 + q*4);
            }
            __syncthreads();
#pragma unroll
            for (int st = 0; st < 2; ++st) {
                int pb = st*8 + kq;
                uint32_t aH[2][4], aL[2][4];
#pragma unroll
                for (int mt = 0; mt < 2; ++mt) {
                    int mr = m_off + mt*16 + g;
                    aH[mt][0] = AsH[mr*20 + pb];       aL[mt][0] = AsL[mr*20 + pb];
                    aH[mt][1] = AsH[(mr+8)*20 + pb];   aL[mt][1] = AsL[(mr+8)*20 + pb];
                    aH[mt][2] = AsH[mr*20 + pb + 4];   aL[mt][2] = AsL[mr*20 + pb + 4];
                    aH[mt][3] = AsH[(mr+8)*20 + pb+4]; aL[mt][3] = AsL[(mr+8)*20 + pb+4];
                }
#pragma unroll
                for (int nt = 0; nt < 4; ++nt) {
                    int nr = n_off + nt*8 + g;
                    uint32_t bH0 = BsH[nr*20 + pb], bH1 = BsH[nr*20 + pb + 4];
                    uint32_t bL0 = BsL[nr*20 + pb], bL1 = BsL[nr*20 + pb + 4];
#pragma unroll
                    for (int mt = 0; mt < 2; ++mt) {
                        mma_bf(acc[mt][nt], aH[mt], bH0, bH1);
                        mma_bf(acc[mt][nt], aH[mt], bL0, bL1);
                        mma_bf(acc[mt][nt], aL[mt], bH0, bH1);
                    }
                }
            }
        }
    }

#pragma unroll
    for (int mt = 0; mt < 2; ++mt) {
#pragma unroll
        for (int nt = 0; nt < 4; ++nt) {
            int mr = row0 + m_off + mt*16 + g;
            int nc = col0 + n_off + nt*8 + 2*kq;
            float b0 = 0.f, b1 = 0.f;
            if (EPI) {
                b0 = bias1[nc]   + (FUSE2 ? bias2[nc]   : 0.f);
                b1 = bias1[nc+1] + (FUSE2 ? bias2[nc+1] : 0.f);
            }
            float v0 = acc[mt][nt][0] + b0;
            float v1 = acc[mt][nt][1] + b1;
            float v2 = acc[mt][nt][2] + b0;
            float v3 = acc[mt][nt][3] + b1;
            if (EPI) { v0 = tanhf(v0); v1 = tanhf(v1); v2 = tanhf(v2); v3 = tanhf(v3); }
            if (PAIROUT) {
                uint32_t* CH = CH2 + (long long)z * (sC / 2);
                uint32_t* CL = CL2 + (long long)z * (sC / 2);
                int np = nc >> 1;
                uint32_t H, L;
                splitbf(v0, v1, H, L);
                CH[(size_t)mr*(N/2) + np] = H; CL[(size_t)mr*(N/2) + np] = L;
                splitbf(v2, v3, H, L);
                CH[(size_t)(mr+8)*(N/2) + np] = H; CL[(size_t)(mr+8)*(N/2) + np] = L;
            } else {
                float* C = Cf + (long long)z * sC;
                C[(size_t)mr * N + nc]       = v0;
                C[(size_t)mr * N + nc + 1]   = v1;
                C[(size_t)(mr+8) * N + nc]   = v2;
                C[(size_t)(mr+8) * N + nc+1] = v3;
            }
        }
    }
}

// ---------------- classifier (group bilinear, bf16 3x MMA, pre-split W) ----------------
#define CLAS_SMEM (128*33*4 + 4096*8 + 2*WT_U*4)
__global__ __launch_bounds__(256)
void clasmma_k(const float* __restrict__ Hf, const float* __restrict__ Tf,
               const uint32_t* __restrict__ WtH, const uint32_t* __restrict__ WtL,
               float* __restrict__ part)
{
    extern __shared__ char smraw[];
    float*  hs  = (float*)smraw;                // [128][33]
    float2* ts2 = (float2*)(hs + 128*33);       // 4096 float2
    uint32_t* wsH = (uint32_t*)(ts2 + 4096);    // WT_U
    uint32_t* wsL = wsH + WT_U;

    const int n = blockIdx.y, z = blockIdx.z;
    const int p0 = blockIdx.x * 128;
    int tid = threadIdx.x, lane = tid & 31, wid = tid >> 5;
    int pbase = (wid & 3) * 32, nbase = (wid >> 2) * 56;
    int g = lane >> 2, kq = lane & 3;

    for (int v = tid; v < 128*32; v += 256) {
        int p = v >> 5, ii = v & 31;
        hs[p*33 + ii] = Hf[(size_t)(p0 + p)*DD + n*64 + z*32 + ii];
    }
    // ts2: {t[j0], t[j0+1]} at [((s*2+hi8)*128 + p)*4 + kq], j = s*16+hi8*8+2kq+e
    for (int v = tid; v < 128*64; v += 256) {
        int p = v >> 6, j = v & 63;
        float t = Tf[(size_t)(p0 + p)*DD + n*64 + j];
        int s = j >> 4, hi8 = (j >> 3) & 1, kq2 = (j & 7) >> 1, e = j & 1;
        ((float*)ts2)[((((s*2 + hi8)*128 + p)*4 + kq2) << 1) + e] = t;
    }

    float acc[2][7][4];
#pragma unroll
    for (int a = 0; a < 2; ++a)
#pragma unroll
        for (int b = 0; b < 7; ++b)
#pragma unroll
            for (int c = 0; c < 4; ++c) acc[a][b][c] = 0.f;

    for (int ii = 0; ii < 32; ++ii) {
        int i = z*32 + ii;
        size_t wbase = (size_t)(n*64 + i) * WT_U;
        __syncthreads();
        {
            const uint4* srcH = (const uint4*)(WtH + wbase);
            const uint4* srcL = (const uint4*)(WtL + wbase);
            uint4* dH = (uint4*)wsH;
            uint4* dL = (uint4*)wsL;
            for (int v = tid; v < WT_U/4; v += 256) { dH[v] = srcH[v]; dL[v] = srcL[v]; }
        }
        __syncthreads();

        float hv0[2], hv1[2];
#pragma unroll
        for (int mt = 0; mt < 2; ++mt) {
            int pr = pbase + mt*16 + g;
            hv0[mt] = hs[pr*33 + ii];
            hv1[mt] = hs[(pr+8)*33 + ii];
        }
        const uint2* wh2 = (const uint2*)wsH;
        const uint2* wl2 = (const uint2*)wsL;
#pragma unroll
        for (int s = 0; s < 4; ++s) {
            uint32_t aH[2][4], aL[2][4];
#pragma unroll
            for (int mt = 0; mt < 2; ++mt) {
                int pr = pbase + mt*16 + g;
                float2 lo  = ts2[((s*2 + 0)*128 + pr)*4 + kq];
                float2 lo8 = ts2[((s*2 + 0)*128 + pr + 8)*4 + kq];
                float2 hi  = ts2[((s*2 + 1)*128 + pr)*4 + kq];
                float2 hi8 = ts2[((s*2 + 1)*128 + pr + 8)*4 + kq];
                splitbf(hv0[mt]*lo.x,  hv0[mt]*lo.y,  aH[mt][0], aL[mt][0]);
                splitbf(hv1[mt]*lo8.x, hv1[mt]*lo8.y, aH[mt][1], aL[mt][1]);
                splitbf(hv0[mt]*hi.x,  hv0[mt]*hi.y,  aH[mt][2], aL[mt][2]);
                splitbf(hv1[mt]*hi8.x, hv1[mt]*hi8.y, aH[mt][3], aL[mt][3]);
            }
#pragma unroll
            for (int nt = 0; nt < 7; ++nt) {
                int r = nbase + nt*8 + g;
                uint2 bh = wh2[(s*112 + r)*4 + kq];
                uint2 bl = wl2[(s*112 + r)*4 + kq];
#pragma unroll
                for (int mt = 0; mt < 2; ++mt) {
                    mma_bf(acc[mt][nt], aH[mt], bh.x, bh.y);
                    mma_bf(acc[mt][nt], aH[mt], bl.x, bl.y);
                    mma_bf(acc[mt][nt], aL[mt], bh.x, bh.y);
                }
            }
        }
    }

    int chunk = n*2 + z;
    float* po = part + (size_t)chunk * (BB*PP*RR);
#pragma unroll
    for (int mt = 0; mt < 2; ++mt) {
#pragma unroll
        for (int nt = 0; nt < 7; ++nt) {
            int p = p0 + pbase + mt*16 + g;
            int r = nbase + nt*8 + 2*kq;
            if (r < RR)   po[(size_t)p*RR + r]       = acc[mt][nt][0];
            if (r+1 < RR) po[(size_t)p*RR + r + 1]   = acc[mt][nt][1];
            if (r < RR)   po[(size_t)(p+8)*RR + r]   = acc[mt][nt][2];
            if (r+1 < RR) po[(size_t)(p+8)*RR + r+1] = acc[mt][nt][3];
        }
    }
}

__global__ void clas_red_k(const float* __restrict__ part,
                           const float* __restrict__ clasb,
                           float* __restrict__ out)
{
    int idx = blockIdx.x * 256 + threadIdx.x;
    if (idx >= BB * PP * RR) return;
    int r = idx % RR;
    float s = clasb[r];
#pragma unroll
    for (int c = 0; c < NCH; ++c) s += part[(size_t)c * (BB * PP * RR) + idx];
    out[idx] = s;
}

// ---------------- host ----------------
extern "C" void kernel_launch(void* const* d_in, const int* in_sizes, int n_in,
                              void* d_out, int out_size)
{
    const float* context   = (const float*)d_in[0];
    const float* attention = (const float*)d_in[1];
    const float* mmap      = (const float*)d_in[2];
    const float* emap      = (const float*)d_in[3];
    const int*   hts       = (const int*)d_in[4];
    const float* hW   = (const float*)d_in[5];
    const float* hb   = (const float*)d_in[6];
    const float* tW   = (const float*)d_in[7];
    const float* tb   = (const float*)d_in[8];
    const float* hcW  = (const float*)d_in[9];
    const float* hcb  = (const float*)d_in[10];
    const float* tcW  = (const float*)d_in[11];
    const float* tcb  = (const float*)d_in[12];
    const float* clasW = (const float*)d_in[13];
    const float* clasb = (const float*)d_in[14];
    float* out = (float*)d_out;

#define GETF(p, s) float* p; cudaGetSymbolAddress((void**)&p, s)
#define GETU(p, s) uint32_t* p; cudaGetSymbolAddress((void**)&p, s)
    GETF(att_sum, g_att_sum); GETF(mention, g_mention); GETF(tmp1, g_tmp1);
    GETF(matt, g_matt); GETF(eatt, g_eatt); GETF(emtok, g_emtok);
    GETF(entatt, g_entatt); GETF(hatt, g_hatt); GETF(tatt, g_tatt);
    GETU(ctxH2, g_ctxH2); GETU(ctxL2, g_ctxL2);
    GETU(hH2, g_hH2); GETU(hL2, g_hL2); GETU(tH2, g_tH2); GETU(tL2, g_tL2);
    GETU(cinfoH2, g_cinfoH2); GETU(cinfoL2, g_cinfoL2);
    GETF(hf, g_hf); GETF(tf, g_tf); GETF(part, g_part);
    GETU(hWH2, g_hWH2); GETU(hWL2, g_hWL2); GETU(tWH2, g_tWH2); GETU(tWL2, g_tWL2);
    GETU(hcWH2, g_hcWH2); GETU(hcWL2, g_hcWL2); GETU(tcWH2, g_tcWH2); GETU(tcWL2, g_tcWL2);
    GETU(ctxtH2, g_ctxtH2); GETU(ctxtL2, g_ctxtL2);
    GETU(WtH, g_WtH); GETU(WtL, g_WtL);
#undef GETF
#undef GETU

    cudaFuncSetAttribute(clasmma_k, cudaFuncAttributeMaxDynamicSharedMemorySize, CLAS_SMEM);

    // 0) static operand preprocessing
    const int WP = DD*DD/2;
    splitpair_k<<<(WP+255)/256, 256>>>(hW,  hWH2,  hWL2,  WP);
    splitpair_k<<<(WP+255)/256, 256>>>(tW,  tWH2,  tWL2,  WP);
    splitpair_k<<<(WP+255)/256, 256>>>(hcW, hcWH2, hcWL2, WP);
    splitpair_k<<<(WP+255)/256, 256>>>(tcW, tcWH2, tcWL2, WP);
    ctxt_k<<<(BB*DD*(LL/2)+255)/256, 256>>>(context, ctxtH2, ctxtL2);
    wtransform_k<<<(NBK*64*WT_U+255)/256, 256>>>(clasW, WtH, WtL);

    // 1) att_sum
    att_sum_k<<<(BB*LL*LL + 255)/256, 256>>>(attention, att_sum);

    // 2) mention = mention_map @ context
    gemm_k<false><<<dim3(12,1,BB),256>>>(
        mmap, context, mention, nullptr, nullptr, MM, DD, LL,
        (long long)MM*LL, (long long)LL*DD, (long long)MM*DD, 1,1,1);

    // 3) tmp1 = mention_map @ att_sum
    gemm_k<false><<<dim3(8,1,BB),256>>>(
        mmap, att_sum, tmp1, nullptr, nullptr, MM, LL, LL,
        (long long)MM*LL, (long long)LL*LL, (long long)MM*LL, 1,1,1);

    // 4) mention_att
    matt_k<<<(BB*MM*MM*32 + 255)/256, 256>>>(tmp1, mmap, matt);

    // 5) entity_att
    eatt_k<<<BB, 256>>>(emap, matt, eatt);

    // 6) em_tok + normalize
    gemm_k<false><<<dim3(8,1,BB),256>>>(
        emap, mmap, emtok, nullptr, nullptr, EE, LL, MM,
        (long long)EE*MM, (long long)MM*LL, (long long)EE*LL, 1,1,1);
    rownorm_k<<<BB*EE, 256>>>(emtok);

    // 7) ent_att
    gemm_k<false><<<dim3(8,1,BB*HH),256>>>(
        emtok, attention, entatt, nullptr, nullptr, EE, LL, LL,
        (long long)EE*LL, (long long)LL*LL, (long long)EE*LL, HH,1,1);

    // 8) per-pair vectors (ctx -> pair-split)
    pair_att_k<<<BB*PP, 64>>>(hts, emap, eatt, hatt, tatt);
    ctx_k<<<BB*PP, 256>>>(hts, entatt, ctxH2, ctxL2);

    // 9) h, t (FFMA, pair-split epilogue)
    gemm_k<true><<<dim3(12,8,BB),256>>>(
        tatt, mention, nullptr, hH2, hL2, PP, DD, MM,
        (long long)PP*MM, (long long)MM*DD, (long long)PP*DD, 1,1,1);
    gemm_k<true><<<dim3(12,8,BB),256>>>(
        hatt, mention, nullptr, tH2, tL2, PP, DD, MM,
        (long long)PP*MM, (long long)MM*DD, (long long)PP*DD, 1,1,1);

    // 10) context_info = ctx @ context^T(pre-transposed)  (bf16x3, pair-split out)
    bfgemm_k<false,false,true><<<dim3(12,4,BB),256,BF_SMEM>>>(
        ctxH2, ctxL2, ctxtH2, ctxtL2, nullptr, nullptr, nullptr, nullptr,
        nullptr, nullptr, nullptr, cinfoH2, cinfoL2,
        PP, DD, LL/2,
        (long long)PP*(LL/2), (long long)DD*(LL/2), (long long)PP*DD);

    // 11+12) hf = tanh(h@hW^T + cinfo@hcW^T + hb + hcb); tf likewise
    bfgemm_k<true,true,false><<<dim3(12,16,1),256,BF_SMEM>>>(
        hH2, hL2, hWH2, hWL2, cinfoH2, cinfoL2, hcWH2, hcWL2,
        hb, hcb, hf, nullptr, nullptr, BB*PP, DD, DD/2, 0,0,0);
    bfgemm_k<true,true,false><<<dim3(12,16,1),256,BF_SMEM>>>(
        tH2, tL2, tWH2, tWL2, cinfoH2, cinfoL2, tcWH2, tcWL2,
        tb, tcb, tf, nullptr, nullptr, BB*PP, DD, DD/2, 0,0,0);

    // 13) classifier
    clasmma_k<<<dim3(BB*PP/128, NBK, 2), 256, CLAS_SMEM>>>(hf, tf, WtH, WtL, part);
    clas_red_k<<<(BB*PP*RR + 255)/256, 256>>>(part, clasb, out);
}

// round 6
// speedup vs baseline: 1.7098x; 1.1825x over previous
#include <cuda_runtime.h>
#include <cuda_bf16.h>
#include <cstdint>
#include <math.h>

// Problem constants
#define BB 4
#define LL 512
#define DD 768
#define HH 12
#define MM 48
#define EE 32
#define PP 512
#define RR 97
#define NBK 12      // D / 64 group blocks
#define NCH 24      // NBK * 2 (i-split)
#define KCLAS 49152 // D * 64
#define WT_U 3584   // uints (bf162 pairs) per (n,i) W fragment slice

// ---------------- scratch (device globals; allocation-free) ----------------
__device__ float g_att_sum[BB*LL*LL];
__device__ float g_mention[BB*MM*DD];
__device__ float g_tmp1[BB*MM*LL];
__device__ float g_matt[BB*MM*MM];
__device__ float g_eatt[BB*EE*MM];
__device__ float g_emtok[BB*EE*LL];
__device__ float g_entatt[BB*HH*EE*LL];
__device__ float g_hatt[BB*PP*MM];
__device__ float g_tatt[BB*PP*MM];
__device__ uint32_t g_ctxH2[BB*PP*LL/2];
__device__ uint32_t g_ctxL2[BB*PP*LL/2];
__device__ uint32_t g_hH2[BB*PP*DD/2];
__device__ uint32_t g_hL2[BB*PP*DD/2];
__device__ uint32_t g_tH2[BB*PP*DD/2];
__device__ uint32_t g_tL2[BB*PP*DD/2];
__device__ uint32_t g_cinfoH2[BB*PP*DD/2];
__device__ uint32_t g_cinfoL2[BB*PP*DD/2];
__device__ float g_hf[BB*PP*DD];
__device__ float g_tf[BB*PP*DD];
__device__ float g_part[NCH*BB*PP*RR];
// pre-split static operands (bf162 pair-packed, [rows][K/2])
__device__ uint32_t g_hWH2[DD*DD/2];
__device__ uint32_t g_hWL2[DD*DD/2];
__device__ uint32_t g_tWH2[DD*DD/2];
__device__ uint32_t g_tWL2[DD*DD/2];
__device__ uint32_t g_hcWH2[DD*DD/2];
__device__ uint32_t g_hcWL2[DD*DD/2];
__device__ uint32_t g_tcWH2[DD*DD/2];
__device__ uint32_t g_tcWL2[DD*DD/2];
__device__ uint32_t g_ctxtH2[BB*DD*LL/2];  // context transposed: [b][d][l/2]
__device__ uint32_t g_ctxtL2[BB*DD*LL/2];
__device__ uint32_t g_WtH[NBK*64*WT_U];
__device__ uint32_t g_WtL[NBK*64*WT_U];

// ---------------- bf16 helpers ----------------
static __device__ __forceinline__ uint32_t pk2(float e0, float e1) {
    uint32_t r;
    asm("cvt.rn.bf16x2.f32 %0, %1, %2;" : "=r"(r) : "f"(e1), "f"(e0));
    return r; // lo = e0, hi = e1
}
static __device__ __forceinline__ void splitbf(float e0, float e1,
                                               uint32_t& H, uint32_t& L) {
    H = pk2(e0, e1);
    float h0 = __uint_as_float(H << 16);
    float h1 = __uint_as_float(H & 0xffff0000u);
    L = pk2(e0 - h0, e1 - h1);
}
static __device__ __forceinline__ void mma_bf(float* c, const uint32_t* a,
                                              uint32_t b0, uint32_t b1) {
    asm volatile(
        "mma.sync.aligned.m16n8k16.row.col.f32.bf16.bf16.f32 "
        "{%0,%1,%2,%3}, {%4,%5,%6,%7}, {%8,%9}, {%0,%1,%2,%3};"
        : "+f"(c[0]), "+f"(c[1]), "+f"(c[2]), "+f"(c[3])
        : "r"(a[0]), "r"(a[1]), "r"(a[2]), "r"(a[3]), "r"(b0), "r"(b1));
}

// ---------------- preprocessing kernels ----------------
// split all 4 DxD weights in one launch
__global__ void splitall_k(const float* __restrict__ w0, const float* __restrict__ w1,
                           const float* __restrict__ w2, const float* __restrict__ w3,
                           uint32_t* __restrict__ h0, uint32_t* __restrict__ l0,
                           uint32_t* __restrict__ h1, uint32_t* __restrict__ l1,
                           uint32_t* __restrict__ h2, uint32_t* __restrict__ l2,
                           uint32_t* __restrict__ h3, uint32_t* __restrict__ l3)
{
    const int WP = DD*DD/2;
    int i = blockIdx.x * 256 + threadIdx.x;
    if (i >= 4*WP) return;
    int w = i / WP, j = i % WP;
    const float* src = (w == 0) ? w0 : (w == 1) ? w1 : (w == 2) ? w2 : w3;
    uint32_t* H = (w == 0) ? h0 : (w == 1) ? h1 : (w == 2) ? h2 : h3;
    uint32_t* L = (w == 0) ? l0 : (w == 1) ? l1 : (w == 2) ? l2 : l3;
    float2 v = ((const float2*)src)[j];
    uint32_t h, l; splitbf(v.x, v.y, h, l);
    H[j] = h; L[j] = l;
}

// context -> transposed pair-split: out[b][d][lp] = {ctx[b][2lp][d], ctx[b][2lp+1][d]}
__global__ void ctxt_k(const float* __restrict__ ctxt,
                       uint32_t* __restrict__ H, uint32_t* __restrict__ L)
{
    int idx = blockIdx.x * 256 + threadIdx.x;
    if (idx >= BB*DD*(LL/2)) return;
    int lp = idx & 255;
    int bd = idx >> 8;
    int d = bd % DD, b = bd / DD;
    float e0 = ctxt[((size_t)b*LL + 2*lp)     * DD + d];
    float e1 = ctxt[((size_t)b*LL + 2*lp + 1) * DD + d];
    uint32_t h, l; splitbf(e0, e1, h, l);
    H[idx] = h; L[idx] = l;
}

// clasW -> fragment-packed bf162 per (n,i), padded r 97..111 with zeros
__global__ void wtransform_k(const float* __restrict__ W,
                             uint32_t* __restrict__ WtH, uint32_t* __restrict__ WtL)
{
    int idx = blockIdx.x * 256 + threadIdx.x;
    if (idx >= NBK*64*WT_U) return;
    int fi = idx % WT_U;
    int ni = idx / WT_U;
    int i = ni & 63, n = ni >> 6;
    int half = fi & 1;
    int kq = (fi >> 1) & 3;
    int r = (fi >> 3) % 112;
    int s = (fi >> 3) / 112;
    int j0 = s*16 + half*8 + 2*kq;
    float w0 = 0.f, w1 = 0.f;
    if (r < RR) {
        const float* base = W + (size_t)r*KCLAS + (size_t)n*4096 + i*64;
        w0 = base[j0]; w1 = base[j0 + 1];
    }
    uint32_t h, l; splitbf(w0, w1, h, l);
    WtH[idx] = h; WtL[idx] = l;
}

// ---------------- small kernels ----------------
__global__ void att_sum_k(const float* __restrict__ att, float* __restrict__ out)
{
    int idx = blockIdx.x * 256 + threadIdx.x;
    if (idx >= BB*LL*LL) return;
    int b  = idx >> 18;
    int lm = idx & (LL*LL - 1);
    const float* p = att + (size_t)b*HH*LL*LL + lm;
    float s = 0.f;
#pragma unroll
    for (int h = 0; h < HH; ++h) s += p[(size_t)h*LL*LL];
    out[idx] = s;
}

__global__ void rownorm_k(float* __restrict__ x)
{
    int row = blockIdx.x;
    float* p = x + (size_t)row * LL;
    int t = threadIdx.x;
    float v0 = p[t], v1 = p[t + 256];
    __shared__ float sm[256];
    sm[t] = v0 + v1; __syncthreads();
    for (int o = 128; o > 0; o >>= 1) { if (t < o) sm[t] += sm[t + o]; __syncthreads(); }
    float inv = 1.f / (sm[0] + 1e-30f);
    p[t] = v0 * inv; p[t + 256] = v1 * inv;
}

__global__ void pair_att_k(const int* __restrict__ hts,
                           const float* __restrict__ emap,
                           const float* __restrict__ eatt,
                           float* __restrict__ hattO, float* __restrict__ tattO)
{
    int bp = blockIdx.x;
    int b  = bp >> 9;
    int hi = hts[(size_t)bp*2], ti = hts[(size_t)bp*2 + 1];
    float mask = (hi + ti != 0) ? 1.f : 0.f;
    int t = threadIdx.x;
    float ha = 0.f, ta = 0.f;
    if (t < MM) {
        float hm = emap[((size_t)b*EE + hi)*MM + t] * mask;
        float tm = emap[((size_t)b*EE + ti)*MM + t] * mask;
        ha = eatt[((size_t)b*EE + hi)*MM + t] * tm;
        ta = eatt[((size_t)b*EE + ti)*MM + t] * hm;
    }
    __shared__ float smh[64], smt[64];
    smh[t] = ha; smt[t] = ta; __syncthreads();
    for (int o = 32; o > 0; o >>= 1) {
        if (t < o) { smh[t] += smh[t + o]; smt[t] += smt[t + o]; }
        __syncthreads();
    }
    float invh = 1.f / (smh[0] + 1e-30f);
    float invt = 1.f / (smt[0] + 1e-30f);
    if (t < MM) {
        hattO[(size_t)bp*MM + t] = ha * invh;
        tattO[(size_t)bp*MM + t] = ta * invt;
    }
}

__global__ void ctx_k(const int* __restrict__ hts,
                      const float* __restrict__ entatt,
                      uint32_t* __restrict__ ctxH2, uint32_t* __restrict__ ctxL2)
{
    int bp = blockIdx.x; int b = bp >> 9;
    int hi = hts[(size_t)bp*2], ti = hts[(size_t)bp*2 + 1];
    float mask = (hi + ti != 0) ? 1.f : 0.f;
    int t = threadIdx.x;   // 256
    const float* base = entatt + (size_t)b*HH*EE*LL;
    float v0 = 0.f, v1 = 0.f;
#pragma unroll
    for (int h = 0; h < HH; ++h) {
        const float2* ph = (const float2*)(base + ((size_t)h*EE + hi)*LL);
        const float2* pt = (const float2*)(base + ((size_t)h*EE + ti)*LL);
        float2 x = ph[t], y = pt[t];
        v0 += x.x * y.x;
        v1 += x.y * y.y;
    }
    __shared__ float sm[256];
    sm[t] = v0 + v1; __syncthreads();
    for (int o = 128; o > 0; o >>= 1) { if (t < o) sm[t] += sm[t + o]; __syncthreads(); }
    float inv = mask / (sm[0] + 1e-30f);
    uint32_t H, L; splitbf(v0 * inv, v1 * inv, H, L);
    ctxH2[(size_t)bp*(LL/2) + t] = H;
    ctxL2[(size_t)bp*(LL/2) + t] = L;
}

__global__ void matt_k(const float* __restrict__ tmp1, const float* __restrict__ mmap,
                       float* __restrict__ matt)
{
    int gw = (blockIdx.x * 256 + threadIdx.x) >> 5;
    if (gw >= BB*MM*MM) return;
    int lane = threadIdx.x & 31;
    int b = gw / (MM*MM);
    int rem = gw % (MM*MM);
    int m = rem / MM, j = rem % MM;
    const float4* a = (const float4*)(tmp1 + ((size_t)b*MM + m)*LL);
    const float4* c = (const float4*)(mmap + ((size_t)b*MM + j)*LL);
    float s = 0.f;
#pragma unroll
    for (int k = lane; k < 128; k += 32) {
        float4 x = a[k], y = c[k];
        s += x.x*y.x + x.y*y.y + x.z*y.z + x.w*y.w;
    }
#pragma unroll
    for (int o = 16; o; o >>= 1) s += __shfl_xor_sync(0xffffffffu, s, o);
    if (lane == 0) matt[gw] = s;
}

__global__ void eatt_k(const float* __restrict__ emap, const float* __restrict__ matt,
                       float* __restrict__ eatt)
{
    int b = blockIdx.x;
    int idx = threadIdx.x;
    for (int v = idx; v < EE*MM; v += 256) {
        int e = v / MM, j = v % MM;
        float s = 0.f;
#pragma unroll
        for (int m = 0; m < MM; ++m)
            s += emap[((size_t)b*EE + e)*MM + m] * matt[(size_t)b*MM*MM + m*MM + j];
        eatt[(size_t)b*EE*MM + v] = s;
    }
}

// ---------------- generic FFMA GEMM (small steps) ----------------
template<bool SPLITPAIR>
__global__ __launch_bounds__(256)
void gemm_k(const float* __restrict__ Ag, const float* __restrict__ Bg,
            float* __restrict__ Cg, uint32_t* __restrict__ CH2, uint32_t* __restrict__ CL2,
            int M, int N, int K,
            long long sA, long long sB, long long sC,
            int dA, int dB, int dC)
{
    const int BM = 64, BN = 64, BK = 16;
    int z = blockIdx.z;
    const float* A  = Ag + (long long)(z / dA) * sA;
    const float* Bp = Bg + (long long)(z / dB) * sB;
    int row0 = blockIdx.y * BM;
    int col0 = blockIdx.x * BN;

    __shared__ float As[BK][BM + 1];
    __shared__ float Bs[BK][BN + 1];

    int tid = threadIdx.x;
    int tx = tid & 15, ty = tid >> 4;
    float acc[4][4] = {};

    for (int k0 = 0; k0 < K; k0 += BK) {
#pragma unroll
        for (int r = 0; r < 4; ++r) {
            int idx = tid + r * 256;
            int m = idx >> 4, k = idx & 15;
            float v = 0.f;
            if (row0 + m < M) v = A[(size_t)(row0 + m) * K + k0 + k];
            As[k][m] = v;
        }
#pragma unroll
        for (int r = 0; r < 4; ++r) {
            int idx = tid + r * 256;
            int k = idx >> 6, n = idx & 63;
            float v = 0.f;
            if (col0 + n < N) v = Bp[(size_t)(k0 + k) * N + col0 + n];
            Bs[k][n] = v;
        }
        __syncthreads();
#pragma unroll
        for (int k = 0; k < BK; ++k) {
            float a[4], bb[4];
#pragma unroll
            for (int i = 0; i < 4; ++i) a[i]  = As[k][ty * 4 + i];
#pragma unroll
            for (int j = 0; j < 4; ++j) bb[j] = Bs[k][tx * 4 + j];
#pragma unroll
            for (int i = 0; i < 4; ++i)
#pragma unroll
                for (int j = 0; j < 4; ++j) acc[i][j] += a[i] * bb[j];
        }
        __syncthreads();
    }

    if (SPLITPAIR) {
        uint32_t* CH = CH2 + (long long)(z / dC) * (sC / 2);
        uint32_t* CL = CL2 + (long long)(z / dC) * (sC / 2);
#pragma unroll
        for (int i = 0; i < 4; ++i) {
            int m = row0 + ty * 4 + i;
            int np = (col0 + tx * 4) >> 1;
            uint32_t H, L;
            splitbf(acc[i][0], acc[i][1], H, L);
            CH[(size_t)m * (N/2) + np]     = H;
            CL[(size_t)m * (N/2) + np]     = L;
            splitbf(acc[i][2], acc[i][3], H, L);
            CH[(size_t)m * (N/2) + np + 1] = H;
            CL[(size_t)m * (N/2) + np + 1] = L;
        }
    } else {
        float* C = Cg + (long long)(z / dC) * sC;
#pragma unroll
        for (int i = 0; i < 4; ++i) {
            int m = row0 + ty * 4 + i;
            if (m >= M) continue;
#pragma unroll
            for (int j = 0; j < 4; ++j) {
                int n = col0 + tx * 4 + j;
                if (n >= N) continue;
                C[(size_t)m * N + n] = acc[i][j];
            }
        }
    }
}

// ---------------- bf16 (3x) NT GEMM core (shared by bf10 and fused linears) ----
#define BF_SMEM ((128*20 + 64*20) * 2 * 4)
template<bool FUSE2, bool EPI, bool PAIROUT>
static __device__ __forceinline__
void bf_gemm_body(const uint32_t* __restrict__ A1H, const uint32_t* __restrict__ A1L,
                  const uint32_t* __restrict__ B1H, const uint32_t* __restrict__ B1L,
                  const uint32_t* __restrict__ A2H, const uint32_t* __restrict__ A2L,
                  const uint32_t* __restrict__ B2H, const uint32_t* __restrict__ B2L,
                  const float* __restrict__ bias1, const float* __restrict__ bias2,
                  float* __restrict__ Cf, uint32_t* __restrict__ CH2, uint32_t* __restrict__ CL2,
                  int N, int KP, int row0, int col0)
{
    extern __shared__ uint32_t usm[];
    uint32_t* AsH = usm;
    uint32_t* AsL = AsH + 128*20;
    uint32_t* BsH = AsL + 128*20;
    uint32_t* BsL = BsH + 64*20;

    int tid = threadIdx.x, lane = tid & 31, wid = tid >> 5;
    int m_off = (wid & 3) * 32, n_off = (wid >> 2) * 32;
    int g = lane >> 2, kq = lane & 3;

    float acc[2][4][4];
#pragma unroll
    for (int a = 0; a < 2; ++a)
#pragma unroll
        for (int b = 0; b < 4; ++b)
#pragma unroll
            for (int c = 0; c < 4; ++c) acc[a][b][c] = 0.f;

    const int NPASS = FUSE2 ? 2 : 1;
    for (int pass = 0; pass < NPASS; ++pass) {
        const uint32_t* AH = pass ? A2H : A1H;
        const uint32_t* AL = pass ? A2L : A1L;
        const uint32_t* BH = pass ? B2H : B1H;
        const uint32_t* BL = pass ? B2L : B1L;
        for (int kp0 = 0; kp0 < KP; kp0 += 16) {
            __syncthreads();
#pragma unroll
            for (int r2 = 0; r2 < 2; ++r2) {
                int slot = tid + r2 * 256;
                int m = slot >> 2, q = slot & 3;
                *(uint4*)(AsH + m*20 + q*4) =
                    *(const uint4*)(AH + (size_t)(row0 + m)*KP + kp0 + q*4);
                *(uint4*)(AsL + m*20 + q*4) =
                    *(const uint4*)(AL + (size_t)(row0 + m)*KP + kp0 + q*4);
            }
            {
                int n = tid >> 2, q = tid & 3;
                *(uint4*)(BsH + n*20 + q*4) =
                    *(const uint4*)(BH + (size_t)(col0 + n)*KP + kp0 + q*4);
                *(uint4*)(BsL + n*20 + q*4) =
                    *(const uint4*)(BL + (size_t)(col0 + n)*KP + kp0 + q*4);
            }
            __syncthreads();
#pragma unroll
            for (int st = 0; st < 2; ++st) {
                int pb = st*8 + kq;
                uint32_t aH[2][4], aL[2][4];
#pragma unroll
                for (int mt = 0; mt < 2; ++mt) {
                    int mr = m_off + mt*16 + g;
                    aH[mt][0] = AsH[mr*20 + pb];       aL[mt][0] = AsL[mr*20 + pb];
                    aH[mt][1] = AsH[(mr+8)*20 + pb];   aL[mt][1] = AsL[(mr+8)*20 + pb];
                    aH[mt][2] = AsH[mr*20 + pb + 4];   aL[mt][2] = AsL[mr*20 + pb + 4];
                    aH[mt][3] = AsH[(mr+8)*20 + pb+4]; aL[mt][3] = AsL[(mr+8)*20 + pb+4];
                }
#pragma unroll
                for (int nt = 0; nt < 4; ++nt) {
                    int nr = n_off + nt*8 + g;
                    uint32_t bH0 = BsH[nr*20 + pb], bH1 = BsH[nr*20 + pb + 4];
                    uint32_t bL0 = BsL[nr*20 + pb], bL1 = BsL[nr*20 + pb + 4];
#pragma unroll
                    for (int mt = 0; mt < 2; ++mt) {
                        mma_bf(acc[mt][nt], aH[mt], bH0, bH1);
                        mma_bf(acc[mt][nt], aH[mt], bL0, bL1);
                        mma_bf(acc[mt][nt], aL[mt], bH0, bH1);
                    }
                }
            }
        }
    }

#pragma unroll
    for (int mt = 0; mt < 2; ++mt) {
#pragma unroll
        for (int nt = 0; nt < 4; ++nt) {
            int mr = row0 + m_off + mt*16 + g;
            int nc = col0 + n_off + nt*8 + 2*kq;
            float b0 = 0.f, b1 = 0.f;
            if (EPI) {
                b0 = bias1[nc]   + (FUSE2 ? bias2[nc]   : 0.f);
                b1 = bias1[nc+1] + (FUSE2 ? bias2[nc+1] : 0.f);
            }
            float v0 = acc[mt][nt][0] + b0;
            float v1 = acc[mt][nt][1] + b1;
            float v2 = acc[mt][nt][2] + b0;
            float v3 = acc[mt][nt][3] + b1;
            if (EPI) { v0 = tanhf(v0); v1 = tanhf(v1); v2 = tanhf(v2); v3 = tanhf(v3); }
            if (PAIROUT) {
                int np = nc >> 1;
                uint32_t H, L;
                splitbf(v0, v1, H, L);
                CH2[(size_t)mr*(N/2) + np] = H; CL2[(size_t)mr*(N/2) + np] = L;
                splitbf(v2, v3, H, L);
                CH2[(size_t)(mr+8)*(N/2) + np] = H; CL2[(size_t)(mr+8)*(N/2) + np] = L;
            } else {
                Cf[(size_t)mr * N + nc]       = v0;
                Cf[(size_t)mr * N + nc + 1]   = v1;
                Cf[(size_t)(mr+8) * N + nc]   = v2;
                Cf[(size_t)(mr+8) * N + nc+1] = v3;
            }
        }
    }
}

// bf10: cinfo = ctx @ ctxt^T, pair-split out, batched over b
__global__ __launch_bounds__(256)
void bf10_k(const uint32_t* __restrict__ AH, const uint32_t* __restrict__ AL,
            const uint32_t* __restrict__ BH, const uint32_t* __restrict__ BL,
            uint32_t* __restrict__ CH2, uint32_t* __restrict__ CL2)
{
    int z = blockIdx.z;
    const int KP = LL/2;
    bf_gemm_body<false,false,true>(
        AH + (size_t)z*PP*KP, AL + (size_t)z*PP*KP,
        BH + (size_t)z*DD*KP, BL + (size_t)z*DD*KP,
        nullptr, nullptr, nullptr, nullptr, nullptr, nullptr,
        nullptr,
        CH2 + (size_t)z*PP*(DD/2), CL2 + (size_t)z*PP*(DD/2),
        DD, KP, blockIdx.y * 128, blockIdx.x * 64);
}

// fused tanh-linears: z=0 -> hf, z=1 -> tf
__global__ __launch_bounds__(256)
void bf1112_k(const uint32_t* __restrict__ hH2, const uint32_t* __restrict__ hL2,
              const uint32_t* __restrict__ tH2, const uint32_t* __restrict__ tL2,
              const uint32_t* __restrict__ hWH2, const uint32_t* __restrict__ hWL2,
              const uint32_t* __restrict__ tWH2, const uint32_t* __restrict__ tWL2,
              const uint32_t* __restrict__ cH2, const uint32_t* __restrict__ cL2,
              const uint32_t* __restrict__ hcWH2, const uint32_t* __restrict__ hcWL2,
              const uint32_t* __restrict__ tcWH2, const uint32_t* __restrict__ tcWL2,
              const float* __restrict__ hb, const float* __restrict__ tb,
              const float* __restrict__ hcb, const float* __restrict__ tcb,
              float* __restrict__ hf, float* __restrict__ tf)
{
    int z = blockIdx.z;
    bf_gemm_body<true,true,false>(
        z ? tH2 : hH2,  z ? tL2 : hL2,
        z ? tWH2 : hWH2, z ? tWL2 : hWL2,
        cH2, cL2,
        z ? tcWH2 : hcWH2, z ? tcWL2 : hcWL2,
        z ? tb : hb, z ? tcb : hcb,
        z ? tf : hf, nullptr, nullptr,
        DD, DD/2, blockIdx.y * 128, blockIdx.x * 64);
}

// ---------------- classifier: acc += h_i * (t @ W_i^T), t-splits hoisted -----
#define CLAS_SMEM (128*33*4 * 3)
__global__ __launch_bounds__(256, 1)
void clasmma_k(const float* __restrict__ Hf, const float* __restrict__ Tf,
               const uint32_t* __restrict__ WtH, const uint32_t* __restrict__ WtL,
               float* __restrict__ part)
{
    extern __shared__ char smraw[];
    float*    hs  = (float*)smraw;               // [128][33]
    uint32_t* tsH = (uint32_t*)(hs + 128*33);    // [128][33] pair-packed
    uint32_t* tsL = tsH + 128*33;

    const int n = blockIdx.y, z = blockIdx.z;
    const int p0 = blockIdx.x * 128;
    int tid = threadIdx.x, lane = tid & 31, wid = tid >> 5;
    int pbase = (wid & 3) * 32, nbase = (wid >> 2) * 56;
    int g = lane >> 2, kq = lane & 3;

    // stage h (this z-half of i) and pair-split t once per block
    for (int v = tid; v < 128*32; v += 256) {
        int p = v >> 5, q = v & 31;
        hs[p*33 + q] = Hf[(size_t)(p0 + p)*DD + n*64 + z*32 + q];
        float t0 = Tf[(size_t)(p0 + p)*DD + n*64 + 2*q];
        float t1 = Tf[(size_t)(p0 + p)*DD + n*64 + 2*q + 1];
        uint32_t H, L; splitbf(t0, t1, H, L);
        tsH[p*33 + q] = H; tsL[p*33 + q] = L;
    }
    __syncthreads();

    // hoist t A-fragments into registers (constant across all i)
    uint32_t tAH[2][4][4], tAL[2][4][4];
#pragma unroll
    for (int mt = 0; mt < 2; ++mt) {
        int pr = pbase + mt*16 + g;
#pragma unroll
        for (int s = 0; s < 4; ++s) {
            int pp = s*8 + kq;
            tAH[mt][s][0] = tsH[pr*33 + pp];       tAL[mt][s][0] = tsL[pr*33 + pp];
            tAH[mt][s][1] = tsH[(pr+8)*33 + pp];   tAL[mt][s][1] = tsL[(pr+8)*33 + pp];
            tAH[mt][s][2] = tsH[pr*33 + pp + 4];   tAL[mt][s][2] = tsL[pr*33 + pp + 4];
            tAH[mt][s][3] = tsH[(pr+8)*33 + pp+4]; tAL[mt][s][3] = tsL[(pr+8)*33 + pp+4];
        }
    }

    float acc[2][7][4];
#pragma unroll
    for (int a = 0; a < 2; ++a)
#pragma unroll
        for (int b = 0; b < 7; ++b)
#pragma unroll
            for (int c = 0; c < 4; ++c) acc[a][b][c] = 0.f;

    for (int ii = 0; ii < 32; ++ii) {
        int i = z*32 + ii;
        const uint2* WH2 = (const uint2*)(WtH + (size_t)(n*64 + i) * WT_U);
        const uint2* WL2 = (const uint2*)(WtL + (size_t)(n*64 + i) * WT_U);

        float hv0[2], hv1[2];
#pragma unroll
        for (int mt = 0; mt < 2; ++mt) {
            int pr = pbase + mt*16 + g;
            hv0[mt] = hs[pr*33 + ii];
            hv1[mt] = hs[(pr+8)*33 + ii];
        }

        float tmp[2][7][4];
#pragma unroll
        for (int a = 0; a < 2; ++a)
#pragma unroll
            for (int b = 0; b < 7; ++b)
#pragma unroll
                for (int c = 0; c < 4; ++c) tmp[a][b][c] = 0.f;

#pragma unroll
        for (int s = 0; s < 4; ++s) {
#pragma unroll
            for (int nt = 0; nt < 7; ++nt) {
                int r = nbase + nt*8 + g;
                uint2 bh = WH2[(s*112 + r)*4 + kq];
                uint2 bl = WL2[(s*112 + r)*4 + kq];
#pragma unroll
                for (int mt = 0; mt < 2; ++mt) {
                    mma_bf(tmp[mt][nt], tAH[mt][s], bh.x, bh.y);
                    mma_bf(tmp[mt][nt], tAH[mt][s], bl.x, bl.y);
                    mma_bf(tmp[mt][nt], tAL[mt][s], bh.x, bh.y);
                }
            }
        }
#pragma unroll
        for (int mt = 0; mt < 2; ++mt)
#pragma unroll
            for (int nt = 0; nt < 7; ++nt) {
                acc[mt][nt][0] += hv0[mt] * tmp[mt][nt][0];
                acc[mt][nt][1] += hv0[mt] * tmp[mt][nt][1];
                acc[mt][nt][2] += hv1[mt] * tmp[mt][nt][2];
                acc[mt][nt][3] += hv1[mt] * tmp[mt][nt][3];
            }
    }

    int chunk = n*2 + z;
    float* po = part + (size_t)chunk * (BB*PP*RR);
#pragma unroll
    for (int mt = 0; mt < 2; ++mt) {
#pragma unroll
        for (int nt = 0; nt < 7; ++nt) {
            int p = p0 + pbase + mt*16 + g;
            int r = nbase + nt*8 + 2*kq;
            if (r < RR)   po[(size_t)p*RR + r]       = acc[mt][nt][0];
            if (r+1 < RR) po[(size_t)p*RR + r + 1]   = acc[mt][nt][1];
            if (r < RR)   po[(size_t)(p+8)*RR + r]   = acc[mt][nt][2];
            if (r+1 < RR) po[(size_t)(p+8)*RR + r+1] = acc[mt][nt][3];
        }
    }
}

__global__ void clas_red_k(const float* __restrict__ part,
                           const float* __restrict__ clasb,
                           float* __restrict__ out)
{
    int idx = blockIdx.x * 256 + threadIdx.x;
    if (idx >= BB * PP * RR) return;
    int r = idx % RR;
    float s = clasb[r];
#pragma unroll
    for (int c = 0; c < NCH; ++c) s += part[(size_t)c * (BB * PP * RR) + idx];
    out[idx] = s;
}

// ---------------- host ----------------
extern "C" void kernel_launch(void* const* d_in, const int* in_sizes, int n_in,
                              void* d_out, int out_size)
{
    const float* context   = (const float*)d_in[0];
    const float* attention = (const float*)d_in[1];
    const float* mmap      = (const float*)d_in[2];
    const float* emap      = (const float*)d_in[3];
    const int*   hts       = (const int*)d_in[4];
    const float* hW   = (const float*)d_in[5];
    const float* hb   = (const float*)d_in[6];
    const float* tW   = (const float*)d_in[7];
    const float* tb   = (const float*)d_in[8];
    const float* hcW  = (const float*)d_in[9];
    const float* hcb  = (const float*)d_in[10];
    const float* tcW  = (const float*)d_in[11];
    const float* tcb  = (const float*)d_in[12];
    const float* clasW = (const float*)d_in[13];
    const float* clasb = (const float*)d_in[14];
    float* out = (float*)d_out;

#define GETF(p, s) float* p; cudaGetSymbolAddress((void**)&p, s)
#define GETU(p, s) uint32_t* p; cudaGetSymbolAddress((void**)&p, s)
    GETF(att_sum, g_att_sum); GETF(mention, g_mention); GETF(tmp1, g_tmp1);
    GETF(matt, g_matt); GETF(eatt, g_eatt); GETF(emtok, g_emtok);
    GETF(entatt, g_entatt); GETF(hatt, g_hatt); GETF(tatt, g_tatt);
    GETU(ctxH2, g_ctxH2); GETU(ctxL2, g_ctxL2);
    GETU(hH2, g_hH2); GETU(hL2, g_hL2); GETU(tH2, g_tH2); GETU(tL2, g_tL2);
    GETU(cinfoH2, g_cinfoH2); GETU(cinfoL2, g_cinfoL2);
    GETF(hf, g_hf); GETF(tf, g_tf); GETF(part, g_part);
    GETU(hWH2, g_hWH2); GETU(hWL2, g_hWL2); GETU(tWH2, g_tWH2); GETU(tWL2, g_tWL2);
    GETU(hcWH2, g_hcWH2); GETU(hcWL2, g_hcWL2); GETU(tcWH2, g_tcWH2); GETU(tcWL2, g_tcWL2);
    GETU(ctxtH2, g_ctxtH2); GETU(ctxtL2, g_ctxtL2);
    GETU(WtH, g_WtH); GETU(WtL, g_WtL);
#undef GETF
#undef GETU

    cudaFuncSetAttribute(clasmma_k, cudaFuncAttributeMaxDynamicSharedMemorySize, CLAS_SMEM);

    // 0) static operand preprocessing
    const int WP = DD*DD/2;
    splitall_k<<<(4*WP+255)/256, 256>>>(hW, tW, hcW, tcW,
        hWH2, hWL2, tWH2, tWL2, hcWH2, hcWL2, tcWH2, tcWL2);
    ctxt_k<<<(BB*DD*(LL/2)+255)/256, 256>>>(context, ctxtH2, ctxtL2);
    wtransform_k<<<(NBK*64*WT_U+255)/256, 256>>>(clasW, WtH, WtL);

    // 1) att_sum
    att_sum_k<<<(BB*LL*LL + 255)/256, 256>>>(attention, att_sum);

    // 2) mention = mention_map @ context
    gemm_k<false><<<dim3(12,1,BB),256>>>(
        mmap, context, mention, nullptr, nullptr, MM, DD, LL,
        (long long)MM*LL, (long long)LL*DD, (long long)MM*DD, 1,1,1);

    // 3) tmp1 = mention_map @ att_sum
    gemm_k<false><<<dim3(8,1,BB),256>>>(
        mmap, att_sum, tmp1, nullptr, nullptr, MM, LL, LL,
        (long long)MM*LL, (long long)LL*LL, (long long)MM*LL, 1,1,1);

    // 4) mention_att
    matt_k<<<(BB*MM*MM*32 + 255)/256, 256>>>(tmp1, mmap, matt);

    // 5) entity_att
    eatt_k<<<BB, 256>>>(emap, matt, eatt);

    // 6) em_tok + normalize
    gemm_k<false><<<dim3(8,1,BB),256>>>(
        emap, mmap, emtok, nullptr, nullptr, EE, LL, MM,
        (long long)EE*MM, (long long)MM*LL, (long long)EE*LL, 1,1,1);
    rownorm_k<<<BB*EE, 256>>>(emtok);

    // 7) ent_att
    gemm_k<false><<<dim3(8,1,BB*HH),256>>>(
        emtok, attention, entatt, nullptr, nullptr, EE, LL, LL,
        (long long)EE*LL, (long long)LL*LL, (long long)EE*LL, HH,1,1);

    // 8) per-pair vectors
    pair_att_k<<<BB*PP, 64>>>(hts, emap, eatt, hatt, tatt);
    ctx_k<<<BB*PP, 256>>>(hts, entatt, ctxH2, ctxL2);

    // 9) h, t (FFMA, pair-split epilogue)
    gemm_k<true><<<dim3(12,8,BB),256>>>(
        tatt, mention, nullptr, hH2, hL2, PP, DD, MM,
        (long long)PP*MM, (long long)MM*DD, (long long)PP*DD, 1,1,1);
    gemm_k<true><<<dim3(12,8,BB),256>>>(
        hatt, mention, nullptr, tH2, tL2, PP, DD, MM,
        (long long)PP*MM, (long long)MM*DD, (long long)PP*DD, 1,1,1);

    // 10) context_info (bf16x3 NT, pair-split out)
    bf10_k<<<dim3(12,4,BB),256,BF_SMEM>>>(ctxH2, ctxL2, ctxtH2, ctxtL2,
                                          cinfoH2, cinfoL2);

    // 11+12) fused: hf/tf = tanh(x@W^T + cinfo@cW^T + biases), z picks h/t
    bf1112_k<<<dim3(12,16,2),256,BF_SMEM>>>(
        hH2, hL2, tH2, tL2, hWH2, hWL2, tWH2, tWL2,
        cinfoH2, cinfoL2, hcWH2, hcWL2, tcWH2, tcWL2,
        hb, tb, hcb, tcb, hf, tf);

    // 13) classifier
    clasmma_k<<<dim3(BB*PP/128, NBK, 2), 256, CLAS_SMEM>>>(hf, tf, WtH, WtL, part);
    clas_red_k<<<(BB*PP*RR + 255)/256, 256>>>(part, clasb, out);
}

// round 7
// speedup vs baseline: 1.7168x; 1.0041x over previous
#include <cuda_runtime.h>
#include <cuda_bf16.h>
#include <cstdint>
#include <math.h>

// Problem constants
#define BB 4
#define LL 512
#define DD 768
#define HH 12
#define MM 48
#define EE 32
#define PP 512
#define RR 97
#define NBK 12      // D / 64 group blocks
#define NCH 24      // NBK * 2 (i-split)
#define KCLAS 49152 // D * 64
#define WT_U 3584   // uints (bf162 pairs) per (n,i) W fragment slice

// ---------------- scratch (device globals; allocation-free) ----------------
__device__ float g_att_sum[BB*LL*LL];
__device__ float g_mention[BB*MM*DD];
__device__ float g_tmp1[BB*MM*LL];
__device__ float g_matt[BB*MM*MM];
__device__ float g_eatt[BB*EE*MM];
__device__ float g_emtok[BB*EE*LL];
__device__ float g_entatt[BB*HH*EE*LL];
__device__ float g_hatt[BB*PP*MM];
__device__ float g_tatt[BB*PP*MM];
__device__ uint32_t g_ctxH2[BB*PP*LL/2];
__device__ uint32_t g_ctxL2[BB*PP*LL/2];
__device__ uint32_t g_hH2[BB*PP*DD/2];
__device__ uint32_t g_hL2[BB*PP*DD/2];
__device__ uint32_t g_tH2[BB*PP*DD/2];
__device__ uint32_t g_tL2[BB*PP*DD/2];
__device__ uint32_t g_cinfoH2[BB*PP*DD/2];
__device__ uint32_t g_cinfoL2[BB*PP*DD/2];
__device__ float g_hf[BB*PP*DD];
__device__ float g_tf[BB*PP*DD];
__device__ float g_part[NCH*BB*PP*RR];
// pre-split static operands (bf162 pair-packed, [rows][K/2])
__device__ uint32_t g_hWH2[DD*DD/2];
__device__ uint32_t g_hWL2[DD*DD/2];
__device__ uint32_t g_tWH2[DD*DD/2];
__device__ uint32_t g_tWL2[DD*DD/2];
__device__ uint32_t g_hcWH2[DD*DD/2];
__device__ uint32_t g_hcWL2[DD*DD/2];
__device__ uint32_t g_tcWH2[DD*DD/2];
__device__ uint32_t g_tcWL2[DD*DD/2];
__device__ uint32_t g_ctxtH2[BB*DD*LL/2];  // context transposed: [b][d][l/2]
__device__ uint32_t g_ctxtL2[BB*DD*LL/2];
__device__ uint32_t g_WtH[NBK*64*WT_U];
__device__ uint32_t g_WtL[NBK*64*WT_U];

// ---------------- bf16 helpers ----------------
static __device__ __forceinline__ uint32_t pk2(float e0, float e1) {
    uint32_t r;
    asm("cvt.rn.bf16x2.f32 %0, %1, %2;" : "=r"(r) : "f"(e1), "f"(e0));
    return r; // lo = e0, hi = e1
}
static __device__ __forceinline__ void splitbf(float e0, float e1,
                                               uint32_t& H, uint32_t& L) {
    H = pk2(e0, e1);
    float h0 = __uint_as_float(H << 16);
    float h1 = __uint_as_float(H & 0xffff0000u);
    L = pk2(e0 - h0, e1 - h1);
}
static __device__ __forceinline__ void mma_bf(float* c, const uint32_t* a,
                                              uint32_t b0, uint32_t b1) {
    asm volatile(
        "mma.sync.aligned.m16n8k16.row.col.f32.bf16.bf16.f32 "
        "{%0,%1,%2,%3}, {%4,%5,%6,%7}, {%8,%9}, {%0,%1,%2,%3};"
        : "+f"(c[0]), "+f"(c[1]), "+f"(c[2]), "+f"(c[3])
        : "r"(a[0]), "r"(a[1]), "r"(a[2]), "r"(a[3]), "r"(b0), "r"(b1));
}

// ---------------- preprocessing kernels ----------------
// split all 4 DxD weights in one launch
__global__ void splitall_k(const float* __restrict__ w0, const float* __restrict__ w1,
                           const float* __restrict__ w2, const float* __restrict__ w3,
                           uint32_t* __restrict__ h0, uint32_t* __restrict__ l0,
                           uint32_t* __restrict__ h1, uint32_t* __restrict__ l1,
                           uint32_t* __restrict__ h2, uint32_t* __restrict__ l2,
                           uint32_t* __restrict__ h3, uint32_t* __restrict__ l3)
{
    const int WP = DD*DD/2;
    int i = blockIdx.x * 256 + threadIdx.x;
    if (i >= 4*WP) return;
    int w = i / WP, j = i % WP;
    const float* src = (w == 0) ? w0 : (w == 1) ? w1 : (w == 2) ? w2 : w3;
    uint32_t* H = (w == 0) ? h0 : (w == 1) ? h1 : (w == 2) ? h2 : h3;
    uint32_t* L = (w == 0) ? l0 : (w == 1) ? l1 : (w == 2) ? l2 : l3;
    float2 v = ((const float2*)src)[j];
    uint32_t h, l; splitbf(v.x, v.y, h, l);
    H[j] = h; L[j] = l;
}

// context -> transposed pair-split: out[b][d][lp] = {ctx[b][2lp][d], ctx[b][2lp+1][d]}
__global__ void ctxt_k(const float* __restrict__ ctxt,
                       uint32_t* __restrict__ H, uint32_t* __restrict__ L)
{
    int idx = blockIdx.x * 256 + threadIdx.x;
    if (idx >= BB*DD*(LL/2)) return;
    int lp = idx & 255;
    int bd = idx >> 8;
    int d = bd % DD, b = bd / DD;
    float e0 = ctxt[((size_t)b*LL + 2*lp)     * DD + d];
    float e1 = ctxt[((size_t)b*LL + 2*lp + 1) * DD + d];
    uint32_t h, l; splitbf(e0, e1, h, l);
    H[idx] = h; L[idx] = l;
}

// clasW -> fragment-packed bf162 per (n,i), padded r 97..111 with zeros
__global__ void wtransform_k(const float* __restrict__ W,
                             uint32_t* __restrict__ WtH, uint32_t* __restrict__ WtL)
{
    int idx = blockIdx.x * 256 + threadIdx.x;
    if (idx >= NBK*64*WT_U) return;
    int fi = idx % WT_U;
    int ni = idx / WT_U;
    int i = ni & 63, n = ni >> 6;
    int half = fi & 1;
    int kq = (fi >> 1) & 3;
    int r = (fi >> 3) % 112;
    int s = (fi >> 3) / 112;
    int j0 = s*16 + half*8 + 2*kq;
    float w0 = 0.f, w1 = 0.f;
    if (r < RR) {
        const float* base = W + (size_t)r*KCLAS + (size_t)n*4096 + i*64;
        w0 = base[j0]; w1 = base[j0 + 1];
    }
    uint32_t h, l; splitbf(w0, w1, h, l);
    WtH[idx] = h; WtL[idx] = l;
}

// ---------------- small kernels ----------------
__global__ void att_sum_k(const float* __restrict__ att, float* __restrict__ out)
{
    int idx = blockIdx.x * 256 + threadIdx.x;
    if (idx >= BB*LL*LL) return;
    int b  = idx >> 18;
    int lm = idx & (LL*LL - 1);
    const float* p = att + (size_t)b*HH*LL*LL + lm;
    float s = 0.f;
#pragma unroll
    for (int h = 0; h < HH; ++h) s += p[(size_t)h*LL*LL];
    out[idx] = s;
}

__global__ void rownorm_k(float* __restrict__ x)
{
    int row = blockIdx.x;
    float* p = x + (size_t)row * LL;
    int t = threadIdx.x;
    float v0 = p[t], v1 = p[t + 256];
    __shared__ float sm[256];
    sm[t] = v0 + v1; __syncthreads();
    for (int o = 128; o > 0; o >>= 1) { if (t < o) sm[t] += sm[t + o]; __syncthreads(); }
    float inv = 1.f / (sm[0] + 1e-30f);
    p[t] = v0 * inv; p[t + 256] = v1 * inv;
}

__global__ void pair_att_k(const int* __restrict__ hts,
                           const float* __restrict__ emap,
                           const float* __restrict__ eatt,
                           float* __restrict__ hattO, float* __restrict__ tattO)
{
    int bp = blockIdx.x;
    int b  = bp >> 9;
    int hi = hts[(size_t)bp*2], ti = hts[(size_t)bp*2 + 1];
    float mask = (hi + ti != 0) ? 1.f : 0.f;
    int t = threadIdx.x;
    float ha = 0.f, ta = 0.f;
    if (t < MM) {
        float hm = emap[((size_t)b*EE + hi)*MM + t] * mask;
        float tm = emap[((size_t)b*EE + ti)*MM + t] * mask;
        ha = eatt[((size_t)b*EE + hi)*MM + t] * tm;
        ta = eatt[((size_t)b*EE + ti)*MM + t] * hm;
    }
    __shared__ float smh[64], smt[64];
    smh[t] = ha; smt[t] = ta; __syncthreads();
    for (int o = 32; o > 0; o >>= 1) {
        if (t < o) { smh[t] += smh[t + o]; smt[t] += smt[t + o]; }
        __syncthreads();
    }
    float invh = 1.f / (smh[0] + 1e-30f);
    float invt = 1.f / (smt[0] + 1e-30f);
    if (t < MM) {
        hattO[(size_t)bp*MM + t] = ha * invh;
        tattO[(size_t)bp*MM + t] = ta * invt;
    }
}

__global__ void ctx_k(const int* __restrict__ hts,
                      const float* __restrict__ entatt,
                      uint32_t* __restrict__ ctxH2, uint32_t* __restrict__ ctxL2)
{
    int bp = blockIdx.x; int b = bp >> 9;
    int hi = hts[(size_t)bp*2], ti = hts[(size_t)bp*2 + 1];
    float mask = (hi + ti != 0) ? 1.f : 0.f;
    int t = threadIdx.x;   // 256
    const float* base = entatt + (size_t)b*HH*EE*LL;
    float v0 = 0.f, v1 = 0.f;
#pragma unroll
    for (int h = 0; h < HH; ++h) {
        const float2* ph = (const float2*)(base + ((size_t)h*EE + hi)*LL);
        const float2* pt = (const float2*)(base + ((size_t)h*EE + ti)*LL);
        float2 x = ph[t], y = pt[t];
        v0 += x.x * y.x;
        v1 += x.y * y.y;
    }
    __shared__ float sm[256];
    sm[t] = v0 + v1; __syncthreads();
    for (int o = 128; o > 0; o >>= 1) { if (t < o) sm[t] += sm[t + o]; __syncthreads(); }
    float inv = mask / (sm[0] + 1e-30f);
    uint32_t H, L; splitbf(v0 * inv, v1 * inv, H, L);
    ctxH2[(size_t)bp*(LL/2) + t] = H;
    ctxL2[(size_t)bp*(LL/2) + t] = L;
}

__global__ void matt_k(const float* __restrict__ tmp1, const float* __restrict__ mmap,
                       float* __restrict__ matt)
{
    int gw = (blockIdx.x * 256 + threadIdx.x) >> 5;
    if (gw >= BB*MM*MM) return;
    int lane = threadIdx.x & 31;
    int b = gw / (MM*MM);
    int rem = gw % (MM*MM);
    int m = rem / MM, j = rem % MM;
    const float4* a = (const float4*)(tmp1 + ((size_t)b*MM + m)*LL);
    const float4* c = (const float4*)(mmap + ((size_t)b*MM + j)*LL);
    float s = 0.f;
#pragma unroll
    for (int k = lane; k < 128; k += 32) {
        float4 x = a[k], y = c[k];
        s += x.x*y.x + x.y*y.y + x.z*y.z + x.w*y.w;
    }
#pragma unroll
    for (int o = 16; o; o >>= 1) s += __shfl_xor_sync(0xffffffffu, s, o);
    if (lane == 0) matt[gw] = s;
}

__global__ void eatt_k(const float* __restrict__ emap, const float* __restrict__ matt,
                       float* __restrict__ eatt)
{
    int b = blockIdx.x;
    int idx = threadIdx.x;
    for (int v = idx; v < EE*MM; v += 256) {
        int e = v / MM, j = v % MM;
        float s = 0.f;
#pragma unroll
        for (int m = 0; m < MM; ++m)
            s += emap[((size_t)b*EE + e)*MM + m] * matt[(size_t)b*MM*MM + m*MM + j];
        eatt[(size_t)b*EE*MM + v] = s;
    }
}

// ---------------- generic FFMA GEMM (small steps) ----------------
template<bool SPLITPAIR>
__global__ __launch_bounds__(256)
void gemm_k(const float* __restrict__ Ag, const float* __restrict__ Bg,
            float* __restrict__ Cg, uint32_t* __restrict__ CH2, uint32_t* __restrict__ CL2,
            int M, int N, int K,
            long long sA, long long sB, long long sC,
            int dA, int dB, int dC)
{
    const int BM = 64, BN = 64, BK = 16;
    int z = blockIdx.z;
    const float* A  = Ag + (long long)(z / dA) * sA;
    const float* Bp = Bg + (long long)(z / dB) * sB;
    int row0 = blockIdx.y * BM;
    int col0 = blockIdx.x * BN;

    __shared__ float As[BK][BM + 1];
    __shared__ float Bs[BK][BN + 1];

    int tid = threadIdx.x;
    int tx = tid & 15, ty = tid >> 4;
    float acc[4][4] = {};

    for (int k0 = 0; k0 < K; k0 += BK) {
#pragma unroll
        for (int r = 0; r < 4; ++r) {
            int idx = tid + r * 256;
            int m = idx >> 4, k = idx & 15;
            float v = 0.f;
            if (row0 + m < M) v = A[(size_t)(row0 + m) * K + k0 + k];
            As[k][m] = v;
        }
#pragma unroll
        for (int r = 0; r < 4; ++r) {
            int idx = tid + r * 256;
            int k = idx >> 6, n = idx & 63;
            float v = 0.f;
            if (col0 + n < N) v = Bp[(size_t)(k0 + k) * N + col0 + n];
            Bs[k][n] = v;
        }
        __syncthreads();
#pragma unroll
        for (int k = 0; k < BK; ++k) {
            float a[4], bb[4];
#pragma unroll
            for (int i = 0; i < 4; ++i) a[i]  = As[k][ty * 4 + i];
#pragma unroll
            for (int j = 0; j < 4; ++j) bb[j] = Bs[k][tx * 4 + j];
#pragma unroll
            for (int i = 0; i < 4; ++i)
#pragma unroll
                for (int j = 0; j < 4; ++j) acc[i][j] += a[i] * bb[j];
        }
        __syncthreads();
    }

    if (SPLITPAIR) {
        uint32_t* CH = CH2 + (long long)(z / dC) * (sC / 2);
        uint32_t* CL = CL2 + (long long)(z / dC) * (sC / 2);
#pragma unroll
        for (int i = 0; i < 4; ++i) {
            int m = row0 + ty * 4 + i;
            int np = (col0 + tx * 4) >> 1;
            uint32_t H, L;
            splitbf(acc[i][0], acc[i][1], H, L);
            CH[(size_t)m * (N/2) + np]     = H;
            CL[(size_t)m * (N/2) + np]     = L;
            splitbf(acc[i][2], acc[i][3], H, L);
            CH[(size_t)m * (N/2) + np + 1] = H;
            CL[(size_t)m * (N/2) + np + 1] = L;
        }
    } else {
        float* C = Cg + (long long)(z / dC) * sC;
#pragma unroll
        for (int i = 0; i < 4; ++i) {
            int m = row0 + ty * 4 + i;
            if (m >= M) continue;
#pragma unroll
            for (int j = 0; j < 4; ++j) {
                int n = col0 + tx * 4 + j;
                if (n >= N) continue;
                C[(size_t)m * N + n] = acc[i][j];
            }
        }
    }
}

// ---------------- bf16 (3x) NT GEMM core (shared by bf10 and fused linears) ----
#define BF_SMEM ((128*20 + 64*20) * 2 * 4)
template<bool FUSE2, bool EPI, bool PAIROUT>
static __device__ __forceinline__
void bf_gemm_body(const uint32_t* __restrict__ A1H, const uint32_t* __restrict__ A1L,
                  const uint32_t* __restrict__ B1H, const uint32_t* __restrict__ B1L,
                  const uint32_t* __restrict__ A2H, const uint32_t* __restrict__ A2L,
                  const uint32_t* __restrict__ B2H, const uint32_t* __restrict__ B2L,
                  const float* __restrict__ bias1, const float* __restrict__ bias2,
                  float* __restrict__ Cf, uint32_t* __restrict__ CH2, uint32_t* __restrict__ CL2,
                  int N, int KP, int row0, int col0)
{
    extern __shared__ uint32_t usm[];
    uint32_t* AsH = usm;
    uint32_t* AsL = AsH + 128*20;
    uint32_t* BsH = AsL + 128*20;
    uint32_t* BsL = BsH + 64*20;

    int tid = threadIdx.x, lane = tid & 31, wid = tid >> 5;
    int m_off = (wid & 3) * 32, n_off = (wid >> 2) * 32;
    int g = lane >> 2, kq = lane & 3;

    float acc[2][4][4];
#pragma unroll
    for (int a = 0; a < 2; ++a)
#pragma unroll
        for (int b = 0; b < 4; ++b)
#pragma unroll
            for (int c = 0; c < 4; ++c) acc[a][b][c] = 0.f;

    const int NPASS = FUSE2 ? 2 : 1;
    for (int pass = 0; pass < NPASS; ++pass) {
        const uint32_t* AH = pass ? A2H : A1H;
        const uint32_t* AL = pass ? A2L : A1L;
        const uint32_t* BH = pass ? B2H : B1H;
        const uint32_t* BL = pass ? B2L : B1L;
        for (int kp0 = 0; kp0 < KP; kp0 += 16) {
            __syncthreads();
#pragma unroll
            for (int r2 = 0; r2 < 2; ++r2) {
                int slot = tid + r2 * 256;
                int m = slot >> 2, q = slot & 3;
                *(uint4*)(AsH + m*20 + q*4) =
                    *(const uint4*)(AH + (size_t)(row0 + m)*KP + kp0 + q*4);
                *(uint4*)(AsL + m*20 + q*4) =
                    *(const uint4*)(AL + (size_t)(row0 + m)*KP + kp0 + q*4);
            }
            {
                int n = tid >> 2, q = tid & 3;
                *(uint4*)(BsH + n*20 + q*4) =
                    *(const uint4*)(BH + (size_t)(col0 + n)*KP + kp0 + q*4);
                *(uint4*)(BsL + n*20 + q*4) =
                    *(const uint4*)(BL + (size_t)(col0 + n)*KP + kp0 + q*4);
            }
            __syncthreads();
#pragma unroll
            for (int st = 0; st < 2; ++st) {
                int pb = st*8 + kq;
                uint32_t aH[2][4], aL[2][4];
#pragma unroll
                for (int mt = 0; mt < 2; ++mt) {
                    int mr = m_off + mt*16 + g;
                    aH[mt][0] = AsH[mr*20 + pb];       aL[mt][0] = AsL[mr*20 + pb];
                    aH[mt][1] = AsH[(mr+8)*20 + pb];   aL[mt][1] = AsL[(mr+8)*20 + pb];
                    aH[mt][2] = AsH[mr*20 + pb + 4];   aL[mt][2] = AsL[mr*20 + pb + 4];
                    aH[mt][3] = AsH[(mr+8)*20 + pb+4]; aL[mt][3] = AsL[(mr+8)*20 + pb+4];
                }
#pragma unroll
                for (int nt = 0; nt < 4; ++nt) {
                    int nr = n_off + nt*8 + g;
                    uint32_t bH0 = BsH[nr*20 + pb], bH1 = BsH[nr*20 + pb + 4];
                    uint32_t bL0 = BsL[nr*20 + pb], bL1 = BsL[nr*20 + pb + 4];
#pragma unroll
                    for (int mt = 0; mt < 2; ++mt) {
                        mma_bf(acc[mt][nt], aH[mt], bH0, bH1);
                        mma_bf(acc[mt][nt], aH[mt], bL0, bL1);
                        mma_bf(acc[mt][nt], aL[mt], bH0, bH1);
                    }
                }
            }
        }
    }

#pragma unroll
    for (int mt = 0; mt < 2; ++mt) {
#pragma unroll
        for (int nt = 0; nt < 4; ++nt) {
            int mr = row0 + m_off + mt*16 + g;
            int nc = col0 + n_off + nt*8 + 2*kq;
            float b0 = 0.f, b1 = 0.f;
            if (EPI) {
                b0 = bias1[nc]   + (FUSE2 ? bias2[nc]   : 0.f);
                b1 = bias1[nc+1] + (FUSE2 ? bias2[nc+1] : 0.f);
            }
            float v0 = acc[mt][nt][0] + b0;
            float v1 = acc[mt][nt][1] + b1;
            float v2 = acc[mt][nt][2] + b0;
            float v3 = acc[mt][nt][3] + b1;
            if (EPI) { v0 = tanhf(v0); v1 = tanhf(v1); v2 = tanhf(v2); v3 = tanhf(v3); }
            if (PAIROUT) {
                int np = nc >> 1;
                uint32_t H, L;
                splitbf(v0, v1, H, L);
                CH2[(size_t)mr*(N/2) + np] = H; CL2[(size_t)mr*(N/2) + np] = L;
                splitbf(v2, v3, H, L);
                CH2[(size_t)(mr+8)*(N/2) + np] = H; CL2[(size_t)(mr+8)*(N/2) + np] = L;
            } else {
                Cf[(size_t)mr * N + nc]       = v0;
                Cf[(size_t)mr * N + nc + 1]   = v1;
                Cf[(size_t)(mr+8) * N + nc]   = v2;
                Cf[(size_t)(mr+8) * N + nc+1] = v3;
            }
        }
    }
}

// bf10: cinfo = ctx @ ctxt^T, pair-split out, batched over b
__global__ __launch_bounds__(256)
void bf10_k(const uint32_t* __restrict__ AH, const uint32_t* __restrict__ AL,
            const uint32_t* __restrict__ BH, const uint32_t* __restrict__ BL,
            uint32_t* __restrict__ CH2, uint32_t* __restrict__ CL2)
{
    int z = blockIdx.z;
    const int KP = LL/2;
    bf_gemm_body<false,false,true>(
        AH + (size_t)z*PP*KP, AL + (size_t)z*PP*KP,
        BH + (size_t)z*DD*KP, BL + (size_t)z*DD*KP,
        nullptr, nullptr, nullptr, nullptr, nullptr, nullptr,
        nullptr,
        CH2 + (size_t)z*PP*(DD/2), CL2 + (size_t)z*PP*(DD/2),
        DD, KP, blockIdx.y * 128, blockIdx.x * 64);
}

// fused tanh-linears: z=0 -> hf, z=1 -> tf
__global__ __launch_bounds__(256)
void bf1112_k(const uint32_t* __restrict__ hH2, const uint32_t* __restrict__ hL2,
              const uint32_t* __restrict__ tH2, const uint32_t* __restrict__ tL2,
              const uint32_t* __restrict__ hWH2, const uint32_t* __restrict__ hWL2,
              const uint32_t* __restrict__ tWH2, const uint32_t* __restrict__ tWL2,
              const uint32_t* __restrict__ cH2, const uint32_t* __restrict__ cL2,
              const uint32_t* __restrict__ hcWH2, const uint32_t* __restrict__ hcWL2,
              const uint32_t* __restrict__ tcWH2, const uint32_t* __restrict__ tcWL2,
              const float* __restrict__ hb, const float* __restrict__ tb,
              const float* __restrict__ hcb, const float* __restrict__ tcb,
              float* __restrict__ hf, float* __restrict__ tf)
{
    int z = blockIdx.z;
    bf_gemm_body<true,true,false>(
        z ? tH2 : hH2,  z ? tL2 : hL2,
        z ? tWH2 : hWH2, z ? tWL2 : hWL2,
        cH2, cL2,
        z ? tcWH2 : hcWH2, z ? tcWL2 : hcWL2,
        z ? tb : hb, z ? tcb : hcb,
        z ? tf : hf, nullptr, nullptr,
        DD, DD/2, blockIdx.y * 128, blockIdx.x * 64);
}

// ---------------- classifier: acc += h_i * (t @ W_i^T), t-splits hoisted -----
#define CLAS_SMEM (128*33*4 * 3)
__global__ __launch_bounds__(256, 1)
void clasmma_k(const float* __restrict__ Hf, const float* __restrict__ Tf,
               const uint32_t* __restrict__ WtH, const uint32_t* __restrict__ WtL,
               float* __restrict__ part)
{
    extern __shared__ char smraw[];
    float*    hs  = (float*)smraw;               // [128][33]
    uint32_t* tsH = (uint32_t*)(hs + 128*33);    // [128][33] pair-packed
    uint32_t* tsL = tsH + 128*33;

    const int n = blockIdx.y, z = blockIdx.z;
    const int p0 = blockIdx.x * 128;
    int tid = threadIdx.x, lane = tid & 31, wid = tid >> 5;
    int pbase = (wid & 3) * 32, nbase = (wid >> 2) * 56;
    int g = lane >> 2, kq = lane & 3;

    // stage h (this z-half of i) and pair-split t once per block
    for (int v = tid; v < 128*32; v += 256) {
        int p = v >> 5, q = v & 31;
        hs[p*33 + q] = Hf[(size_t)(p0 + p)*DD + n*64 + z*32 + q];
        float t0 = Tf[(size_t)(p0 + p)*DD + n*64 + 2*q];
        float t1 = Tf[(size_t)(p0 + p)*DD + n*64 + 2*q + 1];
        uint32_t H, L; splitbf(t0, t1, H, L);
        tsH[p*33 + q] = H; tsL[p*33 + q] = L;
    }
    __syncthreads();

    // hoist t A-fragments into registers (constant across all i)
    uint32_t tAH[2][4][4], tAL[2][4][4];
#pragma unroll
    for (int mt = 0; mt < 2; ++mt) {
        int pr = pbase + mt*16 + g;
#pragma unroll
        for (int s = 0; s < 4; ++s) {
            int pp = s*8 + kq;
            tAH[mt][s][0] = tsH[pr*33 + pp];       tAL[mt][s][0] = tsL[pr*33 + pp];
            tAH[mt][s][1] = tsH[(pr+8)*33 + pp];   tAL[mt][s][1] = tsL[(pr+8)*33 + pp];
            tAH[mt][s][2] = tsH[pr*33 + pp + 4];   tAL[mt][s][2] = tsL[pr*33 + pp + 4];
            tAH[mt][s][3] = tsH[(pr+8)*33 + pp+4]; tAL[mt][s][3] = tsL[(pr+8)*33 + pp+4];
        }
    }

    float acc[2][7][4];
#pragma unroll
    for (int a = 0; a < 2; ++a)
#pragma unroll
        for (int b = 0; b < 7; ++b)
#pragma unroll
            for (int c = 0; c < 4; ++c) acc[a][b][c] = 0.f;

    for (int ii = 0; ii < 32; ++ii) {
        int i = z*32 + ii;
        const uint2* WH2 = (const uint2*)(WtH + (size_t)(n*64 + i) * WT_U);
        const uint2* WL2 = (const uint2*)(WtL + (size_t)(n*64 + i) * WT_U);

        float hv0[2], hv1[2];
#pragma unroll
        for (int mt = 0; mt < 2; ++mt) {
            int pr = pbase + mt*16 + g;
            hv0[mt] = hs[pr*33 + ii];
            hv1[mt] = hs[(pr+8)*33 + ii];
        }

        float tmp[2][7][4];
#pragma unroll
        for (int a = 0; a < 2; ++a)
#pragma unroll
            for (int b = 0; b < 7; ++b)
#pragma unroll
                for (int c = 0; c < 4; ++c) tmp[a][b][c] = 0.f;

#pragma unroll
        for (int s = 0; s < 4; ++s) {
#pragma unroll
            for (int nt = 0; nt < 7; ++nt) {
                int r = nbase + nt*8 + g;
                uint2 bh = WH2[(s*112 + r)*4 + kq];
                uint2 bl = WL2[(s*112 + r)*4 + kq];
#pragma unroll
                for (int mt = 0; mt < 2; ++mt) {
                    mma_bf(tmp[mt][nt], tAH[mt][s], bh.x, bh.y);
                    mma_bf(tmp[mt][nt], tAH[mt][s], bl.x, bl.y);
                    mma_bf(tmp[mt][nt], tAL[mt][s], bh.x, bh.y);
                }
            }
        }
#pragma unroll
        for (int mt = 0; mt < 2; ++mt)
#pragma unroll
            for (int nt = 0; nt < 7; ++nt) {
                acc[mt][nt][0] += hv0[mt] * tmp[mt][nt][0];
                acc[mt][nt][1] += hv0[mt] * tmp[mt][nt][1];
                acc[mt][nt][2] += hv1[mt] * tmp[mt][nt][2];
                acc[mt][nt][3] += hv1[mt] * tmp[mt][nt][3];
            }
    }

    int chunk = n*2 + z;
    float* po = part + (size_t)chunk * (BB*PP*RR);
#pragma unroll
    for (int mt = 0; mt < 2; ++mt) {
#pragma unroll
        for (int nt = 0; nt < 7; ++nt) {
            int p = p0 + pbase + mt*16 + g;
            int r = nbase + nt*8 + 2*kq;
            if (r < RR)   po[(size_t)p*RR + r]       = acc[mt][nt][0];
            if (r+1 < RR) po[(size_t)p*RR + r + 1]   = acc[mt][nt][1];
            if (r < RR)   po[(size_t)(p+8)*RR + r]   = acc[mt][nt][2];
            if (r+1 < RR) po[(size_t)(p+8)*RR + r+1] = acc[mt][nt][3];
        }
    }
}

__global__ void clas_red_k(const float* __restrict__ part,
                           const float* __restrict__ clasb,
                           float* __restrict__ out)
{
    int idx = blockIdx.x * 256 + threadIdx.x;
    if (idx >= BB * PP * RR) return;
    int r = idx % RR;
    float s = clasb[r];
#pragma unroll
    for (int c = 0; c < NCH; ++c) s += part[(size_t)c * (BB * PP * RR) + idx];
    out[idx] = s;
}

// ---------------- host ----------------
extern "C" void kernel_launch(void* const* d_in, const int* in_sizes, int n_in,
                              void* d_out, int out_size)
{
    const float* context   = (const float*)d_in[0];
    const float* attention = (const float*)d_in[1];
    const float* mmap      = (const float*)d_in[2];
    const float* emap      = (const float*)d_in[3];
    const int*   hts       = (const int*)d_in[4];
    const float* hW   = (const float*)d_in[5];
    const float* hb   = (const float*)d_in[6];
    const float* tW   = (const float*)d_in[7];
    const float* tb   = (const float*)d_in[8];
    const float* hcW  = (const float*)d_in[9];
    const float* hcb  = (const float*)d_in[10];
    const float* tcW  = (const float*)d_in[11];
    const float* tcb  = (const float*)d_in[12];
    const float* clasW = (const float*)d_in[13];
    const float* clasb = (const float*)d_in[14];
    float* out = (float*)d_out;

#define GETF(p, s) float* p; cudaGetSymbolAddress((void**)&p, s)
#define GETU(p, s) uint32_t* p; cudaGetSymbolAddress((void**)&p, s)
    GETF(att_sum, g_att_sum); GETF(mention, g_mention); GETF(tmp1, g_tmp1);
    GETF(matt, g_matt); GETF(eatt, g_eatt); GETF(emtok, g_emtok);
    GETF(entatt, g_entatt); GETF(hatt, g_hatt); GETF(tatt, g_tatt);
    GETU(ctxH2, g_ctxH2); GETU(ctxL2, g_ctxL2);
    GETU(hH2, g_hH2); GETU(hL2, g_hL2); GETU(tH2, g_tH2); GETU(tL2, g_tL2);
    GETU(cinfoH2, g_cinfoH2); GETU(cinfoL2, g_cinfoL2);
    GETF(hf, g_hf); GETF(tf, g_tf); GETF(part, g_part);
    GETU(hWH2, g_hWH2); GETU(hWL2, g_hWL2); GETU(tWH2, g_tWH2); GETU(tWL2, g_tWL2);
    GETU(hcWH2, g_hcWH2); GETU(hcWL2, g_hcWL2); GETU(tcWH2, g_tcWH2); GETU(tcWL2, g_tcWL2);
    GETU(ctxtH2, g_ctxtH2); GETU(ctxtL2, g_ctxtL2);
    GETU(WtH, g_WtH); GETU(WtL, g_WtL);
#undef GETF
#undef GETU

    cudaFuncSetAttribute(clasmma_k, cudaFuncAttributeMaxDynamicSharedMemorySize, CLAS_SMEM);

    // 0) static operand preprocessing
    const int WP = DD*DD/2;
    splitall_k<<<(4*WP+255)/256, 256>>>(hW, tW, hcW, tcW,
        hWH2, hWL2, tWH2, tWL2, hcWH2, hcWL2, tcWH2, tcWL2);
    ctxt_k<<<(BB*DD*(LL/2)+255)/256, 256>>>(context, ctxtH2, ctxtL2);
    wtransform_k<<<(NBK*64*WT_U+255)/256, 256>>>(clasW, WtH, WtL);

    // 1) att_sum
    att_sum_k<<<(BB*LL*LL + 255)/256, 256>>>(attention, att_sum);

    // 2) mention = mention_map @ context
    gemm_k<false><<<dim3(12,1,BB),256>>>(
        mmap, context, mention, nullptr, nullptr, MM, DD, LL,
        (long long)MM*LL, (long long)LL*DD, (long long)MM*DD, 1,1,1);

    // 3) tmp1 = mention_map @ att_sum
    gemm_k<false><<<dim3(8,1,BB),256>>>(
        mmap, att_sum, tmp1, nullptr, nullptr, MM, LL, LL,
        (long long)MM*LL, (long long)LL*LL, (long long)MM*LL, 1,1,1);

    // 4) mention_att
    matt_k<<<(BB*MM*MM*32 + 255)/256, 256>>>(tmp1, mmap, matt);

    // 5) entity_att
    eatt_k<<<BB, 256>>>(emap, matt, eatt);

    // 6) em_tok + normalize
    gemm_k<false><<<dim3(8,1,BB),256>>>(
        emap, mmap, emtok, nullptr, nullptr, EE, LL, MM,
        (long long)EE*MM, (long long)MM*LL, (long long)EE*LL, 1,1,1);
    rownorm_k<<<BB*EE, 256>>>(emtok);

    // 7) ent_att
    gemm_k<false><<<dim3(8,1,BB*HH),256>>>(
        emtok, attention, entatt, nullptr, nullptr, EE, LL, LL,
        (long long)EE*LL, (long long)LL*LL, (long long)EE*LL, HH,1,1);

    // 8) per-pair vectors
    pair_att_k<<<BB*PP, 64>>>(hts, emap, eatt, hatt, tatt);
    ctx_k<<<BB*PP, 256>>>(hts, entatt, ctxH2, ctxL2);

    // 9) h, t (FFMA, pair-split epilogue)
    gemm_k<true><<<dim3(12,8,BB),256>>>(
        tatt, mention, nullptr, hH2, hL2, PP, DD, MM,
        (long long)PP*MM, (long long)MM*DD, (long long)PP*DD, 1,1,1);
    gemm_k<true><<<dim3(12,8,BB),256>>>(
        hatt, mention, nullptr, tH2, tL2, PP, DD, MM,
        (long long)PP*MM, (long long)MM*DD, (long long)PP*DD, 1,1,1);

    // 10) context_info (bf16x3 NT, pair-split out)
    bf10_k<<<dim3(12,4,BB),256,BF_SMEM>>>(ctxH2, ctxL2, ctxtH2, ctxtL2,
                                          cinfoH2, cinfoL2);

    // 11+12) fused: hf/tf = tanh(x@W^T + cinfo@cW^T + biases), z picks h/t
    bf1112_k<<<dim3(12,16,2),256,BF_SMEM>>>(
        hH2, hL2, tH2, tL2, hWH2, hWL2, tWH2, tWL2,
        cinfoH2, cinfoL2, hcWH2, hcWL2, tcWH2, tcWL2,
        hb, tb, hcb, tcb, hf, tf);

    // 13) classifier
    clasmma_k<<<dim3(BB*PP/128, NBK, 2), 256, CLAS_SMEM>>>(hf, tf, WtH, WtL, part);
    clas_red_k<<<(BB*PP*RR + 255)/256, 256>>>(part, clasb, out);
}

// round 9
// speedup vs baseline: 1.7638x; 1.0274x over previous
#include <cuda_runtime.h>
#include <cuda_bf16.h>
#include <cstdint>
#include <math.h>

#define BB 4
#define LL 512
#define DD 768
#define HH 12
#define MM 48
#define EE 32
#define PP 512
#define RR 97
#define NBK 12
#define NCH 48      // NBK * 4 (i-quarter split)
#define KCLAS 49152
#define WT_U4 1792  // uint4 fragments per (n,i) W slice

// ---------------- scratch ----------------
__device__ float g_att_sum[BB*LL*LL];
__device__ float g_mention[BB*MM*DD];
__device__ float g_tmp1[BB*MM*LL];
__device__ float g_matt[BB*MM*MM];
__device__ float g_eatt[BB*EE*MM];
__device__ float g_emtok[BB*EE*LL];
__device__ float g_entatt[BB*HH*EE*LL];
__device__ float g_hatt[BB*PP*MM];
__device__ float g_tatt[BB*PP*MM];
__device__ uint32_t g_ctxH2[BB*PP*LL/2];
__device__ uint32_t g_ctxL2[BB*PP*LL/2];
__device__ uint32_t g_hH2[BB*PP*DD/2];
__device__ uint32_t g_hL2[BB*PP*DD/2];
__device__ uint32_t g_tH2[BB*PP*DD/2];
__device__ uint32_t g_tL2[BB*PP*DD/2];
__device__ uint32_t g_cinfoH2[BB*PP*DD/2];
__device__ uint32_t g_cinfoL2[BB*PP*DD/2];
__device__ float g_hf[BB*PP*DD];
__device__ float g_tf[BB*PP*DD];
__device__ float g_part[NCH*BB*PP*RR];
__device__ uint32_t g_hWH2[DD*DD/2];
__device__ uint32_t g_hWL2[DD*DD/2];
__device__ uint32_t g_tWH2[DD*DD/2];
__device__ uint32_t g_tWL2[DD*DD/2];
__device__ uint32_t g_hcWH2[DD*DD/2];
__device__ uint32_t g_hcWL2[DD*DD/2];
__device__ uint32_t g_tcWH2[DD*DD/2];
__device__ uint32_t g_tcWL2[DD*DD/2];
__device__ uint32_t g_ctxtH2[BB*DD*LL/2];
__device__ uint32_t g_ctxtL2[BB*DD*LL/2];
__device__ uint4 g_Wt[NBK*64*WT_U4];

// ---------------- bf16 helpers ----------------
static __device__ __forceinline__ uint32_t pk2(float e0, float e1) {
    uint32_t r;
    asm("cvt.rn.bf16x2.f32 %0, %1, %2;" : "=r"(r) : "f"(e1), "f"(e0));
    return r;
}
static __device__ __forceinline__ void splitbf(float e0, float e1,
                                               uint32_t& H, uint32_t& L) {
    H = pk2(e0, e1);
    float h0 = __uint_as_float(H << 16);
    float h1 = __uint_as_float(H & 0xffff0000u);
    L = pk2(e0 - h0, e1 - h1);
}
static __device__ __forceinline__ void mma_bf(float* c, const uint32_t* a,
                                              uint32_t b0, uint32_t b1) {
    asm volatile(
        "mma.sync.aligned.m16n8k16.row.col.f32.bf16.bf16.f32 "
        "{%0,%1,%2,%3}, {%4,%5,%6,%7}, {%8,%9}, {%0,%1,%2,%3};"
        : "+f"(c[0]), "+f"(c[1]), "+f"(c[2]), "+f"(c[3])
        : "r"(a[0]), "r"(a[1]), "r"(a[2]), "r"(a[3]), "r"(b0), "r"(b1));
}

// ---------------- preprocessing ----------------
__global__ void splitall_k(const float* __restrict__ w0, const float* __restrict__ w1,
                           const float* __restrict__ w2, const float* __restrict__ w3,
                           uint32_t* __restrict__ h0, uint32_t* __restrict__ l0,
                           uint32_t* __restrict__ h1, uint32_t* __restrict__ l1,
                           uint32_t* __restrict__ h2, uint32_t* __restrict__ l2,
                           uint32_t* __restrict__ h3, uint32_t* __restrict__ l3)
{
    const int WP = DD*DD/2;
    int i = blockIdx.x * 256 + threadIdx.x;
    if (i >= 4*WP) return;
    int w = i / WP, j = i % WP;
    const float* src = (w == 0) ? w0 : (w == 1) ? w1 : (w == 2) ? w2 : w3;
    uint32_t* H = (w == 0) ? h0 : (w == 1) ? h1 : (w == 2) ? h2 : h3;
    uint32_t* L = (w == 0) ? l0 : (w == 1) ? l1 : (w == 2) ? l2 : l3;
    float2 v = ((const float2*)src)[j];
    uint32_t h, l; splitbf(v.x, v.y, h, l);
    H[j] = h; L[j] = l;
}

__global__ void ctxt_k(const float* __restrict__ ctxt,
                       uint32_t* __restrict__ H, uint32_t* __restrict__ L)
{
    int idx = blockIdx.x * 256 + threadIdx.x;
    if (idx >= BB*DD*(LL/2)) return;
    int lp = idx & 255;
    int bd = idx >> 8;
    int d = bd % DD, b = bd / DD;
    float e0 = ctxt[((size_t)b*LL + 2*lp)     * DD + d];
    float e1 = ctxt[((size_t)b*LL + 2*lp + 1) * DD + d];
    uint32_t h, l; splitbf(e0, e1, h, l);
    H[idx] = h; L[idx] = l;
}

// clasW -> interleaved uint4 {H(half0), H(half1), L(half0), L(half1)}
__global__ void wtransform_k(const float* __restrict__ W, uint4* __restrict__ Wt)
{
    int idx = blockIdx.x * 256 + threadIdx.x;
    if (idx >= NBK*64*WT_U4) return;
    int fi = idx % WT_U4;
    int ni = idx / WT_U4;
    int i = ni & 63, n = ni >> 6;
    int kq = fi & 3;
    int rs = fi >> 2;
    int r = rs % 112, s = rs / 112;
    int j0 = s*16 + 2*kq;
    float w00 = 0.f, w01 = 0.f, w10 = 0.f, w11 = 0.f;
    if (r < RR) {
        const float* base = W + (size_t)r*KCLAS + (size_t)n*4096 + i*64;
        w00 = base[j0];     w01 = base[j0 + 1];
        w10 = base[j0 + 8]; w11 = base[j0 + 9];
    }
    uint4 o;
    splitbf(w00, w01, o.x, o.z);
    splitbf(w10, w11, o.y, o.w);
    Wt[idx] = o;
}

// ---------------- small kernels ----------------
__global__ void att_sum_k(const float* __restrict__ att, float* __restrict__ out)
{
    int idx = blockIdx.x * 256 + threadIdx.x;
    if (idx >= BB*LL*LL) return;
    int b  = idx >> 18;
    int lm = idx & (LL*LL - 1);
    const float* p = att + (size_t)b*HH*LL*LL + lm;
    float s = 0.f;
#pragma unroll
    for (int h = 0; h < HH; ++h) s += p[(size_t)h*LL*LL];
    out[idx] = s;
}

__global__ void rownorm_k(float* __restrict__ x)
{
    int row = blockIdx.x;
    float* p = x + (size_t)row * LL;
    int t = threadIdx.x;
    float v0 = p[t], v1 = p[t + 256];
    __shared__ float sm[256];
    sm[t] = v0 + v1; __syncthreads();
    for (int o = 128; o > 0; o >>= 1) { if (t < o) sm[t] += sm[t + o]; __syncthreads(); }
    float inv = 1.f / (sm[0] + 1e-30f);
    p[t] = v0 * inv; p[t + 256] = v1 * inv;
}

__global__ void pair_att_k(const int* __restrict__ hts,
                           const float* __restrict__ emap,
                           const float* __restrict__ eatt,
                           float* __restrict__ hattO, float* __restrict__ tattO)
{
    int bp = blockIdx.x;
    int b  = bp >> 9;
    int hi = hts[(size_t)bp*2], ti = hts[(size_t)bp*2 + 1];
    float mask = (hi + ti != 0) ? 1.f : 0.f;
    int t = threadIdx.x;
    float ha = 0.f, ta = 0.f;
    if (t < MM) {
        float hm = emap[((size_t)b*EE + hi)*MM + t] * mask;
        float tm = emap[((size_t)b*EE + ti)*MM + t] * mask;
        ha = eatt[((size_t)b*EE + hi)*MM + t] * tm;
        ta = eatt[((size_t)b*EE + ti)*MM + t] * hm;
    }
    __shared__ float smh[64], smt[64];
    smh[t] = ha; smt[t] = ta; __syncthreads();
    for (int o = 32; o > 0; o >>= 1) {
        if (t < o) { smh[t] += smh[t + o]; smt[t] += smt[t + o]; }
        __syncthreads();
    }
    float invh = 1.f / (smh[0] + 1e-30f);
    float invt = 1.f / (smt[0] + 1e-30f);
    if (t < MM) {
        hattO[(size_t)bp*MM + t] = ha * invh;
        tattO[(size_t)bp*MM + t] = ta * invt;
    }
}

__global__ void ctx_k(const int* __restrict__ hts,
                      const float* __restrict__ entatt,
                      uint32_t* __restrict__ ctxH2, uint32_t* __restrict__ ctxL2)
{
    int bp = blockIdx.x; int b = bp >> 9;
    int hi = hts[(size_t)bp*2], ti = hts[(size_t)bp*2 + 1];
    float mask = (hi + ti != 0) ? 1.f : 0.f;
    int t = threadIdx.x;
    const float* base = entatt + (size_t)b*HH*EE*LL;
    float v0 = 0.f, v1 = 0.f;
#pragma unroll
    for (int h = 0; h < HH; ++h) {
        const float2* ph = (const float2*)(base + ((size_t)h*EE + hi)*LL);
        const float2* pt = (const float2*)(base + ((size_t)h*EE + ti)*LL);
        float2 x = ph[t], y = pt[t];
        v0 += x.x * y.x;
        v1 += x.y * y.y;
    }
    __shared__ float sm[256];
    sm[t] = v0 + v1; __syncthreads();
    for (int o = 128; o > 0; o >>= 1) { if (t < o) sm[t] += sm[t + o]; __syncthreads(); }
    float inv = mask / (sm[0] + 1e-30f);
    uint32_t H, L; splitbf(v0 * inv, v1 * inv, H, L);
    ctxH2[(size_t)bp*(LL/2) + t] = H;
    ctxL2[(size_t)bp*(LL/2) + t] = L;
}

__global__ void matt_k(const float* __restrict__ tmp1, const float* __restrict__ mmap,
                       float* __restrict__ matt)
{
    int gw = (blockIdx.x * 256 + threadIdx.x) >> 5;
    if (gw >= BB*MM*MM) return;
    int lane = threadIdx.x & 31;
    int b = gw / (MM*MM);
    int rem = gw % (MM*MM);
    int m = rem / MM, j = rem % MM;
    const float4* a = (const float4*)(tmp1 + ((size_t)b*MM + m)*LL);
    const float4* c = (const float4*)(mmap + ((size_t)b*MM + j)*LL);
    float s = 0.f;
#pragma unroll
    for (int k = lane; k < 128; k += 32) {
        float4 x = a[k], y = c[k];
        s += x.x*y.x + x.y*y.y + x.z*y.z + x.w*y.w;
    }
#pragma unroll
    for (int o = 16; o; o >>= 1) s += __shfl_xor_sync(0xffffffffu, s, o);
    if (lane == 0) matt[gw] = s;
}

__global__ void eatt_k(const float* __restrict__ emap, const float* __restrict__ matt,
                       float* __restrict__ eatt)
{
    int b = blockIdx.x;
    int idx = threadIdx.x;
    for (int v = idx; v < EE*MM; v += 256) {
        int e = v / MM, j = v % MM;
        float s = 0.f;
#pragma unroll
        for (int m = 0; m < MM; ++m)
            s += emap[((size_t)b*EE + e)*MM + m] * matt[(size_t)b*MM*MM + m*MM + j];
        eatt[(size_t)b*EE*MM + v] = s;
    }
}

// ---------------- generic FFMA GEMM ----------------
template<bool SPLITPAIR>
__global__ __launch_bounds__(256)
void gemm_k(const float* __restrict__ Ag, const float* __restrict__ Bg,
            float* __restrict__ Cg, uint32_t* __restrict__ CH2, uint32_t* __restrict__ CL2,
            int M, int N, int K,
            long long sA, long long sB, long long sC,
            int dA, int dB, int dC)
{
    const int BM = 64, BN = 64, BK = 16;
    int z = blockIdx.z;
    const float* A  = Ag + (long long)(z / dA) * sA;
    const float* Bp = Bg + (long long)(z / dB) * sB;
    int row0 = blockIdx.y * BM;
    int col0 = blockIdx.x * BN;

    __shared__ float As[BK][BM + 1];
    __shared__ float Bs[BK][BN + 1];

    int tid = threadIdx.x;
    int tx = tid & 15, ty = tid >> 4;
    float acc[4][4] = {};

    for (int k0 = 0; k0 < K; k0 += BK) {
#pragma unroll
        for (int r = 0; r < 4; ++r) {
            int idx = tid + r * 256;
            int m = idx >> 4, k = idx & 15;
            float v = 0.f;
            if (row0 + m < M) v = A[(size_t)(row0 + m) * K + k0 + k];
            As[k][m] = v;
        }
#pragma unroll
        for (int r = 0; r < 4; ++r) {
            int idx = tid + r * 256;
            int k = idx >> 6, n = idx & 63;
            float v = 0.f;
            if (col0 + n < N) v = Bp[(size_t)(k0 + k) * N + col0 + n];
            Bs[k][n] = v;
        }
        __syncthreads();
#pragma unroll
        for (int k = 0; k < BK; ++k) {
            float a[4], bb[4];
#pragma unroll
            for (int i = 0; i < 4; ++i) a[i]  = As[k][ty * 4 + i];
#pragma unroll
            for (int j = 0; j < 4; ++j) bb[j] = Bs[k][tx * 4 + j];
#pragma unroll
            for (int i = 0; i < 4; ++i)
#pragma unroll
                for (int j = 0; j < 4; ++j) acc[i][j] += a[i] * bb[j];
        }
        __syncthreads();
    }

    if (SPLITPAIR) {
        uint32_t* CH = CH2 + (long long)(z / dC) * (sC / 2);
        uint32_t* CL = CL2 + (long long)(z / dC) * (sC / 2);
#pragma unroll
        for (int i = 0; i < 4; ++i) {
            int m = row0 + ty * 4 + i;
            int np = (col0 + tx * 4) >> 1;
            uint32_t H, L;
            splitbf(acc[i][0], acc[i][1], H, L);
            CH[(size_t)m * (N/2) + np]     = H;
            CL[(size_t)m * (N/2) + np]     = L;
            splitbf(acc[i][2], acc[i][3], H, L);
            CH[(size_t)m * (N/2) + np + 1] = H;
            CL[(size_t)m * (N/2) + np + 1] = L;
        }
    } else {
        float* C = Cg + (long long)(z / dC) * sC;
#pragma unroll
        for (int i = 0; i < 4; ++i) {
            int m = row0 + ty * 4 + i;
            if (m >= M) continue;
#pragma unroll
            for (int j = 0; j < 4; ++j) {
                int n = col0 + tx * 4 + j;
                if (n >= N) continue;
                C[(size_t)m * N + n] = acc[i][j];
            }
        }
    }
}

// step 9 merged: z = b + BB*sel; sel=0: h=tatt@mention, sel=1: t=hatt@mention
__global__ __launch_bounds__(256)
void ht9_k(const float* __restrict__ tatt, const float* __restrict__ hatt,
           const float* __restrict__ mention,
           uint32_t* __restrict__ hH2, uint32_t* __restrict__ hL2,
           uint32_t* __restrict__ tH2, uint32_t* __restrict__ tL2)
{
    const int BM = 64, BN = 64, BK = 16;
    int zz = blockIdx.z;
    int b = zz & (BB - 1), sel = zz >> 2;
    const float* A  = (sel ? hatt : tatt) + (size_t)b * PP * MM;
    const float* Bp = mention + (size_t)b * MM * DD;
    uint32_t* CH = (sel ? tH2 : hH2) + (size_t)b * PP * (DD/2);
    uint32_t* CL = (sel ? tL2 : hL2) + (size_t)b * PP * (DD/2);
    int row0 = blockIdx.y * BM;
    int col0 = blockIdx.x * BN;

    __shared__ float As[BK][BM + 1];
    __shared__ float Bs[BK][BN + 1];

    int tid = threadIdx.x;
    int tx = tid & 15, ty = tid >> 4;
    float acc[4][4] = {};

    for (int k0 = 0; k0 < MM; k0 += BK) {
#pragma unroll
        for (int r = 0; r < 4; ++r) {
            int idx = tid + r * 256;
            int m = idx >> 4, k = idx & 15;
            As[k][m] = A[(size_t)(row0 + m) * MM + k0 + k];
        }
#pragma unroll
        for (int r = 0; r < 4; ++r) {
            int idx = tid + r * 256;
            int k = idx >> 6, n = idx & 63;
            Bs[k][n] = Bp[(size_t)(k0 + k) * DD + col0 + n];
        }
        __syncthreads();
#pragma unroll
        for (int k = 0; k < BK; ++k) {
            float a[4], bb[4];
#pragma unroll
            for (int i = 0; i < 4; ++i) a[i]  = As[k][ty * 4 + i];
#pragma unroll
            for (int j = 0; j < 4; ++j) bb[j] = Bs[k][tx * 4 + j];
#pragma unroll
            for (int i = 0; i < 4; ++i)
#pragma unroll
                for (int j = 0; j < 4; ++j) acc[i][j] += a[i] * bb[j];
        }
        __syncthreads();
    }

#pragma unroll
    for (int i = 0; i < 4; ++i) {
        int m = row0 + ty * 4 + i;
        int np = (col0 + tx * 4) >> 1;
        uint32_t H, L;
        splitbf(acc[i][0], acc[i][1], H, L);
        CH[(size_t)m * (DD/2) + np]     = H;
        CL[(size_t)m * (DD/2) + np]     = L;
        splitbf(acc[i][2], acc[i][3], H, L);
        CH[(size_t)m * (DD/2) + np + 1] = H;
        CL[(size_t)m * (DD/2) + np + 1] = L;
    }
}

// ---------------- bf16 (3x) NT GEMM core (HMMA) ----------------
#define BF_SMEM ((128*20 + 64*20) * 2 * 4)
template<bool FUSE2, bool EPI, bool PAIROUT>
static __device__ __forceinline__
void bf_gemm_body(const uint32_t* __restrict__ A1H, const uint32_t* __restrict__ A1L,
                  const uint32_t* __restrict__ B1H, const uint32_t* __restrict__ B1L,
                  const uint32_t* __restrict__ A2H, const uint32_t* __restrict__ A2L,
                  const uint32_t* __restrict__ B2H, const uint32_t* __restrict__ B2L,
                  const float* __restrict__ bias1, const float* __restrict__ bias2,
                  float* __restrict__ Cf, uint32_t* __restrict__ CH2, uint32_t* __restrict__ CL2,
                  int N, int KP, int row0, int col0)
{
    extern __shared__ uint32_t usm[];
    uint32_t* AsH = usm;
    uint32_t* AsL = AsH + 128*20;
    uint32_t* BsH = AsL + 128*20;
    uint32_t* BsL = BsH + 64*20;

    int tid = threadIdx.x, lane = tid & 31, wid = tid >> 5;
    int m_off = (wid & 3) * 32, n_off = (wid >> 2) * 32;
    int g = lane >> 2, kq = lane & 3;

    float acc[2][4][4];
#pragma unroll
    for (int a = 0; a < 2; ++a)
#pragma unroll
        for (int b = 0; b < 4; ++b)
#pragma unroll
            for (int c = 0; c < 4; ++c) acc[a][b][c] = 0.f;

    const int NPASS = FUSE2 ? 2 : 1;
    for (int pass = 0; pass < NPASS; ++pass) {
        const uint32_t* AH = pass ? A2H : A1H;
        const uint32_t* AL = pass ? A2L : A1L;
        const uint32_t* BH = pass ? B2H : B1H;
        const uint32_t* BL = pass ? B2L : B1L;
        for (int kp0 = 0; kp0 < KP; kp0 += 16) {
            __syncthreads();
#pragma unroll
            for (int r2 = 0; r2 < 2; ++r2) {
                int slot = tid + r2 * 256;
                int m = slot >> 2, q = slot & 3;
                *(uint4*)(AsH + m*20 + q*4) =
                    *(const uint4*)(AH + (size_t)(row0 + m)*KP + kp0 + q*4);
                *(uint4*)(AsL + m*20 + q*4) =
                    *(const uint4*)(AL + (size_t)(row0 + m)*KP + kp0 + q*4);
            }
            {
                int n = tid >> 2, q = tid & 3;
                *(uint4*)(BsH + n*20 + q*4) =
                    *(const uint4*)(BH + (size_t)(col0 + n)*KP + kp0 + q*4);
                *(uint4*)(BsL + n*20 + q*4) =
                    *(const uint4*)(BL + (size_t)(col0 + n)*KP + kp0 + q*4);
            }
            __syncthreads();
#pragma unroll
            for (int st = 0; st < 2; ++st) {
                int pb = st*8 + kq;
                uint32_t aH[2][4], aL[2][4];
#pragma unroll
                for (int mt = 0; mt < 2; ++mt) {
                    int mr = m_off + mt*16 + g;
                    aH[mt][0] = AsH[mr*20 + pb];       aL[mt][0] = AsL[mr*20 + pb];
                    aH[mt][1] = AsH[(mr+8)*20 + pb];   aL[mt][1] = AsL[(mr+8)*20 + pb];
                    aH[mt][2] = AsH[mr*20 + pb + 4];   aL[mt][2] = AsL[mr*20 + pb + 4];
                    aH[mt][3] = AsH[(mr+8)*20 + pb+4]; aL[mt][3] = AsL[(mr+8)*20 + pb+4];
                }
#pragma unroll
                for (int nt = 0; nt < 4; ++nt) {
                    int nr = n_off + nt*8 + g;
                    uint32_t bH0 = BsH[nr*20 + pb], bH1 = BsH[nr*20 + pb + 4];
                    uint32_t bL0 = BsL[nr*20 + pb], bL1 = BsL[nr*20 + pb + 4];
#pragma unroll
                    for (int mt = 0; mt < 2; ++mt) {
                        mma_bf(acc[mt][nt], aH[mt], bH0, bH1);
                        mma_bf(acc[mt][nt], aH[mt], bL0, bL1);
                        mma_bf(acc[mt][nt], aL[mt], bH0, bH1);
                    }
                }
            }
        }
    }

#pragma unroll
    for (int mt = 0; mt < 2; ++mt) {
#pragma unroll
        for (int nt = 0; nt < 4; ++nt) {
            int mr = row0 + m_off + mt*16 + g;
            int nc = col0 + n_off + nt*8 + 2*kq;
            float b0 = 0.f, b1 = 0.f;
            if (EPI) {
                b0 = bias1[nc]   + (FUSE2 ? bias2[nc]   : 0.f);
                b1 = bias1[nc+1] + (FUSE2 ? bias2[nc+1] : 0.f);
            }
            float v0 = acc[mt][nt][0] + b0;
            float v1 = acc[mt][nt][1] + b1;
            float v2 = acc[mt][nt][2] + b0;
            float v3 = acc[mt][nt][3] + b1;
            if (EPI) { v0 = tanhf(v0); v1 = tanhf(v1); v2 = tanhf(v2); v3 = tanhf(v3); }
            if (PAIROUT) {
                int np = nc >> 1;
                uint32_t H, L;
                splitbf(v0, v1, H, L);
                CH2[(size_t)mr*(N/2) + np] = H; CL2[(size_t)mr*(N/2) + np] = L;
                splitbf(v2, v3, H, L);
                CH2[(size_t)(mr+8)*(N/2) + np] = H; CL2[(size_t)(mr+8)*(N/2) + np] = L;
            } else {
                Cf[(size_t)mr * N + nc]       = v0;
                Cf[(size_t)mr * N + nc + 1]   = v1;
                Cf[(size_t)(mr+8) * N + nc]   = v2;
                Cf[(size_t)(mr+8) * N + nc+1] = v3;
            }
        }
    }
}

__global__ __launch_bounds__(256)
void bf10_k(const uint32_t* __restrict__ AH, const uint32_t* __restrict__ AL,
            const uint32_t* __restrict__ BH, const uint32_t* __restrict__ BL,
            uint32_t* __restrict__ CH2, uint32_t* __restrict__ CL2)
{
    int z = blockIdx.z;
    const int KP = LL/2;
    bf_gemm_body<false,false,true>(
        AH + (size_t)z*PP*KP, AL + (size_t)z*PP*KP,
        BH + (size_t)z*DD*KP, BL + (size_t)z*DD*KP,
        nullptr, nullptr, nullptr, nullptr, nullptr, nullptr,
        nullptr,
        CH2 + (size_t)z*PP*(DD/2), CL2 + (size_t)z*PP*(DD/2),
        DD, KP, blockIdx.y * 128, blockIdx.x * 64);
}

__global__ __launch_bounds__(256)
void bf1112_k(const uint32_t* __restrict__ hH2, const uint32_t* __restrict__ hL2,
              const uint32_t* __restrict__ tH2, const uint32_t* __restrict__ tL2,
              const uint32_t* __restrict__ hWH2, const uint32_t* __restrict__ hWL2,
              const uint32_t* __restrict__ tWH2, const uint32_t* __restrict__ tWL2,
              const uint32_t* __restrict__ cH2, const uint32_t* __restrict__ cL2,
              const uint32_t* __restrict__ hcWH2, const uint32_t* __restrict__ hcWL2,
              const uint32_t* __restrict__ tcWH2, const uint32_t* __restrict__ tcWL2,
              const float* __restrict__ hb, const float* __restrict__ tb,
              const float* __restrict__ hcb, const float* __restrict__ tcb,
              float* __restrict__ hf, float* __restrict__ tf)
{
    int z = blockIdx.z;
    bf_gemm_body<true,true,false>(
        z ? tH2 : hH2,  z ? tL2 : hL2,
        z ? tWH2 : hWH2, z ? tWL2 : hWL2,
        cH2, cL2,
        z ? tcWH2 : hcWH2, z ? tcWL2 : hcWL2,
        z ? tb : hb, z ? tcb : hcb,
        z ? tf : hf, nullptr, nullptr,
        DD, DD/2, blockIdx.y * 128, blockIdx.x * 64);
}

// ---------------- classifier: acc += h_i * (t @ W_i^T) (HMMA, uint4 W) -------
#define CLAS_SMEM (128*17*4 + 2*128*33*4)
__global__ __launch_bounds__(256, 1)
void clasmma_k(const float* __restrict__ Hf, const float* __restrict__ Tf,
               const uint4* __restrict__ Wt, float* __restrict__ part)
{
    extern __shared__ char smraw[];
    float*    hs  = (float*)smraw;               // [128][17]
    uint32_t* tsH = (uint32_t*)(hs + 128*17);    // [128][33]
    uint32_t* tsL = tsH + 128*33;

    const int n = blockIdx.y, z = blockIdx.z;    // z in 0..3, 16 i each
    const int p0 = blockIdx.x * 128;
    int tid = threadIdx.x, lane = tid & 31, wid = tid >> 5;
    int pbase = (wid & 3) * 32, nbase = (wid >> 2) * 56;
    int g = lane >> 2, kq = lane & 3;

    for (int v = tid; v < 128*32; v += 256) {
        int p = v >> 5, q = v & 31;
        if (q < 16)
            hs[p*17 + q] = Hf[(size_t)(p0 + p)*DD + n*64 + z*16 + q];
        float t0 = Tf[(size_t)(p0 + p)*DD + n*64 + 2*q];
        float t1 = Tf[(size_t)(p0 + p)*DD + n*64 + 2*q + 1];
        uint32_t H, L; splitbf(t0, t1, H, L);
        tsH[p*33 + q] = H; tsL[p*33 + q] = L;
    }
    __syncthreads();

    uint32_t tAH[2][4][4], tAL[2][4][4];
#pragma unroll
    for (int mt = 0; mt < 2; ++mt) {
        int pr = pbase + mt*16 + g;
#pragma unroll
        for (int s = 0; s < 4; ++s) {
            int pp = s*8 + kq;
            tAH[mt][s][0] = tsH[pr*33 + pp];       tAL[mt][s][0] = tsL[pr*33 + pp];
            tAH[mt][s][1] = tsH[(pr+8)*33 + pp];   tAL[mt][s][1] = tsL[(pr+8)*33 + pp];
            tAH[mt][s][2] = tsH[pr*33 + pp + 4];   tAL[mt][s][2] = tsL[pr*33 + pp + 4];
            tAH[mt][s][3] = tsH[(pr+8)*33 + pp+4]; tAL[mt][s][3] = tsL[(pr+8)*33 + pp+4];
        }
    }

    float acc[2][7][4];
#pragma unroll
    for (int a = 0; a < 2; ++a)
#pragma unroll
        for (int b = 0; b < 7; ++b)
#pragma unroll
            for (int c = 0; c < 4; ++c) acc[a][b][c] = 0.f;

    for (int ii = 0; ii < 16; ++ii) {
        int i = z*16 + ii;
        const uint4* W4 = Wt + (size_t)(n*64 + i) * WT_U4;

        float hv0[2], hv1[2];
#pragma unroll
        for (int mt = 0; mt < 2; ++mt) {
            int pr = pbase + mt*16 + g;
            hv0[mt] = hs[pr*17 + ii];
            hv1[mt] = hs[(pr+8)*17 + ii];
        }

        float tmp[2][7][4];
#pragma unroll
        for (int a = 0; a < 2; ++a)
#pragma unroll
            for (int b = 0; b < 7; ++b)
#pragma unroll
                for (int c = 0; c < 4; ++c) tmp[a][b][c] = 0.f;

#pragma unroll
        for (int s = 0; s < 4; ++s) {
#pragma unroll
            for (int nt = 0; nt < 7; ++nt) {
                int r = nbase + nt*8 + g;
                uint4 w4 = W4[(s*112 + r)*4 + kq];
#pragma unroll
                for (int mt = 0; mt < 2; ++mt) {
                    mma_bf(tmp[mt][nt], tAH[mt][s], w4.x, w4.y);
                    mma_bf(tmp[mt][nt], tAH[mt][s], w4.z, w4.w);
                    mma_bf(tmp[mt][nt], tAL[mt][s], w4.x, w4.y);
                }
            }
        }
#pragma unroll
        for (int mt = 0; mt < 2; ++mt)
#pragma unroll
            for (int nt = 0; nt < 7; ++nt) {
                acc[mt][nt][0] += hv0[mt] * tmp[mt][nt][0];
                acc[mt][nt][1] += hv0[mt] * tmp[mt][nt][1];
                acc[mt][nt][2] += hv1[mt] * tmp[mt][nt][2];
                acc[mt][nt][3] += hv1[mt] * tmp[mt][nt][3];
            }
    }

    int chunk = n*4 + z;
    float* po = part + (size_t)chunk * (BB*PP*RR);
#pragma unroll
    for (int mt = 0; mt < 2; ++mt) {
#pragma unroll
        for (int nt = 0; nt < 7; ++nt) {
            int p = p0 + pbase + mt*16 + g;
            int r = nbase + nt*8 + 2*kq;
            if (r < RR)   po[(size_t)p*RR + r]       = acc[mt][nt][0];
            if (r+1 < RR) po[(size_t)p*RR + r + 1]   = acc[mt][nt][1];
            if (r < RR)   po[(size_t)(p+8)*RR + r]   = acc[mt][nt][2];
            if (r+1 < RR) po[(size_t)(p+8)*RR + r+1] = acc[mt][nt][3];
        }
    }
}

__global__ void clas_red_k(const float* __restrict__ part,
                           const float* __restrict__ clasb,
                           float* __restrict__ out)
{
    int idx = blockIdx.x * 256 + threadIdx.x;
    if (idx >= BB * PP * RR) return;
    int r = idx % RR;
    float s = clasb[r];
#pragma unroll
    for (int c = 0; c < NCH; ++c) s += part[(size_t)c * (BB * PP * RR) + idx];
    out[idx] = s;
}

// ---------------- host ----------------
extern "C" void kernel_launch(void* const* d_in, const int* in_sizes, int n_in,
                              void* d_out, int out_size)
{
    const float* context   = (const float*)d_in[0];
    const float* attention = (const float*)d_in[1];
    const float* mmap      = (const float*)d_in[2];
    const float* emap      = (const float*)d_in[3];
    const int*   hts       = (const int*)d_in[4];
    const float* hW   = (const float*)d_in[5];
    const float* hb   = (const float*)d_in[6];
    const float* tW   = (const float*)d_in[7];
    const float* tb   = (const float*)d_in[8];
    const float* hcW  = (const float*)d_in[9];
    const float* hcb  = (const float*)d_in[10];
    const float* tcW  = (const float*)d_in[11];
    const float* tcb  = (const float*)d_in[12];
    const float* clasW = (const float*)d_in[13];
    const float* clasb = (const float*)d_in[14];
    float* out = (float*)d_out;

#define GETF(p, s) float* p; cudaGetSymbolAddress((void**)&p, s)
#define GETU(p, s) uint32_t* p; cudaGetSymbolAddress((void**)&p, s)
    GETF(att_sum, g_att_sum); GETF(mention, g_mention); GETF(tmp1, g_tmp1);
    GETF(matt, g_matt); GETF(eatt, g_eatt); GETF(emtok, g_emtok);
    GETF(entatt, g_entatt); GETF(hatt, g_hatt); GETF(tatt, g_tatt);
    GETU(ctxH2, g_ctxH2); GETU(ctxL2, g_ctxL2);
    GETU(hH2, g_hH2); GETU(hL2, g_hL2); GETU(tH2, g_tH2); GETU(tL2, g_tL2);
    GETU(cinfoH2, g_cinfoH2); GETU(cinfoL2, g_cinfoL2);
    GETF(hf, g_hf); GETF(tf, g_tf); GETF(part, g_part);
    GETU(hWH2, g_hWH2); GETU(hWL2, g_hWL2); GETU(tWH2, g_tWH2); GETU(tWL2, g_tWL2);
    GETU(hcWH2, g_hcWH2); GETU(hcWL2, g_hcWL2); GETU(tcWH2, g_tcWH2); GETU(tcWL2, g_tcWL2);
    GETU(ctxtH2, g_ctxtH2); GETU(ctxtL2, g_ctxtL2);
    uint4* Wt; cudaGetSymbolAddress((void**)&Wt, g_Wt);
#undef GETF
#undef GETU

    cudaFuncSetAttribute(clasmma_k, cudaFuncAttributeMaxDynamicSharedMemorySize, CLAS_SMEM);

    // 0) static operand preprocessing
    const int WP = DD*DD/2;
    splitall_k<<<(4*WP+255)/256, 256>>>(hW, tW, hcW, tcW,
        hWH2, hWL2, tWH2, tWL2, hcWH2, hcWL2, tcWH2, tcWL2);
    ctxt_k<<<(BB*DD*(LL/2)+255)/256, 256>>>(context, ctxtH2, ctxtL2);
    wtransform_k<<<(NBK*64*WT_U4+255)/256, 256>>>(clasW, Wt);

    // 1) att_sum
    att_sum_k<<<(BB*LL*LL + 255)/256, 256>>>(attention, att_sum);

    // 2) mention = mention_map @ context
    gemm_k<false><<<dim3(12,1,BB),256>>>(
        mmap, context, mention, nullptr, nullptr, MM, DD, LL,
        (long long)MM*LL, (long long)LL*DD, (long long)MM*DD, 1,1,1);

    // 3) tmp1 = mention_map @ att_sum
    gemm_k<false><<<dim3(8,1,BB),256>>>(
        mmap, att_sum, tmp1, nullptr, nullptr, MM, LL, LL,
        (long long)MM*LL, (long long)LL*LL, (long long)MM*LL, 1,1,1);

    // 4) mention_att
    matt_k<<<(BB*MM*MM*32 + 255)/256, 256>>>(tmp1, mmap, matt);

    // 5) entity_att
    eatt_k<<<BB, 256>>>(emap, matt, eatt);

    // 6) em_tok + normalize
    gemm_k<false><<<dim3(8,1,BB),256>>>(
        emap, mmap, emtok, nullptr, nullptr, EE, LL, MM,
        (long long)EE*MM, (long long)MM*LL, (long long)EE*LL, 1,1,1);
    rownorm_k<<<BB*EE, 256>>>(emtok);

    // 7) ent_att
    gemm_k<false><<<dim3(8,1,BB*HH),256>>>(
        emtok, attention, entatt, nullptr, nullptr, EE, LL, LL,
        (long long)EE*LL, (long long)LL*LL, (long long)EE*LL, HH,1,1);

    // 8) per-pair vectors
    pair_att_k<<<BB*PP, 64>>>(hts, emap, eatt, hatt, tatt);
    ctx_k<<<BB*PP, 256>>>(hts, entatt, ctxH2, ctxL2);

    // 9) h, t merged (FFMA, pair-split epilogue)
    ht9_k<<<dim3(12,8,2*BB),256>>>(tatt, hatt, mention, hH2, hL2, tH2, tL2);

    // 10) context_info (bf16x3 NT, pair-split out)
    bf10_k<<<dim3(12,4,BB),256,BF_SMEM>>>(ctxH2, ctxL2, ctxtH2, ctxtL2,
                                          cinfoH2, cinfoL2);

    // 11+12) fused: hf/tf = tanh(x@W^T + cinfo@cW^T + biases), z picks h/t
    bf1112_k<<<dim3(12,16,2),256,BF_SMEM>>>(
        hH2, hL2, tH2, tL2, hWH2, hWL2, tWH2, tWL2,
        cinfoH2, cinfoL2, hcWH2, hcWL2, tcWH2, tcWL2,
        hb, tb, hcb, tcb, hf, tf);

    // 13) classifier
    clasmma_k<<<dim3(BB*PP/128, NBK, 4), 256, CLAS_SMEM>>>(hf, tf, Wt, part);
    clas_red_k<<<(BB*PP*RR + 255)/256, 256>>>(part, clasb, out);
}

// round 10
// speedup vs baseline: 1.8621x; 1.0557x over previous
#include <cuda_runtime.h>
#include <cuda_bf16.h>
#include <cuda_fp16.h>
#include <cstdint>
#include <math.h>

#define BB 4
#define LL 512
#define DD 768
#define HH 12
#define MM 48
#define EE 32
#define PP 512
#define RR 97
#define NBK 12
#define NCH 48      // NBK * 4 (i-quarter split)
#define KCLAS 49152
#define WT_U2 1792  // uint2 fragments per (n,i) W slice

// ---------------- scratch ----------------
__device__ float g_att_sum[BB*LL*LL];
__device__ float g_mention[BB*MM*DD];
__device__ float g_tmp1[BB*MM*LL];
__device__ float g_matt[BB*MM*MM];
__device__ float g_eatt[BB*EE*MM];
__device__ float g_emtok[BB*EE*LL];
__device__ float g_entatt[BB*HH*EE*LL];
__device__ float g_hatt[BB*PP*MM];
__device__ float g_tatt[BB*PP*MM];
__device__ uint32_t g_ctxH2[BB*PP*LL/2];
__device__ uint32_t g_ctxL2[BB*PP*LL/2];
__device__ uint32_t g_hH2[BB*PP*DD/2];
__device__ uint32_t g_hL2[BB*PP*DD/2];
__device__ uint32_t g_tH2[BB*PP*DD/2];
__device__ uint32_t g_tL2[BB*PP*DD/2];
__device__ uint32_t g_cinfoH2[BB*PP*DD/2];
__device__ uint32_t g_cinfoL2[BB*PP*DD/2];
__device__ float g_hf[BB*PP*DD];
__device__ float g_tf[BB*PP*DD];
__device__ float g_part[NCH*BB*PP*RR];
__device__ uint32_t g_hWH2[DD*DD/2];
__device__ uint32_t g_hWL2[DD*DD/2];
__device__ uint32_t g_tWH2[DD*DD/2];
__device__ uint32_t g_tWL2[DD*DD/2];
__device__ uint32_t g_hcWH2[DD*DD/2];
__device__ uint32_t g_hcWL2[DD*DD/2];
__device__ uint32_t g_tcWH2[DD*DD/2];
__device__ uint32_t g_tcWL2[DD*DD/2];
__device__ uint32_t g_ctxtH2[BB*DD*LL/2];
__device__ uint32_t g_ctxtL2[BB*DD*LL/2];
__device__ uint2 g_Wt[NBK*64*WT_U2];   // plain fp16 W fragments

// ---------------- bf16 helpers ----------------
static __device__ __forceinline__ uint32_t pk2(float e0, float e1) {
    uint32_t r;
    asm("cvt.rn.bf16x2.f32 %0, %1, %2;" : "=r"(r) : "f"(e1), "f"(e0));
    return r;
}
static __device__ __forceinline__ void splitbf(float e0, float e1,
                                               uint32_t& H, uint32_t& L) {
    H = pk2(e0, e1);
    float h0 = __uint_as_float(H << 16);
    float h1 = __uint_as_float(H & 0xffff0000u);
    L = pk2(e0 - h0, e1 - h1);
}
static __device__ __forceinline__ void mma_bf(float* c, const uint32_t* a,
                                              uint32_t b0, uint32_t b1) {
    asm volatile(
        "mma.sync.aligned.m16n8k16.row.col.f32.bf16.bf16.f32 "
        "{%0,%1,%2,%3}, {%4,%5,%6,%7}, {%8,%9}, {%0,%1,%2,%3};"
        : "+f"(c[0]), "+f"(c[1]), "+f"(c[2]), "+f"(c[3])
        : "r"(a[0]), "r"(a[1]), "r"(a[2]), "r"(a[3]), "r"(b0), "r"(b1));
}

// ---------------- fp16 helpers (classifier) ----------------
static __device__ __forceinline__ uint32_t pkh2(float e0, float e1) {
    __half2 h = __floats2half2_rn(e0, e1);
    return *(uint32_t*)&h;
}
static __device__ __forceinline__ void splitfp16(float e0, float e1,
                                                 uint32_t& H, uint32_t& L) {
    __half2 h = __floats2half2_rn(e0, e1);
    float2 hf = __half22float2(h);
    __half2 l = __floats2half2_rn(e0 - hf.x, e1 - hf.y);
    H = *(uint32_t*)&h;
    L = *(uint32_t*)&l;
}
static __device__ __forceinline__ void mma_fp16(float* c, const uint32_t* a,
                                                uint32_t b0, uint32_t b1) {
    asm volatile(
        "mma.sync.aligned.m16n8k16.row.col.f32.f16.f16.f32 "
        "{%0,%1,%2,%3}, {%4,%5,%6,%7}, {%8,%9}, {%0,%1,%2,%3};"
        : "+f"(c[0]), "+f"(c[1]), "+f"(c[2]), "+f"(c[3])
        : "r"(a[0]), "r"(a[1]), "r"(a[2]), "r"(a[3]), "r"(b0), "r"(b1));
}

// ---------------- preprocessing ----------------
__global__ void splitall_k(const float* __restrict__ w0, const float* __restrict__ w1,
                           const float* __restrict__ w2, const float* __restrict__ w3,
                           uint32_t* __restrict__ h0, uint32_t* __restrict__ l0,
                           uint32_t* __restrict__ h1, uint32_t* __restrict__ l1,
                           uint32_t* __restrict__ h2, uint32_t* __restrict__ l2,
                           uint32_t* __restrict__ h3, uint32_t* __restrict__ l3)
{
    const int WP = DD*DD/2;
    int i = blockIdx.x * 256 + threadIdx.x;
    if (i >= 4*WP) return;
    int w = i / WP, j = i % WP;
    const float* src = (w == 0) ? w0 : (w == 1) ? w1 : (w == 2) ? w2 : w3;
    uint32_t* H = (w == 0) ? h0 : (w == 1) ? h1 : (w == 2) ? h2 : h3;
    uint32_t* L = (w == 0) ? l0 : (w == 1) ? l1 : (w == 2) ? l2 : l3;
    float2 v = ((const float2*)src)[j];
    uint32_t h, l; splitbf(v.x, v.y, h, l);
    H[j] = h; L[j] = l;
}

__global__ void ctxt_k(const float* __restrict__ ctxt,
                       uint32_t* __restrict__ H, uint32_t* __restrict__ L)
{
    int idx = blockIdx.x * 256 + threadIdx.x;
    if (idx >= BB*DD*(LL/2)) return;
    int lp = idx & 255;
    int bd = idx >> 8;
    int d = bd % DD, b = bd / DD;
    float e0 = ctxt[((size_t)b*LL + 2*lp)     * DD + d];
    float e1 = ctxt[((size_t)b*LL + 2*lp + 1) * DD + d];
    uint32_t h, l; splitbf(e0, e1, h, l);
    H[idx] = h; L[idx] = l;
}

// clasW -> plain fp16 fragment uint2 {f16x2(w[j0],w[j0+1]), f16x2(w[j0+8],w[j0+9])}
__global__ void wtransform_k(const float* __restrict__ W, uint2* __restrict__ Wt)
{
    int idx = blockIdx.x * 256 + threadIdx.x;
    if (idx >= NBK*64*WT_U2) return;
    int fi = idx % WT_U2;
    int ni = idx / WT_U2;
    int i = ni & 63, n = ni >> 6;
    int kq = fi & 3;
    int rs = fi >> 2;
    int r = rs % 112, s = rs / 112;
    int j0 = s*16 + 2*kq;
    float w00 = 0.f, w01 = 0.f, w10 = 0.f, w11 = 0.f;
    if (r < RR) {
        const float* base = W + (size_t)r*KCLAS + (size_t)n*4096 + i*64;
        w00 = base[j0];     w01 = base[j0 + 1];
        w10 = base[j0 + 8]; w11 = base[j0 + 9];
    }
    uint2 o;
    o.x = pkh2(w00, w01);
    o.y = pkh2(w10, w11);
    Wt[idx] = o;
}

// ---------------- small kernels ----------------
__global__ void att_sum_k(const float* __restrict__ att, float* __restrict__ out)
{
    int idx = blockIdx.x * 256 + threadIdx.x;
    if (idx >= BB*LL*LL) return;
    int b  = idx >> 18;
    int lm = idx & (LL*LL - 1);
    const float* p = att + (size_t)b*HH*LL*LL + lm;
    float s = 0.f;
#pragma unroll
    for (int h = 0; h < HH; ++h) s += p[(size_t)h*LL*LL];
    out[idx] = s;
}

__global__ void rownorm_k(float* __restrict__ x)
{
    int row = blockIdx.x;
    float* p = x + (size_t)row * LL;
    int t = threadIdx.x;
    float v0 = p[t], v1 = p[t + 256];
    __shared__ float sm[256];
    sm[t] = v0 + v1; __syncthreads();
    for (int o = 128; o > 0; o >>= 1) { if (t < o) sm[t] += sm[t + o]; __syncthreads(); }
    float inv = 1.f / (sm[0] + 1e-30f);
    p[t] = v0 * inv; p[t + 256] = v1 * inv;
}

__global__ void pair_att_k(const int* __restrict__ hts,
                           const float* __restrict__ emap,
                           const float* __restrict__ eatt,
                           float* __restrict__ hattO, float* __restrict__ tattO)
{
    int bp = blockIdx.x;
    int b  = bp >> 9;
    int hi = hts[(size_t)bp*2], ti = hts[(size_t)bp*2 + 1];
    float mask = (hi + ti != 0) ? 1.f : 0.f;
    int t = threadIdx.x;
    float ha = 0.f, ta = 0.f;
    if (t < MM) {
        float hm = emap[((size_t)b*EE + hi)*MM + t] * mask;
        float tm = emap[((size_t)b*EE + ti)*MM + t] * mask;
        ha = eatt[((size_t)b*EE + hi)*MM + t] * tm;
        ta = eatt[((size_t)b*EE + ti)*MM + t] * hm;
    }
    __shared__ float smh[64], smt[64];
    smh[t] = ha; smt[t] = ta; __syncthreads();
    for (int o = 32; o > 0; o >>= 1) {
        if (t < o) { smh[t] += smh[t + o]; smt[t] += smt[t + o]; }
        __syncthreads();
    }
    float invh = 1.f / (smh[0] + 1e-30f);
    float invt = 1.f / (smt[0] + 1e-30f);
    if (t < MM) {
        hattO[(size_t)bp*MM + t] = ha * invh;
        tattO[(size_t)bp*MM + t] = ta * invt;
    }
}

__global__ void ctx_k(const int* __restrict__ hts,
                      const float* __restrict__ entatt,
                      uint32_t* __restrict__ ctxH2, uint32_t* __restrict__ ctxL2)
{
    int bp = blockIdx.x; int b = bp >> 9;
    int hi = hts[(size_t)bp*2], ti = hts[(size_t)bp*2 + 1];
    float mask = (hi + ti != 0) ? 1.f : 0.f;
    int t = threadIdx.x;
    const float* base = entatt + (size_t)b*HH*EE*LL;
    float v0 = 0.f, v1 = 0.f;
#pragma unroll
    for (int h = 0; h < HH; ++h) {
        const float2* ph = (const float2*)(base + ((size_t)h*EE + hi)*LL);
        const float2* pt = (const float2*)(base + ((size_t)h*EE + ti)*LL);
        float2 x = ph[t], y = pt[t];
        v0 += x.x * y.x;
        v1 += x.y * y.y;
    }
    __shared__ float sm[256];
    sm[t] = v0 + v1; __syncthreads();
    for (int o = 128; o > 0; o >>= 1) { if (t < o) sm[t] += sm[t + o]; __syncthreads(); }
    float inv = mask / (sm[0] + 1e-30f);
    uint32_t H, L; splitbf(v0 * inv, v1 * inv, H, L);
    ctxH2[(size_t)bp*(LL/2) + t] = H;
    ctxL2[(size_t)bp*(LL/2) + t] = L;
}

__global__ void matt_k(const float* __restrict__ tmp1, const float* __restrict__ mmap,
                       float* __restrict__ matt)
{
    int gw = (blockIdx.x * 256 + threadIdx.x) >> 5;
    if (gw >= BB*MM*MM) return;
    int lane = threadIdx.x & 31;
    int b = gw / (MM*MM);
    int rem = gw % (MM*MM);
    int m = rem / MM, j = rem % MM;
    const float4* a = (const float4*)(tmp1 + ((size_t)b*MM + m)*LL);
    const float4* c = (const float4*)(mmap + ((size_t)b*MM + j)*LL);
    float s = 0.f;
#pragma unroll
    for (int k = lane; k < 128; k += 32) {
        float4 x = a[k], y = c[k];
        s += x.x*y.x + x.y*y.y + x.z*y.z + x.w*y.w;
    }
#pragma unroll
    for (int o = 16; o; o >>= 1) s += __shfl_xor_sync(0xffffffffu, s, o);
    if (lane == 0) matt[gw] = s;
}

__global__ void eatt_k(const float* __restrict__ emap, const float* __restrict__ matt,
                       float* __restrict__ eatt)
{
    int b = blockIdx.x;
    int idx = threadIdx.x;
    for (int v = idx; v < EE*MM; v += 256) {
        int e = v / MM, j = v % MM;
        float s = 0.f;
#pragma unroll
        for (int m = 0; m < MM; ++m)
            s += emap[((size_t)b*EE + e)*MM + m] * matt[(size_t)b*MM*MM + m*MM + j];
        eatt[(size_t)b*EE*MM + v] = s;
    }
}

// ---------------- generic FFMA GEMM ----------------
template<bool SPLITPAIR>
__global__ __launch_bounds__(256)
void gemm_k(const float* __restrict__ Ag, const float* __restrict__ Bg,
            float* __restrict__ Cg, uint32_t* __restrict__ CH2, uint32_t* __restrict__ CL2,
            int M, int N, int K,
            long long sA, long long sB, long long sC,
            int dA, int dB, int dC)
{
    const int BM = 64, BN = 64, BK = 16;
    int z = blockIdx.z;
    const float* A  = Ag + (long long)(z / dA) * sA;
    const float* Bp = Bg + (long long)(z / dB) * sB;
    int row0 = blockIdx.y * BM;
    int col0 = blockIdx.x * BN;

    __shared__ float As[BK][BM + 1];
    __shared__ float Bs[BK][BN + 1];

    int tid = threadIdx.x;
    int tx = tid & 15, ty = tid >> 4;
    float acc[4][4] = {};

    for (int k0 = 0; k0 < K; k0 += BK) {
#pragma unroll
        for (int r = 0; r < 4; ++r) {
            int idx = tid + r * 256;
            int m = idx >> 4, k = idx & 15;
            float v = 0.f;
            if (row0 + m < M) v = A[(size_t)(row0 + m) * K + k0 + k];
            As[k][m] = v;
        }
#pragma unroll
        for (int r = 0; r < 4; ++r) {
            int idx = tid + r * 256;
            int k = idx >> 6, n = idx & 63;
            float v = 0.f;
            if (col0 + n < N) v = Bp[(size_t)(k0 + k) * N + col0 + n];
            Bs[k][n] = v;
        }
        __syncthreads();
#pragma unroll
        for (int k = 0; k < BK; ++k) {
            float a[4], bb[4];
#pragma unroll
            for (int i = 0; i < 4; ++i) a[i]  = As[k][ty * 4 + i];
#pragma unroll
            for (int j = 0; j < 4; ++j) bb[j] = Bs[k][tx * 4 + j];
#pragma unroll
            for (int i = 0; i < 4; ++i)
#pragma unroll
                for (int j = 0; j < 4; ++j) acc[i][j] += a[i] * bb[j];
        }
        __syncthreads();
    }

    if (SPLITPAIR) {
        uint32_t* CH = CH2 + (long long)(z / dC) * (sC / 2);
        uint32_t* CL = CL2 + (long long)(z / dC) * (sC / 2);
#pragma unroll
        for (int i = 0; i < 4; ++i) {
            int m = row0 + ty * 4 + i;
            int np = (col0 + tx * 4) >> 1;
            uint32_t H, L;
            splitbf(acc[i][0], acc[i][1], H, L);
            CH[(size_t)m * (N/2) + np]     = H;
            CL[(size_t)m * (N/2) + np]     = L;
            splitbf(acc[i][2], acc[i][3], H, L);
            CH[(size_t)m * (N/2) + np + 1] = H;
            CL[(size_t)m * (N/2) + np + 1] = L;
        }
    } else {
        float* C = Cg + (long long)(z / dC) * sC;
#pragma unroll
        for (int i = 0; i < 4; ++i) {
            int m = row0 + ty * 4 + i;
            if (m >= M) continue;
#pragma unroll
            for (int j = 0; j < 4; ++j) {
                int n = col0 + tx * 4 + j;
                if (n >= N) continue;
                C[(size_t)m * N + n] = acc[i][j];
            }
        }
    }
}

// step 9 merged: z = b + BB*sel
__global__ __launch_bounds__(256)
void ht9_k(const float* __restrict__ tatt, const float* __restrict__ hatt,
           const float* __restrict__ mention,
           uint32_t* __restrict__ hH2, uint32_t* __restrict__ hL2,
           uint32_t* __restrict__ tH2, uint32_t* __restrict__ tL2)
{
    const int BM = 64, BN = 64, BK = 16;
    int zz = blockIdx.z;
    int b = zz & (BB - 1), sel = zz >> 2;
    const float* A  = (sel ? hatt : tatt) + (size_t)b * PP * MM;
    const float* Bp = mention + (size_t)b * MM * DD;
    uint32_t* CH = (sel ? tH2 : hH2) + (size_t)b * PP * (DD/2);
    uint32_t* CL = (sel ? tL2 : hL2) + (size_t)b * PP * (DD/2);
    int row0 = blockIdx.y * BM;
    int col0 = blockIdx.x * BN;

    __shared__ float As[BK][BM + 1];
    __shared__ float Bs[BK][BN + 1];

    int tid = threadIdx.x;
    int tx = tid & 15, ty = tid >> 4;
    float acc[4][4] = {};

    for (int k0 = 0; k0 < MM; k0 += BK) {
#pragma unroll
        for (int r = 0; r < 4; ++r) {
            int idx = tid + r * 256;
            int m = idx >> 4, k = idx & 15;
            As[k][m] = A[(size_t)(row0 + m) * MM + k0 + k];
        }
#pragma unroll
        for (int r = 0; r < 4; ++r) {
            int idx = tid + r * 256;
            int k = idx >> 6, n = idx & 63;
            Bs[k][n] = Bp[(size_t)(k0 + k) * DD + col0 + n];
        }
        __syncthreads();
#pragma unroll
        for (int k = 0; k < BK; ++k) {
            float a[4], bb[4];
#pragma unroll
            for (int i = 0; i < 4; ++i) a[i]  = As[k][ty * 4 + i];
#pragma unroll
            for (int j = 0; j < 4; ++j) bb[j] = Bs[k][tx * 4 + j];
#pragma unroll
            for (int i = 0; i < 4; ++i)
#pragma unroll
                for (int j = 0; j < 4; ++j) acc[i][j] += a[i] * bb[j];
        }
        __syncthreads();
    }

#pragma unroll
    for (int i = 0; i < 4; ++i) {
        int m = row0 + ty * 4 + i;
        int np = (col0 + tx * 4) >> 1;
        uint32_t H, L;
        splitbf(acc[i][0], acc[i][1], H, L);
        CH[(size_t)m * (DD/2) + np]     = H;
        CL[(size_t)m * (DD/2) + np]     = L;
        splitbf(acc[i][2], acc[i][3], H, L);
        CH[(size_t)m * (DD/2) + np + 1] = H;
        CL[(size_t)m * (DD/2) + np + 1] = L;
    }
}

// ---------------- bf16 (3x) NT GEMM core (HMMA) ----------------
#define BF_SMEM ((128*20 + 64*20) * 2 * 4)
template<bool FUSE2, bool EPI, bool PAIROUT>
static __device__ __forceinline__
void bf_gemm_body(const uint32_t* __restrict__ A1H, const uint32_t* __restrict__ A1L,
                  const uint32_t* __restrict__ B1H, const uint32_t* __restrict__ B1L,
                  const uint32_t* __restrict__ A2H, const uint32_t* __restrict__ A2L,
                  const uint32_t* __restrict__ B2H, const uint32_t* __restrict__ B2L,
                  const float* __restrict__ bias1, const float* __restrict__ bias2,
                  float* __restrict__ Cf, uint32_t* __restrict__ CH2, uint32_t* __restrict__ CL2,
                  int N, int KP, int row0, int col0)
{
    extern __shared__ uint32_t usm[];
    uint32_t* AsH = usm;
    uint32_t* AsL = AsH + 128*20;
    uint32_t* BsH = AsL + 128*20;
    uint32_t* BsL = BsH + 64*20;

    int tid = threadIdx.x, lane = tid & 31, wid = tid >> 5;
    int m_off = (wid & 3) * 32, n_off = (wid >> 2) * 32;
    int g = lane >> 2, kq = lane & 3;

    float acc[2][4][4];
#pragma unroll
    for (int a = 0; a < 2; ++a)
#pragma unroll
        for (int b = 0; b < 4; ++b)
#pragma unroll
            for (int c = 0; c < 4; ++c) acc[a][b][c] = 0.f;

    const int NPASS = FUSE2 ? 2 : 1;
    for (int pass = 0; pass < NPASS; ++pass) {
        const uint32_t* AH = pass ? A2H : A1H;
        const uint32_t* AL = pass ? A2L : A1L;
        const uint32_t* BH = pass ? B2H : B1H;
        const uint32_t* BL = pass ? B2L : B1L;
        for (int kp0 = 0; kp0 < KP; kp0 += 16) {
            __syncthreads();
#pragma unroll
            for (int r2 = 0; r2 < 2; ++r2) {
                int slot = tid + r2 * 256;
                int m = slot >> 2, q = slot & 3;
                *(uint4*)(AsH + m*20 + q*4) =
                    *(const uint4*)(AH + (size_t)(row0 + m)*KP + kp0 + q*4);
                *(uint4*)(AsL + m*20 + q*4) =
                    *(const uint4*)(AL + (size_t)(row0 + m)*KP + kp0 + q*4);
            }
            {
                int n = tid >> 2, q = tid & 3;
                *(uint4*)(BsH + n*20 + q*4) =
                    *(const uint4*)(BH + (size_t)(col0 + n)*KP + kp0 + q*4);
                *(uint4*)(BsL + n*20 + q*4) =
                    *(const uint4*)(BL + (size_t)(col0 + n)*KP + kp0 + q*4);
            }
            __syncthreads();
#pragma unroll
            for (int st = 0; st < 2; ++st) {
                int pb = st*8 + kq;
                uint32_t aH[2][4], aL[2][4];
#pragma unroll
                for (int mt = 0; mt < 2; ++mt) {
                    int mr = m_off + mt*16 + g;
                    aH[mt][0] = AsH[mr*20 + pb];       aL[mt][0] = AsL[mr*20 + pb];
                    aH[mt][1] = AsH[(mr+8)*20 + pb];   aL[mt][1] = AsL[(mr+8)*20 + pb];
                    aH[mt][2] = AsH[mr*20 + pb + 4];   aL[mt][2] = AsL[mr*20 + pb + 4];
                    aH[mt][3] = AsH[(mr+8)*20 + pb+4]; aL[mt][3] = AsL[(mr+8)*20 + pb+4];
                }
#pragma unroll
                for (int nt = 0; nt < 4; ++nt) {
                    int nr = n_off + nt*8 + g;
                    uint32_t bH0 = BsH[nr*20 + pb], bH1 = BsH[nr*20 + pb + 4];
                    uint32_t bL0 = BsL[nr*20 + pb], bL1 = BsL[nr*20 + pb + 4];
#pragma unroll
                    for (int mt = 0; mt < 2; ++mt) {
                        mma_bf(acc[mt][nt], aH[mt], bH0, bH1);
                        mma_bf(acc[mt][nt], aH[mt], bL0, bL1);
                        mma_bf(acc[mt][nt], aL[mt], bH0, bH1);
                    }
                }
            }
        }
    }

#pragma unroll
    for (int mt = 0; mt < 2; ++mt) {
#pragma unroll
        for (int nt = 0; nt < 4; ++nt) {
            int mr = row0 + m_off + mt*16 + g;
            int nc = col0 + n_off + nt*8 + 2*kq;
            float b0 = 0.f, b1 = 0.f;
            if (EPI) {
                b0 = bias1[nc]   + (FUSE2 ? bias2[nc]   : 0.f);
                b1 = bias1[nc+1] + (FUSE2 ? bias2[nc+1] : 0.f);
            }
            float v0 = acc[mt][nt][0] + b0;
            float v1 = acc[mt][nt][1] + b1;
            float v2 = acc[mt][nt][2] + b0;
            float v3 = acc[mt][nt][3] + b1;
            if (EPI) { v0 = tanhf(v0); v1 = tanhf(v1); v2 = tanhf(v2); v3 = tanhf(v3); }
            if (PAIROUT) {
                int np = nc >> 1;
                uint32_t H, L;
                splitbf(v0, v1, H, L);
                CH2[(size_t)mr*(N/2) + np] = H; CL2[(size_t)mr*(N/2) + np] = L;
                splitbf(v2, v3, H, L);
                CH2[(size_t)(mr+8)*(N/2) + np] = H; CL2[(size_t)(mr+8)*(N/2) + np] = L;
            } else {
                Cf[(size_t)mr * N + nc]       = v0;
                Cf[(size_t)mr * N + nc + 1]   = v1;
                Cf[(size_t)(mr+8) * N + nc]   = v2;
                Cf[(size_t)(mr+8) * N + nc+1] = v3;
            }
        }
    }
}

__global__ __launch_bounds__(256)
void bf10_k(const uint32_t* __restrict__ AH, const uint32_t* __restrict__ AL,
            const uint32_t* __restrict__ BH, const uint32_t* __restrict__ BL,
            uint32_t* __restrict__ CH2, uint32_t* __restrict__ CL2)
{
    int z = blockIdx.z;
    const int KP = LL/2;
    bf_gemm_body<false,false,true>(
        AH + (size_t)z*PP*KP, AL + (size_t)z*PP*KP,
        BH + (size_t)z*DD*KP, BL + (size_t)z*DD*KP,
        nullptr, nullptr, nullptr, nullptr, nullptr, nullptr,
        nullptr,
        CH2 + (size_t)z*PP*(DD/2), CL2 + (size_t)z*PP*(DD/2),
        DD, KP, blockIdx.y * 128, blockIdx.x * 64);
}

__global__ __launch_bounds__(256)
void bf1112_k(const uint32_t* __restrict__ hH2, const uint32_t* __restrict__ hL2,
              const uint32_t* __restrict__ tH2, const uint32_t* __restrict__ tL2,
              const uint32_t* __restrict__ hWH2, const uint32_t* __restrict__ hWL2,
              const uint32_t* __restrict__ tWH2, const uint32_t* __restrict__ tWL2,
              const uint32_t* __restrict__ cH2, const uint32_t* __restrict__ cL2,
              const uint32_t* __restrict__ hcWH2, const uint32_t* __restrict__ hcWL2,
              const uint32_t* __restrict__ tcWH2, const uint32_t* __restrict__ tcWL2,
              const float* __restrict__ hb, const float* __restrict__ tb,
              const float* __restrict__ hcb, const float* __restrict__ tcb,
              float* __restrict__ hf, float* __restrict__ tf)
{
    int z = blockIdx.z;
    bf_gemm_body<true,true,false>(
        z ? tH2 : hH2,  z ? tL2 : hL2,
        z ? tWH2 : hWH2, z ? tWL2 : hWL2,
        cH2, cL2,
        z ? tcWH2 : hcWH2, z ? tcWL2 : hcWL2,
        z ? tb : hb, z ? tcb : hcb,
        z ? tf : hf, nullptr, nullptr,
        DD, DD/2, blockIdx.y * 128, blockIdx.x * 64);
}

// ------- classifier: acc += h_i * (t @ W_i^T), fp16 2-term (t split, W plain) -
#define CLAS_SMEM (128*17*4 + 2*128*33*4)
__global__ __launch_bounds__(256, 1)
void clasmma_k(const float* __restrict__ Hf, const float* __restrict__ Tf,
               const uint2* __restrict__ Wt, float* __restrict__ part)
{
    extern __shared__ char smraw[];
    float*    hs  = (float*)smraw;               // [128][17]
    uint32_t* tsH = (uint32_t*)(hs + 128*17);    // [128][33] fp16 pair-packed
    uint32_t* tsL = tsH + 128*33;

    const int n = blockIdx.y, z = blockIdx.z;    // z in 0..3, 16 i each
    const int p0 = blockIdx.x * 128;
    int tid = threadIdx.x, lane = tid & 31, wid = tid >> 5;
    int pbase = (wid & 3) * 32, nbase = (wid >> 2) * 56;
    int g = lane >> 2, kq = lane & 3;

    for (int v = tid; v < 128*32; v += 256) {
        int p = v >> 5, q = v & 31;
        if (q < 16)
            hs[p*17 + q] = Hf[(size_t)(p0 + p)*DD + n*64 + z*16 + q];
        float t0 = Tf[(size_t)(p0 + p)*DD + n*64 + 2*q];
        float t1 = Tf[(size_t)(p0 + p)*DD + n*64 + 2*q + 1];
        uint32_t H, L; splitfp16(t0, t1, H, L);
        tsH[p*33 + q] = H; tsL[p*33 + q] = L;
    }
    __syncthreads();

    uint32_t tAH[2][4][4], tAL[2][4][4];
#pragma unroll
    for (int mt = 0; mt < 2; ++mt) {
        int pr = pbase + mt*16 + g;
#pragma unroll
        for (int s = 0; s < 4; ++s) {
            int pp = s*8 + kq;
            tAH[mt][s][0] = tsH[pr*33 + pp];       tAL[mt][s][0] = tsL[pr*33 + pp];
            tAH[mt][s][1] = tsH[(pr+8)*33 + pp];   tAL[mt][s][1] = tsL[(pr+8)*33 + pp];
            tAH[mt][s][2] = tsH[pr*33 + pp + 4];   tAL[mt][s][2] = tsL[pr*33 + pp + 4];
            tAH[mt][s][3] = tsH[(pr+8)*33 + pp+4]; tAL[mt][s][3] = tsL[(pr+8)*33 + pp+4];
        }
    }

    float acc[2][7][4];
#pragma unroll
    for (int a = 0; a < 2; ++a)
#pragma unroll
        for (int b = 0; b < 7; ++b)
#pragma unroll
            for (int c = 0; c < 4; ++c) acc[a][b][c] = 0.f;

    for (int ii = 0; ii < 16; ++ii) {
        int i = z*16 + ii;
        const uint2* W2 = Wt + (size_t)(n*64 + i) * WT_U2;

        float hv0[2], hv1[2];
#pragma unroll
        for (int mt = 0; mt < 2; ++mt) {
            int pr = pbase + mt*16 + g;
            hv0[mt] = hs[pr*17 + ii];
            hv1[mt] = hs[(pr+8)*17 + ii];
        }

        float tmp[2][7][4];
#pragma unroll
        for (int a = 0; a < 2; ++a)
#pragma unroll
            for (int b = 0; b < 7; ++b)
#pragma unroll
                for (int c = 0; c < 4; ++c) tmp[a][b][c] = 0.f;

#pragma unroll
        for (int s = 0; s < 4; ++s) {
#pragma unroll
            for (int nt = 0; nt < 7; ++nt) {
                int r = nbase + nt*8 + g;
                uint2 w2 = W2[(s*112 + r)*4 + kq];
#pragma unroll
                for (int mt = 0; mt < 2; ++mt) {
                    mma_fp16(tmp[mt][nt], tAH[mt][s], w2.x, w2.y);
                    mma_fp16(tmp[mt][nt], tAL[mt][s], w2.x, w2.y);
                }
            }
        }
#pragma unroll
        for (int mt = 0; mt < 2; ++mt)
#pragma unroll
            for (int nt = 0; nt < 7; ++nt) {
                acc[mt][nt][0] += hv0[mt] * tmp[mt][nt][0];
                acc[mt][nt][1] += hv0[mt] * tmp[mt][nt][1];
                acc[mt][nt][2] += hv1[mt] * tmp[mt][nt][2];
                acc[mt][nt][3] += hv1[mt] * tmp[mt][nt][3];
            }
    }

    int chunk = n*4 + z;
    float* po = part + (size_t)chunk * (BB*PP*RR);
#pragma unroll
    for (int mt = 0; mt < 2; ++mt) {
#pragma unroll
        for (int nt = 0; nt < 7; ++nt) {
            int p = p0 + pbase + mt*16 + g;
            int r = nbase + nt*8 + 2*kq;
            if (r < RR)   po[(size_t)p*RR + r]       = acc[mt][nt][0];
            if (r+1 < RR) po[(size_t)p*RR + r + 1]   = acc[mt][nt][1];
            if (r < RR)   po[(size_t)(p+8)*RR + r]   = acc[mt][nt][2];
            if (r+1 < RR) po[(size_t)(p+8)*RR + r+1] = acc[mt][nt][3];
        }
    }
}

__global__ void clas_red_k(const float* __restrict__ part,
                           const float* __restrict__ clasb,
                           float* __restrict__ out)
{
    int idx = blockIdx.x * 256 + threadIdx.x;
    if (idx >= BB * PP * RR) return;
    int r = idx % RR;
    float s = clasb[r];
#pragma unroll
    for (int c = 0; c < NCH; ++c) s += part[(size_t)c * (BB * PP * RR) + idx];
    out[idx] = s;
}

// ---------------- host ----------------
extern "C" void kernel_launch(void* const* d_in, const int* in_sizes, int n_in,
                              void* d_out, int out_size)
{
    const float* context   = (const float*)d_in[0];
    const float* attention = (const float*)d_in[1];
    const float* mmap      = (const float*)d_in[2];
    const float* emap      = (const float*)d_in[3];
    const int*   hts       = (const int*)d_in[4];
    const float* hW   = (const float*)d_in[5];
    const float* hb   = (const float*)d_in[6];
    const float* tW   = (const float*)d_in[7];
    const float* tb   = (const float*)d_in[8];
    const float* hcW  = (const float*)d_in[9];
    const float* hcb  = (const float*)d_in[10];
    const float* tcW  = (const float*)d_in[11];
    const float* tcb  = (const float*)d_in[12];
    const float* clasW = (const float*)d_in[13];
    const float* clasb = (const float*)d_in[14];
    float* out = (float*)d_out;

#define GETF(p, s) float* p; cudaGetSymbolAddress((void**)&p, s)
#define GETU(p, s) uint32_t* p; cudaGetSymbolAddress((void**)&p, s)
    GETF(att_sum, g_att_sum); GETF(mention, g_mention); GETF(tmp1, g_tmp1);
    GETF(matt, g_matt); GETF(eatt, g_eatt); GETF(emtok, g_emtok);
    GETF(entatt, g_entatt); GETF(hatt, g_hatt); GETF(tatt, g_tatt);
    GETU(ctxH2, g_ctxH2); GETU(ctxL2, g_ctxL2);
    GETU(hH2, g_hH2); GETU(hL2, g_hL2); GETU(tH2, g_tH2); GETU(tL2, g_tL2);
    GETU(cinfoH2, g_cinfoH2); GETU(cinfoL2, g_cinfoL2);
    GETF(hf, g_hf); GETF(tf, g_tf); GETF(part, g_part);
    GETU(hWH2, g_hWH2); GETU(hWL2, g_hWL2); GETU(tWH2, g_tWH2); GETU(tWL2, g_tWL2);
    GETU(hcWH2, g_hcWH2); GETU(hcWL2, g_hcWL2); GETU(tcWH2, g_tcWH2); GETU(tcWL2, g_tcWL2);
    GETU(ctxtH2, g_ctxtH2); GETU(ctxtL2, g_ctxtL2);
    uint2* Wt; cudaGetSymbolAddress((void**)&Wt, g_Wt);
#undef GETF
#undef GETU

    cudaFuncSetAttribute(clasmma_k, cudaFuncAttributeMaxDynamicSharedMemorySize, CLAS_SMEM);

    // 0) static operand preprocessing
    const int WP = DD*DD/2;
    splitall_k<<<(4*WP+255)/256, 256>>>(hW, tW, hcW, tcW,
        hWH2, hWL2, tWH2, tWL2, hcWH2, hcWL2, tcWH2, tcWL2);
    ctxt_k<<<(BB*DD*(LL/2)+255)/256, 256>>>(context, ctxtH2, ctxtL2);
    wtransform_k<<<(NBK*64*WT_U2+255)/256, 256>>>(clasW, Wt);

    // 1) att_sum
    att_sum_k<<<(BB*LL*LL + 255)/256, 256>>>(attention, att_sum);

    // 2) mention = mention_map @ context
    gemm_k<false><<<dim3(12,1,BB),256>>>(
        mmap, context, mention, nullptr, nullptr, MM, DD, LL,
        (long long)MM*LL, (long long)LL*DD, (long long)MM*DD, 1,1,1);

    // 3) tmp1 = mention_map @ att_sum
    gemm_k<false><<<dim3(8,1,BB),256>>>(
        mmap, att_sum, tmp1, nullptr, nullptr, MM, LL, LL,
        (long long)MM*LL, (long long)LL*LL, (long long)MM*LL, 1,1,1);

    // 4) mention_att
    matt_k<<<(BB*MM*MM*32 + 255)/256, 256>>>(tmp1, mmap, matt);

    // 5) entity_att
    eatt_k<<<BB, 256>>>(emap, matt, eatt);

    // 6) em_tok + normalize
    gemm_k<false><<<dim3(8,1,BB),256>>>(
        emap, mmap, emtok, nullptr, nullptr, EE, LL, MM,
        (long long)EE*MM, (long long)MM*LL, (long long)EE*LL, 1,1,1);
    rownorm_k<<<BB*EE, 256>>>(emtok);

    // 7) ent_att
    gemm_k<false><<<dim3(8,1,BB*HH),256>>>(
        emtok, attention, entatt, nullptr, nullptr, EE, LL, LL,
        (long long)EE*LL, (long long)LL*LL, (long long)EE*LL, HH,1,1);

    // 8) per-pair vectors
    pair_att_k<<<BB*PP, 64>>>(hts, emap, eatt, hatt, tatt);
    ctx_k<<<BB*PP, 256>>>(hts, entatt, ctxH2, ctxL2);

    // 9) h, t merged (FFMA, pair-split epilogue)
    ht9_k<<<dim3(12,8,2*BB),256>>>(tatt, hatt, mention, hH2, hL2, tH2, tL2);

    // 10) context_info (bf16x3 NT, pair-split out)
    bf10_k<<<dim3(12,4,BB),256,BF_SMEM>>>(ctxH2, ctxL2, ctxtH2, ctxtL2,
                                          cinfoH2, cinfoL2);

    // 11+12) fused: hf/tf = tanh(x@W^T + cinfo@cW^T + biases), z picks h/t
    bf1112_k<<<dim3(12,16,2),256,BF_SMEM>>>(
        hH2, hL2, tH2, tL2, hWH2, hWL2, tWH2, tWL2,
        cinfoH2, cinfoL2, hcWH2, hcWL2, tcWH2, tcWL2,
        hb, tb, hcb, tcb, hf, tf);

    // 13) classifier (fp16 2-term)
    clasmma_k<<<dim3(BB*PP/128, NBK, 4), 256, CLAS_SMEM>>>(hf, tf, Wt, part);
    clas_red_k<<<(BB*PP*RR + 255)/256, 256>>>(part, clasb, out);
}

// round 11
// speedup vs baseline: 1.9123x; 1.0270x over previous
#include <cuda_runtime.h>
#include <cuda_bf16.h>
#include <cuda_fp16.h>
#include <cstdint>
#include <math.h>

#define BB 4
#define LL 512
#define DD 768
#define HH 12
#define MM 48
#define EE 32
#define PP 512
#define RR 97
#define NBK 12
#define NCH 48      // NBK * 4 (i-quarter split)
#define KCLAS 49152
#define WT_U2 1792  // uint2 fragments per (n,i) W slice
#define WPAD 452    // padded kq-plane stride (uint2) for conflict-free LDS.64

// ---------------- scratch ----------------
__device__ float g_att_sum[BB*LL*LL];
__device__ float g_mention[BB*MM*DD];
__device__ float g_tmp1[BB*MM*LL];
__device__ float g_matt[BB*MM*MM];
__device__ float g_eatt[BB*EE*MM];
__device__ float g_emtok[BB*EE*LL];
__device__ float g_entatt[BB*HH*EE*LL];
__device__ float g_hatt[BB*PP*MM];
__device__ float g_tatt[BB*PP*MM];
__device__ uint32_t g_ctxH2[BB*PP*LL/2];
__device__ uint32_t g_ctxL2[BB*PP*LL/2];
__device__ uint32_t g_hH2[BB*PP*DD/2];
__device__ uint32_t g_hL2[BB*PP*DD/2];
__device__ uint32_t g_tH2[BB*PP*DD/2];
__device__ uint32_t g_tL2[BB*PP*DD/2];
__device__ uint32_t g_cinfoH2[BB*PP*DD/2];
__device__ uint32_t g_cinfoL2[BB*PP*DD/2];
__device__ float g_hf[BB*PP*DD];
__device__ float g_tf[BB*PP*DD];
__device__ float g_part[NCH*BB*PP*RR];
__device__ uint32_t g_hWH2[DD*DD/2];
__device__ uint32_t g_hWL2[DD*DD/2];
__device__ uint32_t g_tWH2[DD*DD/2];
__device__ uint32_t g_tWL2[DD*DD/2];
__device__ uint32_t g_hcWH2[DD*DD/2];
__device__ uint32_t g_hcWL2[DD*DD/2];
__device__ uint32_t g_tcWH2[DD*DD/2];
__device__ uint32_t g_tcWL2[DD*DD/2];
__device__ uint32_t g_ctxtH2[BB*DD*LL/2];
__device__ uint32_t g_ctxtL2[BB*DD*LL/2];
__device__ uint2 g_Wt[NBK*64*WT_U2];   // fp16 W fragments, kq-major per (n,i)

// ---------------- bf16 helpers ----------------
static __device__ __forceinline__ uint32_t pk2(float e0, float e1) {
    uint32_t r;
    asm("cvt.rn.bf16x2.f32 %0, %1, %2;" : "=r"(r) : "f"(e1), "f"(e0));
    return r;
}
static __device__ __forceinline__ void splitbf(float e0, float e1,
                                               uint32_t& H, uint32_t& L) {
    H = pk2(e0, e1);
    float h0 = __uint_as_float(H << 16);
    float h1 = __uint_as_float(H & 0xffff0000u);
    L = pk2(e0 - h0, e1 - h1);
}
static __device__ __forceinline__ void mma_bf(float* c, const uint32_t* a,
                                              uint32_t b0, uint32_t b1) {
    asm volatile(
        "mma.sync.aligned.m16n8k16.row.col.f32.bf16.bf16.f32 "
        "{%0,%1,%2,%3}, {%4,%5,%6,%7}, {%8,%9}, {%0,%1,%2,%3};"
        : "+f"(c[0]), "+f"(c[1]), "+f"(c[2]), "+f"(c[3])
        : "r"(a[0]), "r"(a[1]), "r"(a[2]), "r"(a[3]), "r"(b0), "r"(b1));
}

// ---------------- fp16 helpers (classifier) ----------------
static __device__ __forceinline__ uint32_t pkh2(float e0, float e1) {
    __half2 h = __floats2half2_rn(e0, e1);
    return *(uint32_t*)&h;
}
static __device__ __forceinline__ void splitfp16(float e0, float e1,
                                                 uint32_t& H, uint32_t& L) {
    __half2 h = __floats2half2_rn(e0, e1);
    float2 hf = __half22float2(h);
    __half2 l = __floats2half2_rn(e0 - hf.x, e1 - hf.y);
    H = *(uint32_t*)&h;
    L = *(uint32_t*)&l;
}
static __device__ __forceinline__ void mma_fp16(float* c, const uint32_t* a,
                                                uint32_t b0, uint32_t b1) {
    asm volatile(
        "mma.sync.aligned.m16n8k16.row.col.f32.f16.f16.f32 "
        "{%0,%1,%2,%3}, {%4,%5,%6,%7}, {%8,%9}, {%0,%1,%2,%3};"
        : "+f"(c[0]), "+f"(c[1]), "+f"(c[2]), "+f"(c[3])
        : "r"(a[0]), "r"(a[1]), "r"(a[2]), "r"(a[3]), "r"(b0), "r"(b1));
}

// ---------------- preprocessing ----------------
__global__ void splitall_k(const float* __restrict__ w0, const float* __restrict__ w1,
                           const float* __restrict__ w2, const float* __restrict__ w3,
                           uint32_t* __restrict__ h0, uint32_t* __restrict__ l0,
                           uint32_t* __restrict__ h1, uint32_t* __restrict__ l1,
                           uint32_t* __restrict__ h2, uint32_t* __restrict__ l2,
                           uint32_t* __restrict__ h3, uint32_t* __restrict__ l3)
{
    const int WP = DD*DD/2;
    int i = blockIdx.x * 256 + threadIdx.x;
    if (i >= 4*WP) return;
    int w = i / WP, j = i % WP;
    const float* src = (w == 0) ? w0 : (w == 1) ? w1 : (w == 2) ? w2 : w3;
    uint32_t* H = (w == 0) ? h0 : (w == 1) ? h1 : (w == 2) ? h2 : h3;
    uint32_t* L = (w == 0) ? l0 : (w == 1) ? l1 : (w == 2) ? l2 : l3;
    float2 v = ((const float2*)src)[j];
    uint32_t h, l; splitbf(v.x, v.y, h, l);
    H[j] = h; L[j] = l;
}

__global__ void ctxt_k(const float* __restrict__ ctxt,
                       uint32_t* __restrict__ H, uint32_t* __restrict__ L)
{
    int idx = blockIdx.x * 256 + threadIdx.x;
    if (idx >= BB*DD*(LL/2)) return;
    int lp = idx & 255;
    int bd = idx >> 8;
    int d = bd % DD, b = bd / DD;
    float e0 = ctxt[((size_t)b*LL + 2*lp)     * DD + d];
    float e1 = ctxt[((size_t)b*LL + 2*lp + 1) * DD + d];
    uint32_t h, l; splitbf(e0, e1, h, l);
    H[idx] = h; L[idx] = l;
}

// clasW -> fp16 fragments, kq-major: Wt[(n*64+i)*1792 + kq*448 + s*112 + r]
__global__ void wtransform_k(const float* __restrict__ W, uint2* __restrict__ Wt)
{
    int idx = blockIdx.x * 256 + threadIdx.x;
    if (idx >= NBK*64*WT_U2) return;
    int fi = idx % WT_U2;
    int ni = idx / WT_U2;
    int i = ni & 63, n = ni >> 6;
    int r  = fi % 112;
    int s  = (fi / 112) & 3;
    int kq = fi / 448;
    int j0 = s*16 + 2*kq;
    float w00 = 0.f, w01 = 0.f, w10 = 0.f, w11 = 0.f;
    if (r < RR) {
        const float* base = W + (size_t)r*KCLAS + (size_t)n*4096 + i*64;
        w00 = base[j0];     w01 = base[j0 + 1];
        w10 = base[j0 + 8]; w11 = base[j0 + 9];
    }
    uint2 o;
    o.x = pkh2(w00, w01);
    o.y = pkh2(w10, w11);
    Wt[idx] = o;
}

// ---------------- small kernels ----------------
__global__ void att_sum_k(const float* __restrict__ att, float* __restrict__ out)
{
    int idx = blockIdx.x * 256 + threadIdx.x;      // over BB*LL*LL/4
    if (idx >= BB*LL*LL/4) return;
    int b  = idx >> 16;
    int lm = idx & (LL*LL/4 - 1);
    const float4* p = (const float4*)(att + (size_t)b*HH*LL*LL) + lm;
    float4 s = make_float4(0.f, 0.f, 0.f, 0.f);
#pragma unroll
    for (int h = 0; h < HH; ++h) {
        float4 v = p[(size_t)h*(LL*LL/4)];
        s.x += v.x; s.y += v.y; s.z += v.z; s.w += v.w;
    }
    ((float4*)out)[idx] = s;
}

__global__ void rownorm_k(float* __restrict__ x)
{
    int row = blockIdx.x;
    float* p = x + (size_t)row * LL;
    int t = threadIdx.x;
    float v0 = p[t], v1 = p[t + 256];
    __shared__ float sm[256];
    sm[t] = v0 + v1; __syncthreads();
    for (int o = 128; o > 0; o >>= 1) { if (t < o) sm[t] += sm[t + o]; __syncthreads(); }
    float inv = 1.f / (sm[0] + 1e-30f);
    p[t] = v0 * inv; p[t + 256] = v1 * inv;
}

__global__ void pair_att_k(const int* __restrict__ hts,
                           const float* __restrict__ emap,
                           const float* __restrict__ eatt,
                           float* __restrict__ hattO, float* __restrict__ tattO)
{
    int bp = blockIdx.x;
    int b  = bp >> 9;
    int hi = hts[(size_t)bp*2], ti = hts[(size_t)bp*2 + 1];
    float mask = (hi + ti != 0) ? 1.f : 0.f;
    int t = threadIdx.x;
    float ha = 0.f, ta = 0.f;
    if (t < MM) {
        float hm = emap[((size_t)b*EE + hi)*MM + t] * mask;
        float tm = emap[((size_t)b*EE + ti)*MM + t] * mask;
        ha = eatt[((size_t)b*EE + hi)*MM + t] * tm;
        ta = eatt[((size_t)b*EE + ti)*MM + t] * hm;
    }
    __shared__ float smh[64], smt[64];
    smh[t] = ha; smt[t] = ta; __syncthreads();
    for (int o = 32; o > 0; o >>= 1) {
        if (t < o) { smh[t] += smh[t + o]; smt[t] += smt[t + o]; }
        __syncthreads();
    }
    float invh = 1.f / (smh[0] + 1e-30f);
    float invt = 1.f / (smt[0] + 1e-30f);
    if (t < MM) {
        hattO[(size_t)bp*MM + t] = ha * invh;
        tattO[(size_t)bp*MM + t] = ta * invt;
    }
}

__global__ void ctx_k(const int* __restrict__ hts,
                      const float* __restrict__ entatt,
                      uint32_t* __restrict__ ctxH2, uint32_t* __restrict__ ctxL2)
{
    int bp = blockIdx.x; int b = bp >> 9;
    int hi = hts[(size_t)bp*2], ti = hts[(size_t)bp*2 + 1];
    float mask = (hi + ti != 0) ? 1.f : 0.f;
    int t = threadIdx.x;
    const float* base = entatt + (size_t)b*HH*EE*LL;
    float v0 = 0.f, v1 = 0.f;
#pragma unroll
    for (int h = 0; h < HH; ++h) {
        const float2* ph = (const float2*)(base + ((size_t)h*EE + hi)*LL);
        const float2* pt = (const float2*)(base + ((size_t)h*EE + ti)*LL);
        float2 x = ph[t], y = pt[t];
        v0 += x.x * y.x;
        v1 += x.y * y.y;
    }
    __shared__ float sm[256];
    sm[t] = v0 + v1; __syncthreads();
    for (int o = 128; o > 0; o >>= 1) { if (t < o) sm[t] += sm[t + o]; __syncthreads(); }
    float inv = mask / (sm[0] + 1e-30f);
    uint32_t H, L; splitbf(v0 * inv, v1 * inv, H, L);
    ctxH2[(size_t)bp*(LL/2) + t] = H;
    ctxL2[(size_t)bp*(LL/2) + t] = L;
}

__global__ void matt_k(const float* __restrict__ tmp1, const float* __restrict__ mmap,
                       float* __restrict__ matt)
{
    int gw = (blockIdx.x * 256 + threadIdx.x) >> 5;
    if (gw >= BB*MM*MM) return;
    int lane = threadIdx.x & 31;
    int b = gw / (MM*MM);
    int rem = gw % (MM*MM);
    int m = rem / MM, j = rem % MM;
    const float4* a = (const float4*)(tmp1 + ((size_t)b*MM + m)*LL);
    const float4* c = (const float4*)(mmap + ((size_t)b*MM + j)*LL);
    float s = 0.f;
#pragma unroll
    for (int k = lane; k < 128; k += 32) {
        float4 x = a[k], y = c[k];
        s += x.x*y.x + x.y*y.y + x.z*y.z + x.w*y.w;
    }
#pragma unroll
    for (int o = 16; o; o >>= 1) s += __shfl_xor_sync(0xffffffffu, s, o);
    if (lane == 0) matt[gw] = s;
}

__global__ void eatt_k(const float* __restrict__ emap, const float* __restrict__ matt,
                       float* __restrict__ eatt)
{
    int b = blockIdx.x;
    int idx = threadIdx.x;
    for (int v = idx; v < EE*MM; v += 256) {
        int e = v / MM, j = v % MM;
        float s = 0.f;
#pragma unroll
        for (int m = 0; m < MM; ++m)
            s += emap[((size_t)b*EE + e)*MM + m] * matt[(size_t)b*MM*MM + m*MM + j];
        eatt[(size_t)b*EE*MM + v] = s;
    }
}

// ---------------- generic FFMA GEMM ----------------
template<bool SPLITPAIR>
__global__ __launch_bounds__(256)
void gemm_k(const float* __restrict__ Ag, const float* __restrict__ Bg,
            float* __restrict__ Cg, uint32_t* __restrict__ CH2, uint32_t* __restrict__ CL2,
            int M, int N, int K,
            long long sA, long long sB, long long sC,
            int dA, int dB, int dC)
{
    const int BM = 64, BN = 64, BK = 16;
    int z = blockIdx.z;
    const float* A  = Ag + (long long)(z / dA) * sA;
    const float* Bp = Bg + (long long)(z / dB) * sB;
    int row0 = blockIdx.y * BM;
    int col0 = blockIdx.x * BN;

    __shared__ float As[BK][BM + 1];
    __shared__ float Bs[BK][BN + 1];

    int tid = threadIdx.x;
    int tx = tid & 15, ty = tid >> 4;
    float acc[4][4] = {};

    for (int k0 = 0; k0 < K; k0 += BK) {
#pragma unroll
        for (int r = 0; r < 4; ++r) {
            int idx = tid + r * 256;
            int m = idx >> 4, k = idx & 15;
            float v = 0.f;
            if (row0 + m < M) v = A[(size_t)(row0 + m) * K + k0 + k];
            As[k][m] = v;
        }
#pragma unroll
        for (int r = 0; r < 4; ++r) {
            int idx = tid + r * 256;
            int k = idx >> 6, n = idx & 63;
            float v = 0.f;
            if (col0 + n < N) v = Bp[(size_t)(k0 + k) * N + col0 + n];
            Bs[k][n] = v;
        }
        __syncthreads();
#pragma unroll
        for (int k = 0; k < BK; ++k) {
            float a[4], bb[4];
#pragma unroll
            for (int i = 0; i < 4; ++i) a[i]  = As[k][ty * 4 + i];
#pragma unroll
            for (int j = 0; j < 4; ++j) bb[j] = Bs[k][tx * 4 + j];
#pragma unroll
            for (int i = 0; i < 4; ++i)
#pragma unroll
                for (int j = 0; j < 4; ++j) acc[i][j] += a[i] * bb[j];
        }
        __syncthreads();
    }

    if (SPLITPAIR) {
        uint32_t* CH = CH2 + (long long)(z / dC) * (sC / 2);
        uint32_t* CL = CL2 + (long long)(z / dC) * (sC / 2);
#pragma unroll
        for (int i = 0; i < 4; ++i) {
            int m = row0 + ty * 4 + i;
            int np = (col0 + tx * 4) >> 1;
            uint32_t H, L;
            splitbf(acc[i][0], acc[i][1], H, L);
            CH[(size_t)m * (N/2) + np]     = H;
            CL[(size_t)m * (N/2) + np]     = L;
            splitbf(acc[i][2], acc[i][3], H, L);
            CH[(size_t)m * (N/2) + np + 1] = H;
            CL[(size_t)m * (N/2) + np + 1] = L;
        }
    } else {
        float* C = Cg + (long long)(z / dC) * sC;
#pragma unroll
        for (int i = 0; i < 4; ++i) {
            int m = row0 + ty * 4 + i;
            if (m >= M) continue;
#pragma unroll
            for (int j = 0; j < 4; ++j) {
                int n = col0 + tx * 4 + j;
                if (n >= N) continue;
                C[(size_t)m * N + n] = acc[i][j];
            }
        }
    }
}

// step 9 merged: z = b + BB*sel
__global__ __launch_bounds__(256)
void ht9_k(const float* __restrict__ tatt, const float* __restrict__ hatt,
           const float* __restrict__ mention,
           uint32_t* __restrict__ hH2, uint32_t* __restrict__ hL2,
           uint32_t* __restrict__ tH2, uint32_t* __restrict__ tL2)
{
    const int BM = 64, BN = 64, BK = 16;
    int zz = blockIdx.z;
    int b = zz & (BB - 1), sel = zz >> 2;
    const float* A  = (sel ? hatt : tatt) + (size_t)b * PP * MM;
    const float* Bp = mention + (size_t)b * MM * DD;
    uint32_t* CH = (sel ? tH2 : hH2) + (size_t)b * PP * (DD/2);
    uint32_t* CL = (sel ? tL2 : hL2) + (size_t)b * PP * (DD/2);
    int row0 = blockIdx.y * BM;
    int col0 = blockIdx.x * BN;

    __shared__ float As[BK][BM + 1];
    __shared__ float Bs[BK][BN + 1];

    int tid = threadIdx.x;
    int tx = tid & 15, ty = tid >> 4;
    float acc[4][4] = {};

    for (int k0 = 0; k0 < MM; k0 += BK) {
#pragma unroll
        for (int r = 0; r < 4; ++r) {
            int idx = tid + r * 256;
            int m = idx >> 4, k = idx & 15;
            As[k][m] = A[(size_t)(row0 + m) * MM + k0 + k];
        }
#pragma unroll
        for (int r = 0; r < 4; ++r) {
            int idx = tid + r * 256;
            int k = idx >> 6, n = idx & 63;
            Bs[k][n] = Bp[(size_t)(k0 + k) * DD + col0 + n];
        }
        __syncthreads();
#pragma unroll
        for (int k = 0; k < BK; ++k) {
            float a[4], bb[4];
#pragma unroll
            for (int i = 0; i < 4; ++i) a[i]  = As[k][ty * 4 + i];
#pragma unroll
            for (int j = 0; j < 4; ++j) bb[j] = Bs[k][tx * 4 + j];
#pragma unroll
            for (int i = 0; i < 4; ++i)
#pragma unroll
                for (int j = 0; j < 4; ++j) acc[i][j] += a[i] * bb[j];
        }
        __syncthreads();
    }

#pragma unroll
    for (int i = 0; i < 4; ++i) {
        int m = row0 + ty * 4 + i;
        int np = (col0 + tx * 4) >> 1;
        uint32_t H, L;
        splitbf(acc[i][0], acc[i][1], H, L);
        CH[(size_t)m * (DD/2) + np]     = H;
        CL[(size_t)m * (DD/2) + np]     = L;
        splitbf(acc[i][2], acc[i][3], H, L);
        CH[(size_t)m * (DD/2) + np + 1] = H;
        CL[(size_t)m * (DD/2) + np + 1] = L;
    }
}

// ---------------- bf16 (3x) NT GEMM core (HMMA) ----------------
#define BF_SMEM ((128*20 + 64*20) * 2 * 4)
template<bool FUSE2, bool EPI, bool PAIROUT>
static __device__ __forceinline__
void bf_gemm_body(const uint32_t* __restrict__ A1H, const uint32_t* __restrict__ A1L,
                  const uint32_t* __restrict__ B1H, const uint32_t* __restrict__ B1L,
                  const uint32_t* __restrict__ A2H, const uint32_t* __restrict__ A2L,
                  const uint32_t* __restrict__ B2H, const uint32_t* __restrict__ B2L,
                  const float* __restrict__ bias1, const float* __restrict__ bias2,
                  float* __restrict__ Cf, uint32_t* __restrict__ CH2, uint32_t* __restrict__ CL2,
                  int N, int KP, int row0, int col0)
{
    extern __shared__ uint32_t usm[];
    uint32_t* AsH = usm;
    uint32_t* AsL = AsH + 128*20;
    uint32_t* BsH = AsL + 128*20;
    uint32_t* BsL = BsH + 64*20;

    int tid = threadIdx.x, lane = tid & 31, wid = tid >> 5;
    int m_off = (wid & 3) * 32, n_off = (wid >> 2) * 32;
    int g = lane >> 2, kq = lane & 3;

    float acc[2][4][4];
#pragma unroll
    for (int a = 0; a < 2; ++a)
#pragma unroll
        for (int b = 0; b < 4; ++b)
#pragma unroll
            for (int c = 0; c < 4; ++c) acc[a][b][c] = 0.f;

    const int NPASS = FUSE2 ? 2 : 1;
    for (int pass = 0; pass < NPASS; ++pass) {
        const uint32_t* AH = pass ? A2H : A1H;
        const uint32_t* AL = pass ? A2L : A1L;
        const uint32_t* BH = pass ? B2H : B1H;
        const uint32_t* BL = pass ? B2L : B1L;
        for (int kp0 = 0; kp0 < KP; kp0 += 16) {
            __syncthreads();
#pragma unroll
            for (int r2 = 0; r2 < 2; ++r2) {
                int slot = tid + r2 * 256;
                int m = slot >> 2, q = slot & 3;
                *(uint4*)(AsH + m*20 + q*4) =
                    *(const uint4*)(AH + (size_t)(row0 + m)*KP + kp0 + q*4);
                *(uint4*)(AsL + m*20 + q*4) =
                    *(const uint4*)(AL + (size_t)(row0 + m)*KP + kp0 + q*4);
            }
            {
                int n = tid >> 2, q = tid & 3;
                *(uint4*)(BsH + n*20 + q*4) =
                    *(const uint4*)(BH + (size_t)(col0 + n)*KP + kp0 + q*4);
                *(uint4*)(BsL + n*20 + q*4) =
                    *(const uint4*)(BL + (size_t)(col0 + n)*KP + kp0 + q*4);
            }
            __syncthreads();
#pragma unroll
            for (int st = 0; st < 2; ++st) {
                int pb = st*8 + kq;
                uint32_t aH[2][4], aL[2][4];
#pragma unroll
                for (int mt = 0; mt < 2; ++mt) {
                    int mr = m_off + mt*16 + g;
                    aH[mt][0] = AsH[mr*20 + pb];       aL[mt][0] = AsL[mr*20 + pb];
                    aH[mt][1] = AsH[(mr+8)*20 + pb];   aL[mt][1] = AsL[(mr+8)*20 + pb];
                    aH[mt][2] = AsH[mr*20 + pb + 4];   aL[mt][2] = AsL[mr*20 + pb + 4];
                    aH[mt][3] = AsH[(mr+8)*20 + pb+4]; aL[mt][3] = AsL[(mr+8)*20 + pb+4];
                }
#pragma unroll
                for (int nt = 0; nt < 4; ++nt) {
                    int nr = n_off + nt*8 + g;
                    uint32_t bH0 = BsH[nr*20 + pb], bH1 = BsH[nr*20 + pb + 4];
                    uint32_t bL0 = BsL[nr*20 + pb], bL1 = BsL[nr*20 + pb + 4];
#pragma unroll
                    for (int mt = 0; mt < 2; ++mt) {
                        mma_bf(acc[mt][nt], aH[mt], bH0, bH1);
                        mma_bf(acc[mt][nt], aH[mt], bL0, bL1);
                        mma_bf(acc[mt][nt], aL[mt], bH0, bH1);
                    }
                }
            }
        }
    }

#pragma unroll
    for (int mt = 0; mt < 2; ++mt) {
#pragma unroll
        for (int nt = 0; nt < 4; ++nt) {
            int mr = row0 + m_off + mt*16 + g;
            int nc = col0 + n_off + nt*8 + 2*kq;
            float b0 = 0.f, b1 = 0.f;
            if (EPI) {
                b0 = bias1[nc]   + (FUSE2 ? bias2[nc]   : 0.f);
                b1 = bias1[nc+1] + (FUSE2 ? bias2[nc+1] : 0.f);
            }
            float v0 = acc[mt][nt][0] + b0;
            float v1 = acc[mt][nt][1] + b1;
            float v2 = acc[mt][nt][2] + b0;
            float v3 = acc[mt][nt][3] + b1;
            if (EPI) { v0 = tanhf(v0); v1 = tanhf(v1); v2 = tanhf(v2); v3 = tanhf(v3); }
            if (PAIROUT) {
                int np = nc >> 1;
                uint32_t H, L;
                splitbf(v0, v1, H, L);
                CH2[(size_t)mr*(N/2) + np] = H; CL2[(size_t)mr*(N/2) + np] = L;
                splitbf(v2, v3, H, L);
                CH2[(size_t)(mr+8)*(N/2) + np] = H; CL2[(size_t)(mr+8)*(N/2) + np] = L;
            } else {
                Cf[(size_t)mr * N + nc]       = v0;
                Cf[(size_t)mr * N + nc + 1]   = v1;
                Cf[(size_t)(mr+8) * N + nc]   = v2;
                Cf[(size_t)(mr+8) * N + nc+1] = v3;
            }
        }
    }
}

__global__ __launch_bounds__(256)
void bf10_k(const uint32_t* __restrict__ AH, const uint32_t* __restrict__ AL,
            const uint32_t* __restrict__ BH, const uint32_t* __restrict__ BL,
            uint32_t* __restrict__ CH2, uint32_t* __restrict__ CL2)
{
    int z = blockIdx.z;
    const int KP = LL/2;
    bf_gemm_body<false,false,true>(
        AH + (size_t)z*PP*KP, AL + (size_t)z*PP*KP,
        BH + (size_t)z*DD*KP, BL + (size_t)z*DD*KP,
        nullptr, nullptr, nullptr, nullptr, nullptr, nullptr,
        nullptr,
        CH2 + (size_t)z*PP*(DD/2), CL2 + (size_t)z*PP*(DD/2),
        DD, KP, blockIdx.y * 128, blockIdx.x * 64);
}

__global__ __launch_bounds__(256)
void bf1112_k(const uint32_t* __restrict__ hH2, const uint32_t* __restrict__ hL2,
              const uint32_t* __restrict__ tH2, const uint32_t* __restrict__ tL2,
              const uint32_t* __restrict__ hWH2, const uint32_t* __restrict__ hWL2,
              const uint32_t* __restrict__ tWH2, const uint32_t* __restrict__ tWL2,
              const uint32_t* __restrict__ cH2, const uint32_t* __restrict__ cL2,
              const uint32_t* __restrict__ hcWH2, const uint32_t* __restrict__ hcWL2,
              const uint32_t* __restrict__ tcWH2, const uint32_t* __restrict__ tcWL2,
              const float* __restrict__ hb, const float* __restrict__ tb,
              const float* __restrict__ hcb, const float* __restrict__ tcb,
              float* __restrict__ hf, float* __restrict__ tf)
{
    int z = blockIdx.z;
    bf_gemm_body<true,true,false>(
        z ? tH2 : hH2,  z ? tL2 : hL2,
        z ? tWH2 : hWH2, z ? tWL2 : hWL2,
        cH2, cL2,
        z ? tcWH2 : hcWH2, z ? tcWL2 : hcWL2,
        z ? tb : hb, z ? tcb : hcb,
        z ? tf : hf, nullptr, nullptr,
        DD, DD/2, blockIdx.y * 128, blockIdx.x * 64);
}

// ------- classifier: fp16 2-term, coop double-buffered smem W staging -------
#define CLAS_SMEM (128*17*4 + 2*128*33*4 + 2*4*WPAD*8)
__global__ __launch_bounds__(256, 1)
void clasmma_k(const float* __restrict__ Hf, const float* __restrict__ Tf,
               const uint2* __restrict__ Wt, float* __restrict__ part)
{
    extern __shared__ char smraw[];
    float*    hs  = (float*)smraw;               // [128][17]
    uint32_t* tsH = (uint32_t*)(hs + 128*17);    // [128][33] fp16 pair-packed
    uint32_t* tsL = tsH + 128*33;
    uint2*    ws  = (uint2*)(tsL + 128*33);      // [2][4*WPAD]

    const int n = blockIdx.y, z = blockIdx.z;    // z in 0..3, 16 i each
    const int p0 = blockIdx.x * 128;
    int tid = threadIdx.x, lane = tid & 31, wid = tid >> 5;
    int pbase = (wid & 3) * 32, nbase = (wid >> 2) * 56;
    int g = lane >> 2, kq = lane & 3;

    for (int v = tid; v < 128*32; v += 256) {
        int p = v >> 5, q = v & 31;
        if (q < 16)
            hs[p*17 + q] = Hf[(size_t)(p0 + p)*DD + n*64 + z*16 + q];
        float t0 = Tf[(size_t)(p0 + p)*DD + n*64 + 2*q];
        float t1 = Tf[(size_t)(p0 + p)*DD + n*64 + 2*q + 1];
        uint32_t H, L; splitfp16(t0, t1, H, L);
        tsH[p*33 + q] = H; tsL[p*33 + q] = L;
    }
    // stage W(ii=0) cooperatively
    {
        const uint2* Wg = Wt + (size_t)(n*64 + z*16) * WT_U2;
#pragma unroll
        for (int w = 0; w < 7; ++w) {
            int v = tid + w*256;
            int kq2 = v / 448, rem = v - kq2*448;
            ws[kq2*WPAD + rem] = Wg[v];
        }
    }
    __syncthreads();

    uint32_t tAH[2][4][4], tAL[2][4][4];
#pragma unroll
    for (int mt = 0; mt < 2; ++mt) {
        int pr = pbase + mt*16 + g;
#pragma unroll
        for (int s = 0; s < 4; ++s) {
            int pp = s*8 + kq;
            tAH[mt][s][0] = tsH[pr*33 + pp];       tAL[mt][s][0] = tsL[pr*33 + pp];
            tAH[mt][s][1] = tsH[(pr+8)*33 + pp];   tAL[mt][s][1] = tsL[(pr+8)*33 + pp];
            tAH[mt][s][2] = tsH[pr*33 + pp + 4];   tAL[mt][s][2] = tsL[pr*33 + pp + 4];
            tAH[mt][s][3] = tsH[(pr+8)*33 + pp+4]; tAL[mt][s][3] = tsL[(pr+8)*33 + pp+4];
        }
    }

    float acc[2][7][4];
#pragma unroll
    for (int a = 0; a < 2; ++a)
#pragma unroll
        for (int b = 0; b < 7; ++b)
#pragma unroll
            for (int c = 0; c < 4; ++c) acc[a][b][c] = 0.f;

    for (int ii = 0; ii < 16; ++ii) {
        uint2* wbuf  = ws + (ii & 1) * (4*WPAD);
        uint2* wnext = ws + ((ii + 1) & 1) * (4*WPAD);

        // prefetch next i's W into registers (latency hidden under compute)
        uint2 pf[7];
        if (ii < 15) {
            const uint2* Wg = Wt + (size_t)(n*64 + z*16 + ii + 1) * WT_U2;
#pragma unroll
            for (int w = 0; w < 7; ++w) pf[w] = Wg[tid + w*256];
        }

        float hv0[2], hv1[2];
#pragma unroll
        for (int mt = 0; mt < 2; ++mt) {
            int pr = pbase + mt*16 + g;
            hv0[mt] = hs[pr*17 + ii];
            hv1[mt] = hs[(pr+8)*17 + ii];
        }

        float tmp[2][7][4];
#pragma unroll
        for (int a = 0; a < 2; ++a)
#pragma unroll
            for (int b = 0; b < 7; ++b)
#pragma unroll
                for (int c = 0; c < 4; ++c) tmp[a][b][c] = 0.f;

#pragma unroll
        for (int s = 0; s < 4; ++s) {
#pragma unroll
            for (int nt = 0; nt < 7; ++nt) {
                int r = nbase + nt*8 + g;
                uint2 w2 = wbuf[kq*WPAD + s*112 + r];
#pragma unroll
                for (int mt = 0; mt < 2; ++mt) {
                    mma_fp16(tmp[mt][nt], tAH[mt][s], w2.x, w2.y);
                    mma_fp16(tmp[mt][nt], tAL[mt][s], w2.x, w2.y);
                }
            }
        }
#pragma unroll
        for (int mt = 0; mt < 2; ++mt)
#pragma unroll
            for (int nt = 0; nt < 7; ++nt) {
                acc[mt][nt][0] += hv0[mt] * tmp[mt][nt][0];
                acc[mt][nt][1] += hv0[mt] * tmp[mt][nt][1];
                acc[mt][nt][2] += hv1[mt] * tmp[mt][nt][2];
                acc[mt][nt][3] += hv1[mt] * tmp[mt][nt][3];
            }

        if (ii < 15) {
#pragma unroll
            for (int w = 0; w < 7; ++w) {
                int v = tid + w*256;
                int kq2 = v / 448, rem = v - kq2*448;
                wnext[kq2*WPAD + rem] = pf[w];
            }
        }
        __syncthreads();
    }

    int chunk = n*4 + z;
    float* po = part + (size_t)chunk * (BB*PP*RR);
#pragma unroll
    for (int mt = 0; mt < 2; ++mt) {
#pragma unroll
        for (int nt = 0; nt < 7; ++nt) {
            int p = p0 + pbase + mt*16 + g;
            int r = nbase + nt*8 + 2*kq;
            if (r < RR)   po[(size_t)p*RR + r]       = acc[mt][nt][0];
            if (r+1 < RR) po[(size_t)p*RR + r + 1]   = acc[mt][nt][1];
            if (r < RR)   po[(size_t)(p+8)*RR + r]   = acc[mt][nt][2];
            if (r+1 < RR) po[(size_t)(p+8)*RR + r+1] = acc[mt][nt][3];
        }
    }
}

__global__ void clas_red_k(const float* __restrict__ part,
                           const float* __restrict__ clasb,
                           float* __restrict__ out)
{
    int idx = blockIdx.x * 256 + threadIdx.x;
    if (idx >= BB * PP * RR) return;
    int r = idx % RR;
    float s = clasb[r];
#pragma unroll
    for (int c = 0; c < NCH; ++c) s += part[(size_t)c * (BB * PP * RR) + idx];
    out[idx] = s;
}

// ---------------- host ----------------
extern "C" void kernel_launch(void* const* d_in, const int* in_sizes, int n_in,
                              void* d_out, int out_size)
{
    const float* context   = (const float*)d_in[0];
    const float* attention = (const float*)d_in[1];
    const float* mmap      = (const float*)d_in[2];
    const float* emap      = (const float*)d_in[3];
    const int*   hts       = (const int*)d_in[4];
    const float* hW   = (const float*)d_in[5];
    const float* hb   = (const float*)d_in[6];
    const float* tW   = (const float*)d_in[7];
    const float* tb   = (const float*)d_in[8];
    const float* hcW  = (const float*)d_in[9];
    const float* hcb  = (const float*)d_in[10];
    const float* tcW  = (const float*)d_in[11];
    const float* tcb  = (const float*)d_in[12];
    const float* clasW = (const float*)d_in[13];
    const float* clasb = (const float*)d_in[14];
    float* out = (float*)d_out;

#define GETF(p, s) float* p; cudaGetSymbolAddress((void**)&p, s)
#define GETU(p, s) uint32_t* p; cudaGetSymbolAddress((void**)&p, s)
    GETF(att_sum, g_att_sum); GETF(mention, g_mention); GETF(tmp1, g_tmp1);
    GETF(matt, g_matt); GETF(eatt, g_eatt); GETF(emtok, g_emtok);
    GETF(entatt, g_entatt); GETF(hatt, g_hatt); GETF(tatt, g_tatt);
    GETU(ctxH2, g_ctxH2); GETU(ctxL2, g_ctxL2);
    GETU(hH2, g_hH2); GETU(hL2, g_hL2); GETU(tH2, g_tH2); GETU(tL2, g_tL2);
    GETU(cinfoH2, g_cinfoH2); GETU(cinfoL2, g_cinfoL2);
    GETF(hf, g_hf); GETF(tf, g_tf); GETF(part, g_part);
    GETU(hWH2, g_hWH2); GETU(hWL2, g_hWL2); GETU(tWH2, g_tWH2); GETU(tWL2, g_tWL2);
    GETU(hcWH2, g_hcWH2); GETU(hcWL2, g_hcWL2); GETU(tcWH2, g_tcWH2); GETU(tcWL2, g_tcWL2);
    GETU(ctxtH2, g_ctxtH2); GETU(ctxtL2, g_ctxtL2);
    uint2* Wt; cudaGetSymbolAddress((void**)&Wt, g_Wt);
#undef GETF
#undef GETU

    cudaFuncSetAttribute(clasmma_k, cudaFuncAttributeMaxDynamicSharedMemorySize, CLAS_SMEM);

    // 0) static operand preprocessing
    const int WP = DD*DD/2;
    splitall_k<<<(4*WP+255)/256, 256>>>(hW, tW, hcW, tcW,
        hWH2, hWL2, tWH2, tWL2, hcWH2, hcWL2, tcWH2, tcWL2);
    ctxt_k<<<(BB*DD*(LL/2)+255)/256, 256>>>(context, ctxtH2, ctxtL2);
    wtransform_k<<<(NBK*64*WT_U2+255)/256, 256>>>(clasW, Wt);

    // 1) att_sum (float4)
    att_sum_k<<<(BB*LL*LL/4 + 255)/256, 256>>>(attention, att_sum);

    // 2) mention = mention_map @ context
    gemm_k<false><<<dim3(12,1,BB),256>>>(
        mmap, context, mention, nullptr, nullptr, MM, DD, LL,
        (long long)MM*LL, (long long)LL*DD, (long long)MM*DD, 1,1,1);

    // 3) tmp1 = mention_map @ att_sum
    gemm_k<false><<<dim3(8,1,BB),256>>>(
        mmap, att_sum, tmp1, nullptr, nullptr, MM, LL, LL,
        (long long)MM*LL, (long long)LL*LL, (long long)MM*LL, 1,1,1);

    // 4) mention_att
    matt_k<<<(BB*MM*MM*32 + 255)/256, 256>>>(tmp1, mmap, matt);

    // 5) entity_att
    eatt_k<<<BB, 256>>>(emap, matt, eatt);

    // 6) em_tok + normalize
    gemm_k<false><<<dim3(8,1,BB),256>>>(
        emap, mmap, emtok, nullptr, nullptr, EE, LL, MM,
        (long long)EE*MM, (long long)MM*LL, (long long)EE*LL, 1,1,1);
    rownorm_k<<<BB*EE, 256>>>(emtok);

    // 7) ent_att
    gemm_k<false><<<dim3(8,1,BB*HH),256>>>(
        emtok, attention, entatt, nullptr, nullptr, EE, LL, LL,
        (long long)EE*LL, (long long)LL*LL, (long long)EE*LL, HH,1,1);

    // 8) per-pair vectors
    pair_att_k<<<BB*PP, 64>>>(hts, emap, eatt, hatt, tatt);
    ctx_k<<<BB*PP, 256>>>(hts, entatt, ctxH2, ctxL2);

    // 9) h, t merged (FFMA, pair-split epilogue)
    ht9_k<<<dim3(12,8,2*BB),256>>>(tatt, hatt, mention, hH2, hL2, tH2, tL2);

    // 10) context_info (bf16x3 NT, pair-split out)
    bf10_k<<<dim3(12,4,BB),256,BF_SMEM>>>(ctxH2, ctxL2, ctxtH2, ctxtL2,
                                          cinfoH2, cinfoL2);

    // 11+12) fused: hf/tf = tanh(x@W^T + cinfo@cW^T + biases), z picks h/t
    bf1112_k<<<dim3(12,16,2),256,BF_SMEM>>>(
        hH2, hL2, tH2, tL2, hWH2, hWL2, tWH2, tWL2,
        cinfoH2, cinfoL2, hcWH2, hcWL2, tcWH2, tcWL2,
        hb, tb, hcb, tcb, hf, tf);

    // 13) classifier (fp16 2-term, smem-staged W)
    clasmma_k<<<dim3(BB*PP/128, NBK, 4), 256, CLAS_SMEM>>>(hf, tf, Wt, part);
    clas_red_k<<<(BB*PP*RR + 255)/256, 256>>>(part, clasb, out);
}

// round 12
// speedup vs baseline: 2.3059x; 1.2058x over previous
#include <cuda_runtime.h>
#include <cuda_bf16.h>
#include <cuda_fp16.h>
#include <cstdint>
#include <math.h>

#define BB 4
#define LL 512
#define DD 768
#define HH 12
#define MM 48
#define EE 32
#define PP 512
#define RR 97
#define NBK 12
#define NCH 48
#define KCLAS 49152
#define WT_U2 1792
#define WPAD 452
#define WPACK (DD*DD/2)

// ---------------- scratch ----------------
__device__ float g_att_sum[BB*LL*LL];
__device__ float g_mention[BB*MM*DD];
__device__ float g_tmp1[BB*MM*LL];
__device__ float g_matt[BB*MM*MM];
__device__ float g_eatt[BB*EE*MM];
__device__ float g_emtok[BB*EE*LL];
__device__ float g_entatt[BB*HH*EE*LL];
__device__ float g_hatt[BB*PP*MM];
__device__ float g_tatt[BB*PP*MM];
__device__ uint32_t g_ctxH2[BB*PP*LL/2];
__device__ uint32_t g_ctxL2[BB*PP*LL/2];
__device__ uint32_t g_hH2[BB*PP*DD/2];     // fp16 H/L
__device__ uint32_t g_hL2[BB*PP*DD/2];
__device__ uint32_t g_tH2[BB*PP*DD/2];
__device__ uint32_t g_tL2[BB*PP*DD/2];
__device__ uint32_t g_cinfoH2[BB*PP*DD/2]; // fp16 H/L
__device__ uint32_t g_cinfoL2[BB*PP*DD/2];
__device__ float g_hf[BB*PP*DD];
__device__ float g_tf[BB*PP*DD];
__device__ float g_part[NCH*BB*PP*RR];
__device__ uint32_t g_hWf[WPACK];          // plain fp16 pair-packed weights
__device__ uint32_t g_tWf[WPACK];
__device__ uint32_t g_hcWf[WPACK];
__device__ uint32_t g_tcWf[WPACK];
__device__ uint32_t g_ctxtH2[BB*DD*LL/2];  // bf16 split (for bf10)
__device__ uint32_t g_ctxtL2[BB*DD*LL/2];
__device__ uint2 g_Wt[NBK*64*WT_U2];

// ---------------- bf16 helpers ----------------
static __device__ __forceinline__ uint32_t pk2(float e0, float e1) {
    uint32_t r;
    asm("cvt.rn.bf16x2.f32 %0, %1, %2;" : "=r"(r) : "f"(e1), "f"(e0));
    return r;
}
static __device__ __forceinline__ void splitbf(float e0, float e1,
                                               uint32_t& H, uint32_t& L) {
    H = pk2(e0, e1);
    float h0 = __uint_as_float(H << 16);
    float h1 = __uint_as_float(H & 0xffff0000u);
    L = pk2(e0 - h0, e1 - h1);
}
static __device__ __forceinline__ void mma_bf(float* c, const uint32_t* a,
                                              uint32_t b0, uint32_t b1) {
    asm volatile(
        "mma.sync.aligned.m16n8k16.row.col.f32.bf16.bf16.f32 "
        "{%0,%1,%2,%3}, {%4,%5,%6,%7}, {%8,%9}, {%0,%1,%2,%3};"
        : "+f"(c[0]), "+f"(c[1]), "+f"(c[2]), "+f"(c[3])
        : "r"(a[0]), "r"(a[1]), "r"(a[2]), "r"(a[3]), "r"(b0), "r"(b1));
}

// ---------------- fp16 helpers ----------------
static __device__ __forceinline__ uint32_t pkh2(float e0, float e1) {
    __half2 h = __floats2half2_rn(e0, e1);
    return *(uint32_t*)&h;
}
static __device__ __forceinline__ void splitfp16(float e0, float e1,
                                                 uint32_t& H, uint32_t& L) {
    __half2 h = __floats2half2_rn(e0, e1);
    float2 hf = __half22float2(h);
    __half2 l = __floats2half2_rn(e0 - hf.x, e1 - hf.y);
    H = *(uint32_t*)&h;
    L = *(uint32_t*)&l;
}
static __device__ __forceinline__ void mma_fp16(float* c, const uint32_t* a,
                                                uint32_t b0, uint32_t b1) {
    asm volatile(
        "mma.sync.aligned.m16n8k16.row.col.f32.f16.f16.f32 "
        "{%0,%1,%2,%3}, {%4,%5,%6,%7}, {%8,%9}, {%0,%1,%2,%3};"
        : "+f"(c[0]), "+f"(c[1]), "+f"(c[2]), "+f"(c[3])
        : "r"(a[0]), "r"(a[1]), "r"(a[2]), "r"(a[3]), "r"(b0), "r"(b1));
}

// ---------------- merged preprocessing + att_sum ----------------
// regions: [0,1024) att_sum f4 | [1024,5632) weight fp16 pack |
//          [5632,8704) ctxt bf16 split | [8704,14080) clasW transform
__global__ void prep_k(const float* __restrict__ att, float* __restrict__ att_sum,
                       const float* __restrict__ hW, const float* __restrict__ tW,
                       const float* __restrict__ hcW, const float* __restrict__ tcW,
                       uint32_t* __restrict__ hWf, uint32_t* __restrict__ tWf,
                       uint32_t* __restrict__ hcWf, uint32_t* __restrict__ tcWf,
                       const float* __restrict__ context,
                       uint32_t* __restrict__ ctH, uint32_t* __restrict__ ctL,
                       const float* __restrict__ clasW, uint2* __restrict__ Wt)
{
    int blk = blockIdx.x, tid = threadIdx.x;
    if (blk < 1024) {
        int idx = blk * 256 + tid;
        int b  = idx >> 16;
        int lm = idx & (LL*LL/4 - 1);
        const float4* p = (const float4*)(att + (size_t)b*HH*LL*LL) + lm;
        float4 s = make_float4(0.f, 0.f, 0.f, 0.f);
#pragma unroll
        for (int h = 0; h < HH; ++h) {
            float4 v = p[(size_t)h*(LL*LL/4)];
            s.x += v.x; s.y += v.y; s.z += v.z; s.w += v.w;
        }
        ((float4*)att_sum)[idx] = s;
    } else if (blk < 5632) {
        int idx = (blk - 1024) * 256 + tid;
        int w = idx / WPACK, j = idx % WPACK;
        const float* src = (w == 0) ? hW : (w == 1) ? tW : (w == 2) ? hcW : tcW;
        uint32_t* dst = (w == 0) ? hWf : (w == 1) ? tWf : (w == 2) ? hcWf : tcWf;
        float2 v = ((const float2*)src)[j];
        dst[j] = pkh2(v.x, v.y);
    } else if (blk < 8704) {
        int idx = (blk - 5632) * 256 + tid;
        int lp = idx & 255;
        int bd = idx >> 8;
        int d = bd % DD, b = bd / DD;
        float e0 = context[((size_t)b*LL + 2*lp)     * DD + d];
        float e1 = context[((size_t)b*LL + 2*lp + 1) * DD + d];
        uint32_t h, l; splitbf(e0, e1, h, l);
        ctH[idx] = h; ctL[idx] = l;
    } else {
        int idx = (blk - 8704) * 256 + tid;
        int fi = idx % WT_U2;
        int ni = idx / WT_U2;
        int i = ni & 63, n = ni >> 6;
        int r  = fi % 112;
        int s  = (fi / 112) & 3;
        int kq = fi / 448;
        int j0 = s*16 + 2*kq;
        float w00 = 0.f, w01 = 0.f, w10 = 0.f, w11 = 0.f;
        if (r < RR) {
            const float* base = clasW + (size_t)r*KCLAS + (size_t)n*4096 + i*64;
            w00 = base[j0];     w01 = base[j0 + 1];
            w10 = base[j0 + 8]; w11 = base[j0 + 9];
        }
        uint2 o;
        o.x = pkh2(w00, w01);
        o.y = pkh2(w10, w11);
        Wt[idx] = o;
    }
}

// ---------------- small kernels ----------------
__global__ void rownorm_k(float* __restrict__ x)
{
    int row = blockIdx.x;
    float* p = x + (size_t)row * LL;
    int t = threadIdx.x;
    float v0 = p[t], v1 = p[t + 256];
    __shared__ float sm[256];
    sm[t] = v0 + v1; __syncthreads();
    for (int o = 128; o > 0; o >>= 1) { if (t < o) sm[t] += sm[t + o]; __syncthreads(); }
    float inv = 1.f / (sm[0] + 1e-30f);
    p[t] = v0 * inv; p[t + 256] = v1 * inv;
}

__global__ void pair_att_k(const int* __restrict__ hts,
                           const float* __restrict__ emap,
                           const float* __restrict__ eatt,
                           float* __restrict__ hattO, float* __restrict__ tattO)
{
    int bp = blockIdx.x;
    int b  = bp >> 9;
    int hi = hts[(size_t)bp*2], ti = hts[(size_t)bp*2 + 1];
    float mask = (hi + ti != 0) ? 1.f : 0.f;
    int t = threadIdx.x;
    float ha = 0.f, ta = 0.f;
    if (t < MM) {
        float hm = emap[((size_t)b*EE + hi)*MM + t] * mask;
        float tm = emap[((size_t)b*EE + ti)*MM + t] * mask;
        ha = eatt[((size_t)b*EE + hi)*MM + t] * tm;
        ta = eatt[((size_t)b*EE + ti)*MM + t] * hm;
    }
    __shared__ float smh[64], smt[64];
    smh[t] = ha; smt[t] = ta; __syncthreads();
    for (int o = 32; o > 0; o >>= 1) {
        if (t < o) { smh[t] += smh[t + o]; smt[t] += smt[t + o]; }
        __syncthreads();
    }
    float invh = 1.f / (smh[0] + 1e-30f);
    float invt = 1.f / (smt[0] + 1e-30f);
    if (t < MM) {
        hattO[(size_t)bp*MM + t] = ha * invh;
        tattO[(size_t)bp*MM + t] = ta * invt;
    }
}

__global__ void ctx_k(const int* __restrict__ hts,
                      const float* __restrict__ entatt,
                      uint32_t* __restrict__ ctxH2, uint32_t* __restrict__ ctxL2)
{
    int bp = blockIdx.x; int b = bp >> 9;
    int hi = hts[(size_t)bp*2], ti = hts[(size_t)bp*2 + 1];
    float mask = (hi + ti != 0) ? 1.f : 0.f;
    int t = threadIdx.x;
    const float* base = entatt + (size_t)b*HH*EE*LL;
    float v0 = 0.f, v1 = 0.f;
#pragma unroll
    for (int h = 0; h < HH; ++h) {
        const float2* ph = (const float2*)(base + ((size_t)h*EE + hi)*LL);
        const float2* pt = (const float2*)(base + ((size_t)h*EE + ti)*LL);
        float2 x = ph[t], y = pt[t];
        v0 += x.x * y.x;
        v1 += x.y * y.y;
    }
    __shared__ float sm[256];
    sm[t] = v0 + v1; __syncthreads();
    for (int o = 128; o > 0; o >>= 1) { if (t < o) sm[t] += sm[t + o]; __syncthreads(); }
    float inv = mask / (sm[0] + 1e-30f);
    uint32_t H, L; splitbf(v0 * inv, v1 * inv, H, L);
    ctxH2[(size_t)bp*(LL/2) + t] = H;
    ctxL2[(size_t)bp*(LL/2) + t] = L;
}

__global__ void matt_k(const float* __restrict__ tmp1, const float* __restrict__ mmap,
                       float* __restrict__ matt)
{
    int gw = (blockIdx.x * 256 + threadIdx.x) >> 5;
    if (gw >= BB*MM*MM) return;
    int lane = threadIdx.x & 31;
    int b = gw / (MM*MM);
    int rem = gw % (MM*MM);
    int m = rem / MM, j = rem % MM;
    const float4* a = (const float4*)(tmp1 + ((size_t)b*MM + m)*LL);
    const float4* c = (const float4*)(mmap + ((size_t)b*MM + j)*LL);
    float s = 0.f;
#pragma unroll
    for (int k = lane; k < 128; k += 32) {
        float4 x = a[k], y = c[k];
        s += x.x*y.x + x.y*y.y + x.z*y.z + x.w*y.w;
    }
#pragma unroll
    for (int o = 16; o; o >>= 1) s += __shfl_xor_sync(0xffffffffu, s, o);
    if (lane == 0) matt[gw] = s;
}

__global__ void eatt_k(const float* __restrict__ emap, const float* __restrict__ matt,
                       float* __restrict__ eatt)
{
    int b = blockIdx.x;
    int idx = threadIdx.x;
    for (int v = idx; v < EE*MM; v += 256) {
        int e = v / MM, j = v % MM;
        float s = 0.f;
#pragma unroll
        for (int m = 0; m < MM; ++m)
            s += emap[((size_t)b*EE + e)*MM + m] * matt[(size_t)b*MM*MM + m*MM + j];
        eatt[(size_t)b*EE*MM + v] = s;
    }
}

// ---------------- generic FFMA GEMM (em_tok only) ----------------
__global__ __launch_bounds__(256)
void gemm_k(const float* __restrict__ Ag, const float* __restrict__ Bg,
            float* __restrict__ Cg, int M, int N, int K,
            long long sA, long long sB, long long sC)
{
    const int BM = 64, BN = 64, BK = 16;
    int z = blockIdx.z;
    const float* A  = Ag + (long long)z * sA;
    const float* Bp = Bg + (long long)z * sB;
    float* C = Cg + (long long)z * sC;
    int row0 = blockIdx.y * BM;
    int col0 = blockIdx.x * BN;

    __shared__ float As[BK][BM + 1];
    __shared__ float Bs[BK][BN + 1];

    int tid = threadIdx.x;
    int tx = tid & 15, ty = tid >> 4;
    float acc[4][4] = {};

    for (int k0 = 0; k0 < K; k0 += BK) {
#pragma unroll
        for (int r = 0; r < 4; ++r) {
            int idx = tid + r * 256;
            int m = idx >> 4, k = idx & 15;
            float v = 0.f;
            if (row0 + m < M) v = A[(size_t)(row0 + m) * K + k0 + k];
            As[k][m] = v;
        }
#pragma unroll
        for (int r = 0; r < 4; ++r) {
            int idx = tid + r * 256;
            int k = idx >> 6, n = idx & 63;
            float v = 0.f;
            if (col0 + n < N) v = Bp[(size_t)(k0 + k) * N + col0 + n];
            Bs[k][n] = v;
        }
        __syncthreads();
#pragma unroll
        for (int k = 0; k < BK; ++k) {
            float a[4], bb[4];
#pragma unroll
            for (int i = 0; i < 4; ++i) a[i]  = As[k][ty * 4 + i];
#pragma unroll
            for (int j = 0; j < 4; ++j) bb[j] = Bs[k][tx * 4 + j];
#pragma unroll
            for (int i = 0; i < 4; ++i)
#pragma unroll
                for (int j = 0; j < 4; ++j) acc[i][j] += a[i] * bb[j];
        }
        __syncthreads();
    }

#pragma unroll
    for (int i = 0; i < 4; ++i) {
        int m = row0 + ty * 4 + i;
        if (m >= M) continue;
#pragma unroll
        for (int j = 0; j < 4; ++j) {
            int n = col0 + tx * 4 + j;
            if (n >= N) continue;
            C[(size_t)m * N + n] = acc[i][j];
        }
    }
}

// merged steps 2+3: z = b + 4*sel; sel 0: mention(N=768), 1: tmp1(N=512)
__global__ __launch_bounds__(256)
void gemm23_k(const float* __restrict__ mmap, const float* __restrict__ context,
              const float* __restrict__ att_sum,
              float* __restrict__ mention, float* __restrict__ tmp1)
{
    const int BM = 64, BN = 64, BK = 16;
    int zz = blockIdx.z;
    int b = zz & 3, sel = zz >> 2;
    if (sel && blockIdx.x >= 8) return;
    int N = sel ? LL : DD;
    const float* A  = mmap + (size_t)b*MM*LL;
    const float* Bp = sel ? (att_sum + (size_t)b*LL*LL) : (context + (size_t)b*LL*DD);
    float* C = sel ? (tmp1 + (size_t)b*MM*LL) : (mention + (size_t)b*MM*DD);
    int col0 = blockIdx.x * BN;

    __shared__ float As[BK][BM + 1];
    __shared__ float Bs[BK][BN + 1];

    int tid = threadIdx.x;
    int tx = tid & 15, ty = tid >> 4;
    float acc[4][4] = {};

    for (int k0 = 0; k0 < LL; k0 += BK) {
#pragma unroll
        for (int r = 0; r < 4; ++r) {
            int idx = tid + r * 256;
            int m = idx >> 4, k = idx & 15;
            As[k][m] = (m < MM) ? A[(size_t)m * LL + k0 + k] : 0.f;
        }
#pragma unroll
        for (int r = 0; r < 4; ++r) {
            int idx = tid + r * 256;
            int k = idx >> 6, n = idx & 63;
            Bs[k][n] = Bp[(size_t)(k0 + k) * N + col0 + n];
        }
        __syncthreads();
#pragma unroll
        for (int k = 0; k < BK; ++k) {
            float a[4], bb[4];
#pragma unroll
            for (int i = 0; i < 4; ++i) a[i]  = As[k][ty * 4 + i];
#pragma unroll
            for (int j = 0; j < 4; ++j) bb[j] = Bs[k][tx * 4 + j];
#pragma unroll
            for (int i = 0; i < 4; ++i)
#pragma unroll
                for (int j = 0; j < 4; ++j) acc[i][j] += a[i] * bb[j];
        }
        __syncthreads();
    }

#pragma unroll
    for (int i = 0; i < 4; ++i) {
        int m = ty * 4 + i;
        if (m >= MM) continue;
#pragma unroll
        for (int j = 0; j < 4; ++j)
            C[(size_t)m * N + col0 + tx * 4 + j] = acc[i][j];
    }
}

// step 7: ent_att, BM=32 tile (z = b*HH + h)
__global__ __launch_bounds__(256)
void gemm32_k(const float* __restrict__ emtok, const float* __restrict__ att,
              float* __restrict__ entatt)
{
    int z = blockIdx.z;
    const float* A  = emtok + (size_t)(z / HH) * EE * LL;
    const float* Bp = att + (size_t)z * LL * LL;
    float* C = entatt + (size_t)z * EE * LL;
    int col0 = blockIdx.x * 64;

    __shared__ float As[16][34];
    __shared__ float Bs[16][68];

    int tid = threadIdx.x;
    int tx = tid & 15, ty = tid >> 4;
    float acc[2][4] = {};

    for (int k0 = 0; k0 < LL; k0 += 16) {
#pragma unroll
        for (int r = 0; r < 2; ++r) {
            int idx = tid + r * 256;
            int m = idx >> 4, k = idx & 15;
            As[k][m] = A[(size_t)m * LL + k0 + k];
        }
#pragma unroll
        for (int r = 0; r < 4; ++r) {
            int idx = tid + r * 256;
            int k = idx >> 6, n = idx & 63;
            Bs[k][n] = Bp[(size_t)(k0 + k) * LL + col0 + n];
        }
        __syncthreads();
#pragma unroll
        for (int k = 0; k < 16; ++k) {
            float2 a = *(const float2*)&As[k][ty * 2];
            float4 bv = *(const float4*)&Bs[k][tx * 4];
            acc[0][0] += a.x * bv.x; acc[0][1] += a.x * bv.y;
            acc[0][2] += a.x * bv.z; acc[0][3] += a.x * bv.w;
            acc[1][0] += a.y * bv.x; acc[1][1] += a.y * bv.y;
            acc[1][2] += a.y * bv.z; acc[1][3] += a.y * bv.w;
        }
        __syncthreads();
    }

#pragma unroll
    for (int i = 0; i < 2; ++i)
#pragma unroll
        for (int j = 0; j < 4; ++j)
            C[(size_t)(ty*2 + i) * LL + col0 + tx*4 + j] = acc[i][j];
}

// step 9 merged, fp16-split epilogue
__global__ __launch_bounds__(256)
void ht9_k(const float* __restrict__ tatt, const float* __restrict__ hatt,
           const float* __restrict__ mention,
           uint32_t* __restrict__ hH2, uint32_t* __restrict__ hL2,
           uint32_t* __restrict__ tH2, uint32_t* __restrict__ tL2)
{
    const int BM = 64, BN = 64, BK = 16;
    int zz = blockIdx.z;
    int b = zz & (BB - 1), sel = zz >> 2;
    const float* A  = (sel ? hatt : tatt) + (size_t)b * PP * MM;
    const float* Bp = mention + (size_t)b * MM * DD;
    uint32_t* CH = (sel ? tH2 : hH2) + (size_t)b * PP * (DD/2);
    uint32_t* CL = (sel ? tL2 : hL2) + (size_t)b * PP * (DD/2);
    int row0 = blockIdx.y * BM;
    int col0 = blockIdx.x * BN;

    __shared__ float As[BK][BM + 1];
    __shared__ float Bs[BK][BN + 1];

    int tid = threadIdx.x;
    int tx = tid & 15, ty = tid >> 4;
    float acc[4][4] = {};

    for (int k0 = 0; k0 < MM; k0 += BK) {
#pragma unroll
        for (int r = 0; r < 4; ++r) {
            int idx = tid + r * 256;
            int m = idx >> 4, k = idx & 15;
            As[k][m] = A[(size_t)(row0 + m) * MM + k0 + k];
        }
#pragma unroll
        for (int r = 0; r < 4; ++r) {
            int idx = tid + r * 256;
            int k = idx >> 6, n = idx & 63;
            Bs[k][n] = Bp[(size_t)(k0 + k) * DD + col0 + n];
        }
        __syncthreads();
#pragma unroll
        for (int k = 0; k < BK; ++k) {
            float a[4], bb[4];
#pragma unroll
            for (int i = 0; i < 4; ++i) a[i]  = As[k][ty * 4 + i];
#pragma unroll
            for (int j = 0; j < 4; ++j) bb[j] = Bs[k][tx * 4 + j];
#pragma unroll
            for (int i = 0; i < 4; ++i)
#pragma unroll
                for (int j = 0; j < 4; ++j) acc[i][j] += a[i] * bb[j];
        }
        __syncthreads();
    }

#pragma unroll
    for (int i = 0; i < 4; ++i) {
        int m = row0 + ty * 4 + i;
        int np = (col0 + tx * 4) >> 1;
        uint32_t H, L;
        splitfp16(acc[i][0], acc[i][1], H, L);
        CH[(size_t)m * (DD/2) + np]     = H;
        CL[(size_t)m * (DD/2) + np]     = L;
        splitfp16(acc[i][2], acc[i][3], H, L);
        CH[(size_t)m * (DD/2) + np + 1] = H;
        CL[(size_t)m * (DD/2) + np + 1] = L;
    }
}

// ---------------- bf16x3 NT GEMM: cinfo (fp16-split output) ----------------
#define BF_SMEM ((128*20 + 64*20) * 2 * 4)
__global__ __launch_bounds__(256)
void bf10_k(const uint32_t* __restrict__ AHg, const uint32_t* __restrict__ ALg,
            const uint32_t* __restrict__ BHg, const uint32_t* __restrict__ BLg,
            uint32_t* __restrict__ CH2g, uint32_t* __restrict__ CL2g)
{
    extern __shared__ uint32_t usm[];
    uint32_t* AsH = usm;
    uint32_t* AsL = AsH + 128*20;
    uint32_t* BsH = AsL + 128*20;
    uint32_t* BsL = BsH + 64*20;

    int z = blockIdx.z;
    const int KP = LL/2, N = DD;
    const uint32_t* AH = AHg + (size_t)z*PP*KP;
    const uint32_t* AL = ALg + (size_t)z*PP*KP;
    const uint32_t* BH = BHg + (size_t)z*DD*KP;
    const uint32_t* BL = BLg + (size_t)z*DD*KP;
    uint32_t* CH2 = CH2g + (size_t)z*PP*(DD/2);
    uint32_t* CL2 = CL2g + (size_t)z*PP*(DD/2);
    int row0 = blockIdx.y * 128, col0 = blockIdx.x * 64;
    int tid = threadIdx.x, lane = tid & 31, wid = tid >> 5;
    int m_off = (wid & 3) * 32, n_off = (wid >> 2) * 32;
    int g = lane >> 2, kq = lane & 3;

    float acc[2][4][4];
#pragma unroll
    for (int a = 0; a < 2; ++a)
#pragma unroll
        for (int b = 0; b < 4; ++b)
#pragma unroll
            for (int c = 0; c < 4; ++c) acc[a][b][c] = 0.f;

    for (int kp0 = 0; kp0 < KP; kp0 += 16) {
        __syncthreads();
#pragma unroll
        for (int r2 = 0; r2 < 2; ++r2) {
            int slot = tid + r2 * 256;
            int m = slot >> 2, q = slot & 3;
            *(uint4*)(AsH + m*20 + q*4) =
                *(const uint4*)(AH + (size_t)(row0 + m)*KP + kp0 + q*4);
            *(uint4*)(AsL + m*20 + q*4) =
                *(const uint4*)(AL + (size_t)(row0 + m)*KP + kp0 + q*4);
        }
        {
            int n = tid >> 2, q = tid & 3;
            *(uint4*)(BsH + n*20 + q*4) =
                *(const uint4*)(BH + (size_t)(col0 + n)*KP + kp0 + q*4);
            *(uint4*)(BsL + n*20 + q*4) =
                *(const uint4*)(BL + (size_t)(col0 + n)*KP + kp0 + q*4);
        }
        __syncthreads();
#pragma unroll
        for (int st = 0; st < 2; ++st) {
            int pb = st*8 + kq;
            uint32_t aH[2][4], aL[2][4];
#pragma unroll
            for (int mt = 0; mt < 2; ++mt) {
                int mr = m_off + mt*16 + g;
                aH[mt][0] = AsH[mr*20 + pb];       aL[mt][0] = AsL[mr*20 + pb];
                aH[mt][1] = AsH[(mr+8)*20 + pb];   aL[mt][1] = AsL[(mr+8)*20 + pb];
                aH[mt][2] = AsH[mr*20 + pb + 4];   aL[mt][2] = AsL[mr*20 + pb + 4];
                aH[mt][3] = AsH[(mr+8)*20 + pb+4]; aL[mt][3] = AsL[(mr+8)*20 + pb+4];
            }
#pragma unroll
            for (int nt = 0; nt < 4; ++nt) {
                int nr = n_off + nt*8 + g;
                uint32_t bH0 = BsH[nr*20 + pb], bH1 = BsH[nr*20 + pb + 4];
                uint32_t bL0 = BsL[nr*20 + pb], bL1 = BsL[nr*20 + pb + 4];
#pragma unroll
                for (int mt = 0; mt < 2; ++mt) {
                    mma_bf(acc[mt][nt], aH[mt], bH0, bH1);
                    mma_bf(acc[mt][nt], aH[mt], bL0, bL1);
                    mma_bf(acc[mt][nt], aL[mt], bH0, bH1);
                }
            }
        }
    }

#pragma unroll
    for (int mt = 0; mt < 2; ++mt) {
#pragma unroll
        for (int nt = 0; nt < 4; ++nt) {
            int mr = row0 + m_off + mt*16 + g;
            int nc = col0 + n_off + nt*8 + 2*kq;
            int np = nc >> 1;
            uint32_t H, L;
            splitfp16(acc[mt][nt][0], acc[mt][nt][1], H, L);
            CH2[(size_t)mr*(N/2) + np] = H; CL2[(size_t)mr*(N/2) + np] = L;
            splitfp16(acc[mt][nt][2], acc[mt][nt][3], H, L);
            CH2[(size_t)(mr+8)*(N/2) + np] = H; CL2[(size_t)(mr+8)*(N/2) + np] = L;
        }
    }
}

// ---------------- fp16 2-term fused tanh-linears ----------------
#define HF_SMEM ((128*20*2 + 64*20*2) * 4)
__global__ __launch_bounds__(256)
void hf1112_k(const uint32_t* __restrict__ hH2, const uint32_t* __restrict__ hL2,
              const uint32_t* __restrict__ tH2, const uint32_t* __restrict__ tL2,
              const uint32_t* __restrict__ hWf, const uint32_t* __restrict__ tWf,
              const uint32_t* __restrict__ cH2, const uint32_t* __restrict__ cL2,
              const uint32_t* __restrict__ hcWf, const uint32_t* __restrict__ tcWf,
              const float* __restrict__ hb, const float* __restrict__ tb,
              const float* __restrict__ hcb, const float* __restrict__ tcb,
              float* __restrict__ hf, float* __restrict__ tf)
{
    extern __shared__ uint32_t usm[];
    uint32_t* AsH = usm;                 // [128][20]
    uint32_t* AsL = AsH + 128*20;
    uint32_t* Bs  = AsL + 128*20;        // [64][20] x2 slack

    int zsel = blockIdx.z;
    const uint32_t* A1H = zsel ? tH2 : hH2;
    const uint32_t* A1L = zsel ? tL2 : hL2;
    const uint32_t* B1  = zsel ? tWf : hWf;
    const uint32_t* B2  = zsel ? tcWf : hcWf;
    const float* bias1 = zsel ? tb : hb;
    const float* bias2 = zsel ? tcb : hcb;
    float* C = zsel ? tf : hf;

    const int KP = DD/2, N = DD;
    int row0 = blockIdx.y * 128, col0 = blockIdx.x * 64;
    int tid = threadIdx.x, lane = tid & 31, wid = tid >> 5;
    int m_off = (wid & 3) * 32, n_off = (wid >> 2) * 32;
    int g = lane >> 2, kq = lane & 3;

    float acc[2][4][4];
#pragma unroll
    for (int a = 0; a < 2; ++a)
#pragma unroll
        for (int b = 0; b < 4; ++b)
#pragma unroll
            for (int c = 0; c < 4; ++c) acc[a][b][c] = 0.f;

    for (int pass = 0; pass < 2; ++pass) {
        const uint32_t* AH = pass ? cH2 : A1H;
        const uint32_t* AL = pass ? cL2 : A1L;
        const uint32_t* B  = pass ? B2  : B1;
        for (int kp0 = 0; kp0 < KP; kp0 += 16) {
            __syncthreads();
#pragma unroll
            for (int r2 = 0; r2 < 2; ++r2) {
                int slot = tid + r2 * 256;
                int m = slot >> 2, q = slot & 3;
                *(uint4*)(AsH + m*20 + q*4) =
                    *(const uint4*)(AH + (size_t)(row0 + m)*KP + kp0 + q*4);
                *(uint4*)(AsL + m*20 + q*4) =
                    *(const uint4*)(AL + (size_t)(row0 + m)*KP + kp0 + q*4);
            }
            {
                int n = tid >> 2, q = tid & 3;
                *(uint4*)(Bs + n*20 + q*4) =
                    *(const uint4*)(B + (size_t)(col0 + n)*KP + kp0 + q*4);
            }
            __syncthreads();
#pragma unroll
            for (int st = 0; st < 2; ++st) {
                int pb = st*8 + kq;
                uint32_t aH[2][4], aL[2][4];
#pragma unroll
                for (int mt = 0; mt < 2; ++mt) {
                    int mr = m_off + mt*16 + g;
                    aH[mt][0] = AsH[mr*20 + pb];       aL[mt][0] = AsL[mr*20 + pb];
                    aH[mt][1] = AsH[(mr+8)*20 + pb];   aL[mt][1] = AsL[(mr+8)*20 + pb];
                    aH[mt][2] = AsH[mr*20 + pb + 4];   aL[mt][2] = AsL[mr*20 + pb + 4];
                    aH[mt][3] = AsH[(mr+8)*20 + pb+4]; aL[mt][3] = AsL[(mr+8)*20 + pb+4];
                }
#pragma unroll
                for (int nt = 0; nt < 4; ++nt) {
                    int nr = n_off + nt*8 + g;
                    uint32_t b0 = Bs[nr*20 + pb], b1 = Bs[nr*20 + pb + 4];
#pragma unroll
                    for (int mt = 0; mt < 2; ++mt) {
                        mma_fp16(acc[mt][nt], aH[mt], b0, b1);
                        mma_fp16(acc[mt][nt], aL[mt], b0, b1);
                    }
                }
            }
        }
    }

#pragma unroll
    for (int mt = 0; mt < 2; ++mt) {
#pragma unroll
        for (int nt = 0; nt < 4; ++nt) {
            int mr = row0 + m_off + mt*16 + g;
            int nc = col0 + n_off + nt*8 + 2*kq;
            float b0 = bias1[nc]   + bias2[nc];
            float b1 = bias1[nc+1] + bias2[nc+1];
            C[(size_t)mr * N + nc]       = tanhf(acc[mt][nt][0] + b0);
            C[(size_t)mr * N + nc + 1]   = tanhf(acc[mt][nt][1] + b1);
            C[(size_t)(mr+8) * N + nc]   = tanhf(acc[mt][nt][2] + b0);
            C[(size_t)(mr+8) * N + nc+1] = tanhf(acc[mt][nt][3] + b1);
        }
    }
}

// ------- classifier: fp16 2-term, coop double-buffered smem W staging -------
#define CLAS_SMEM (128*17*4 + 2*128*33*4 + 2*4*WPAD*8)
__global__ __launch_bounds__(256, 1)
void clasmma_k(const float* __restrict__ Hf, const float* __restrict__ Tf,
               const uint2* __restrict__ Wt, float* __restrict__ part)
{
    extern __shared__ char smraw[];
    float*    hs  = (float*)smraw;
    uint32_t* tsH = (uint32_t*)(hs + 128*17);
    uint32_t* tsL = tsH + 128*33;
    uint2*    ws  = (uint2*)(tsL + 128*33);

    const int n = blockIdx.y, z = blockIdx.z;
    const int p0 = blockIdx.x * 128;
    int tid = threadIdx.x, lane = tid & 31, wid = tid >> 5;
    int pbase = (wid & 3) * 32, nbase = (wid >> 2) * 56;
    int g = lane >> 2, kq = lane & 3;

    for (int v = tid; v < 128*32; v += 256) {
        int p = v >> 5, q = v & 31;
        if (q < 16)
            hs[p*17 + q] = Hf[(size_t)(p0 + p)*DD + n*64 + z*16 + q];
        float t0 = Tf[(size_t)(p0 + p)*DD + n*64 + 2*q];
        float t1 = Tf[(size_t)(p0 + p)*DD + n*64 + 2*q + 1];
        uint32_t H, L; splitfp16(t0, t1, H, L);
        tsH[p*33 + q] = H; tsL[p*33 + q] = L;
    }
    {
        const uint2* Wg = Wt + (size_t)(n*64 + z*16) * WT_U2;
#pragma unroll
        for (int w = 0; w < 7; ++w) {
            int v = tid + w*256;
            int kq2 = v / 448, rem = v - kq2*448;
            ws[kq2*WPAD + rem] = Wg[v];
        }
    }
    __syncthreads();

    uint32_t tAH[2][4][4], tAL[2][4][4];
#pragma unroll
    for (int mt = 0; mt < 2; ++mt) {
        int pr = pbase + mt*16 + g;
#pragma unroll
        for (int s = 0; s < 4; ++s) {
            int pp = s*8 + kq;
            tAH[mt][s][0] = tsH[pr*33 + pp];       tAL[mt][s][0] = tsL[pr*33 + pp];
            tAH[mt][s][1] = tsH[(pr+8)*33 + pp];   tAL[mt][s][1] = tsL[(pr+8)*33 + pp];
            tAH[mt][s][2] = tsH[pr*33 + pp + 4];   tAL[mt][s][2] = tsL[pr*33 + pp + 4];
            tAH[mt][s][3] = tsH[(pr+8)*33 + pp+4]; tAL[mt][s][3] = tsL[(pr+8)*33 + pp+4];
        }
    }

    float acc[2][7][4];
#pragma unroll
    for (int a = 0; a < 2; ++a)
#pragma unroll
        for (int b = 0; b < 7; ++b)
#pragma unroll
            for (int c = 0; c < 4; ++c) acc[a][b][c] = 0.f;

    for (int ii = 0; ii < 16; ++ii) {
        uint2* wbuf  = ws + (ii & 1) * (4*WPAD);
        uint2* wnext = ws + ((ii + 1) & 1) * (4*WPAD);

        uint2 pf[7];
        if (ii < 15) {
            const uint2* Wg = Wt + (size_t)(n*64 + z*16 + ii + 1) * WT_U2;
#pragma unroll
            for (int w = 0; w < 7; ++w) pf[w] = Wg[tid + w*256];
        }

        float hv0[2], hv1[2];
#pragma unroll
        for (int mt = 0; mt < 2; ++mt) {
            int pr = pbase + mt*16 + g;
            hv0[mt] = hs[pr*17 + ii];
            hv1[mt] = hs[(pr+8)*17 + ii];
        }

        float tmp[2][7][4];
#pragma unroll
        for (int a = 0; a < 2; ++a)
#pragma unroll
            for (int b = 0; b < 7; ++b)
#pragma unroll
                for (int c = 0; c < 4; ++c) tmp[a][b][c] = 0.f;

#pragma unroll
        for (int s = 0; s < 4; ++s) {
#pragma unroll
            for (int nt = 0; nt < 7; ++nt) {
                int r = nbase + nt*8 + g;
                uint2 w2 = wbuf[kq*WPAD + s*112 + r];
#pragma unroll
                for (int mt = 0; mt < 2; ++mt) {
                    mma_fp16(tmp[mt][nt], tAH[mt][s], w2.x, w2.y);
                    mma_fp16(tmp[mt][nt], tAL[mt][s], w2.x, w2.y);
                }
            }
        }
#pragma unroll
        for (int mt = 0; mt < 2; ++mt)
#pragma unroll
            for (int nt = 0; nt < 7; ++nt) {
                acc[mt][nt][0] += hv0[mt] * tmp[mt][nt][0];
                acc[mt][nt][1] += hv0[mt] * tmp[mt][nt][1];
                acc[mt][nt][2] += hv1[mt] * tmp[mt][nt][2];
                acc[mt][nt][3] += hv1[mt] * tmp[mt][nt][3];
            }

        if (ii < 15) {
#pragma unroll
            for (int w = 0; w < 7; ++w) {
                int v = tid + w*256;
                int kq2 = v / 448, rem = v - kq2*448;
                wnext[kq2*WPAD + rem] = pf[w];
            }
        }
        __syncthreads();
    }

    int chunk = n*4 + z;
    float* po = part + (size_t)chunk * (BB*PP*RR);
#pragma unroll
    for (int mt = 0; mt < 2; ++mt) {
#pragma unroll
        for (int nt = 0; nt < 7; ++nt) {
            int p = p0 + pbase + mt*16 + g;
            int r = nbase + nt*8 + 2*kq;
            if (r < RR)   po[(size_t)p*RR + r]       = acc[mt][nt][0];
            if (r+1 < RR) po[(size_t)p*RR + r + 1]   = acc[mt][nt][1];
            if (r < RR)   po[(size_t)(p+8)*RR + r]   = acc[mt][nt][2];
            if (r+1 < RR) po[(size_t)(p+8)*RR + r+1] = acc[mt][nt][3];
        }
    }
}

__global__ void clas_red_k(const float* __restrict__ part,
                           const float* __restrict__ clasb,
                           float* __restrict__ out)
{
    int idx = blockIdx.x * 256 + threadIdx.x;
    if (idx >= BB * PP * RR) return;
    int r = idx % RR;
    float s = clasb[r];
#pragma unroll
    for (int c = 0; c < NCH; ++c) s += part[(size_t)c * (BB * PP * RR) + idx];
    out[idx] = s;
}

// ---------------- host ----------------
extern "C" void kernel_launch(void* const* d_in, const int* in_sizes, int n_in,
                              void* d_out, int out_size)
{
    const float* context   = (const float*)d_in[0];
    const float* attention = (const float*)d_in[1];
    const float* mmap      = (const float*)d_in[2];
    const float* emap      = (const float*)d_in[3];
    const int*   hts       = (const int*)d_in[4];
    const float* hW   = (const float*)d_in[5];
    const float* hb   = (const float*)d_in[6];
    const float* tW   = (const float*)d_in[7];
    const float* tb   = (const float*)d_in[8];
    const float* hcW  = (const float*)d_in[9];
    const float* hcb  = (const float*)d_in[10];
    const float* tcW  = (const float*)d_in[11];
    const float* tcb  = (const float*)d_in[12];
    const float* clasW = (const float*)d_in[13];
    const float* clasb = (const float*)d_in[14];
    float* out = (float*)d_out;

#define GETF(p, s) float* p; cudaGetSymbolAddress((void**)&p, s)
#define GETU(p, s) uint32_t* p; cudaGetSymbolAddress((void**)&p, s)
    GETF(att_sum, g_att_sum); GETF(mention, g_mention); GETF(tmp1, g_tmp1);
    GETF(matt, g_matt); GETF(eatt, g_eatt); GETF(emtok, g_emtok);
    GETF(entatt, g_entatt); GETF(hatt, g_hatt); GETF(tatt, g_tatt);
    GETU(ctxH2, g_ctxH2); GETU(ctxL2, g_ctxL2);
    GETU(hH2, g_hH2); GETU(hL2, g_hL2); GETU(tH2, g_tH2); GETU(tL2, g_tL2);
    GETU(cinfoH2, g_cinfoH2); GETU(cinfoL2, g_cinfoL2);
    GETF(hf, g_hf); GETF(tf, g_tf); GETF(part, g_part);
    GETU(hWf, g_hWf); GETU(tWf, g_tWf); GETU(hcWf, g_hcWf); GETU(tcWf, g_tcWf);
    GETU(ctxtH2, g_ctxtH2); GETU(ctxtL2, g_ctxtL2);
    uint2* Wt; cudaGetSymbolAddress((void**)&Wt, g_Wt);
#undef GETF
#undef GETU

    cudaFuncSetAttribute(clasmma_k, cudaFuncAttributeMaxDynamicSharedMemorySize, CLAS_SMEM);

    // 0+1) merged preprocessing + att_sum
    prep_k<<<14080, 256>>>(attention, att_sum, hW, tW, hcW, tcW,
                           hWf, tWf, hcWf, tcWf,
                           context, ctxtH2, ctxtL2, clasW, Wt);

    // 2+3) mention & tmp1 merged
    gemm23_k<<<dim3(12,1,8),256>>>(mmap, context, att_sum, mention, tmp1);

    // 4) mention_att
    matt_k<<<(BB*MM*MM*32 + 255)/256, 256>>>(tmp1, mmap, matt);

    // 5) entity_att
    eatt_k<<<BB, 256>>>(emap, matt, eatt);

    // 6) em_tok + normalize
    gemm_k<<<dim3(8,1,BB),256>>>(
        emap, mmap, emtok, EE, LL, MM,
        (long long)EE*MM, (long long)MM*LL, (long long)EE*LL);
    rownorm_k<<<BB*EE, 256>>>(emtok);

    // 7) ent_att (BM=32 tile)
    gemm32_k<<<dim3(8,1,BB*HH),256>>>(emtok, attention, entatt);

    // 8) per-pair vectors
    pair_att_k<<<BB*PP, 64>>>(hts, emap, eatt, hatt, tatt);
    ctx_k<<<BB*PP, 256>>>(hts, entatt, ctxH2, ctxL2);

    // 9) h, t merged (FFMA, fp16-split epilogue)
    ht9_k<<<dim3(12,8,2*BB),256>>>(tatt, hatt, mention, hH2, hL2, tH2, tL2);

    // 10) context_info (bf16x3 NT, fp16-split out)
    bf10_k<<<dim3(12,4,BB),256,BF_SMEM>>>(ctxH2, ctxL2, ctxtH2, ctxtL2,
                                          cinfoH2, cinfoL2);

    // 11+12) fused tanh-linears (fp16 2-term)
    hf1112_k<<<dim3(12,16,2),256,HF_SMEM>>>(
        hH2, hL2, tH2, tL2, hWf, tWf,
        cinfoH2, cinfoL2, hcWf, tcWf,
        hb, tb, hcb, tcb, hf, tf);

    // 13) classifier (fp16 2-term, smem-staged W)
    clasmma_k<<<dim3(BB*PP/128, NBK, 4), 256, CLAS_SMEM>>>(hf, tf, Wt, part);
    clas_red_k<<<(BB*PP*RR + 255)/256, 256>>>(part, clasb, out);
}